// round 2
// baseline (speedup 1.0000x reference)
#include <cuda_runtime.h>
#include <math.h>

// Problem constants
#define BB 4
#define DD 1024
#define NN 4096
#define HH 16
#define KK 128
#define DHH 64

typedef unsigned long long ull;

// Scratch (device globals; no allocation in kernel_launch)
__device__ float g_q[(size_t)BB * DD * NN];      // 67MB
__device__ float g_k[(size_t)BB * DD * NN];      // 67MB
__device__ float g_kp[(size_t)BB * DD * KK];     // 2MB
__device__ float g_msg[(size_t)BB * DD * NN];    // 67MB
__device__ float g_msg2[(size_t)BB * DD * NN];   // 67MB
__device__ float g_h[(size_t)BB * 2 * DD * NN];  // 134MB

// ---- packed f32x2 helpers ----------------------------------------------
__device__ __forceinline__ void ffma2(ull& d, ull a, ull b) {
    asm("fma.rn.f32x2 %0, %1, %2, %0;" : "+l"(d) : "l"(a), "l"(b));
}
__device__ __forceinline__ ull pack2(float x, float y) {
    ull r; asm("mov.b64 %0, {%1, %2};" : "=l"(r) : "f"(x), "f"(y)); return r;
}
__device__ __forceinline__ void unpack2(ull v, float& lo, float& hi) {
    asm("mov.b64 {%0, %1}, %2;" : "=f"(lo), "=f"(hi) : "l"(v));
}

// ---------------------------------------------------------------------------
// Batched 1x1-conv GEMM with packed f32x2 math:
//   out[b,m,n] = sum_i W[m,i] * In(b,i,n) + bias[m]
//   In(b,i,n) = (i < K1) ? in1[b,i,n] : in2[b,i-K1,n]     (channel concat)
// Optional fused BN(eval, eps=1e-3) + ReLU epilogue.
// Tile 128(M) x 128(N) x 8(K), 256 threads, 8x8 microtile as 8x4 f32x2 pairs.
// Columns per thread: n = n0 + 2*tx + 32*jp  (conflict-free LDS.64).
// Double-buffered smem, one __syncthreads per k-tile.
// ---------------------------------------------------------------------------
template <bool CONCAT, bool BNRELU>
__global__ void __launch_bounds__(256) conv_gemm(
    const float* __restrict__ W,
    const float* __restrict__ in1,
    const float* __restrict__ in2,
    const float* __restrict__ bias,
    const float* __restrict__ gamma,
    const float* __restrict__ beta,
    const float* __restrict__ mean,
    const float* __restrict__ var,
    float* __restrict__ outp,
    int M, int Kd, int Nw, int K1)
{
    __shared__ float2 As2[2][8][128];   // A value duplicated into both lanes
    __shared__ float  Bs[2][8][128];

    const int t  = threadIdx.x;
    const int ty = t >> 4;
    const int tx = t & 15;
    const int m0 = blockIdx.y * 128;
    const int n0 = blockIdx.x * 128;
    const int b  = blockIdx.z;

    const float* in1b = in1 + (size_t)b * K1 * Nw;
    const float* in2b = CONCAT ? (in2 + (size_t)b * (size_t)(Kd - K1) * Nw) : nullptr;

    const int ar = t >> 1, ac = (t & 1) * 4;   // A: row m0+ar, k-cols ac..ac+3
    const int br = t >> 5, bc = (t & 31) * 4;  // B: k-row br, n-cols bc..bc+3

    const float* Arow = W + (size_t)(m0 + ar) * Kd + ac;

    ull acc[8][4];
#pragma unroll
    for (int i = 0; i < 8; i++)
#pragma unroll
        for (int j = 0; j < 4; j++) acc[i][j] = 0ULL;

    const int ntiles = Kd >> 3;

    // prologue: load tile 0
    float4 av = *(const float4*)(Arow);
    const float* bsrc0;
    {
        int ii = br;
        if (CONCAT && ii >= K1) bsrc0 = in2b + (size_t)(ii - K1) * Nw;
        else                    bsrc0 = in1b + (size_t)ii * Nw;
    }
    float4 bv = *(const float4*)(bsrc0 + n0 + bc);

    int buf = 0;
    As2[0][ac + 0][ar] = make_float2(av.x, av.x);
    As2[0][ac + 1][ar] = make_float2(av.y, av.y);
    As2[0][ac + 2][ar] = make_float2(av.z, av.z);
    As2[0][ac + 3][ar] = make_float2(av.w, av.w);
    *(float4*)&Bs[0][br][bc] = bv;
    __syncthreads();

    for (int tile = 0; tile < ntiles; tile++) {
        // issue prefetch LDGs for next tile (consumed after compute)
        if (tile + 1 < ntiles) {
            const int kt = (tile + 1) * 8;
            av = *(const float4*)(Arow + kt);
            int ii = kt + br;
            const float* src;
            if (CONCAT && ii >= K1) src = in2b + (size_t)(ii - K1) * Nw;
            else                    src = in1b + (size_t)ii * Nw;
            bv = *(const float4*)(src + n0 + bc);
        }

        // compute on current buffer
#pragma unroll
        for (int kk = 0; kk < 8; kk++) {
            ull a2[8], b2[4];
#pragma unroll
            for (int i = 0; i < 8; i++)
                a2[i] = *(const ull*)&As2[buf][kk][ty * 8 + i];
#pragma unroll
            for (int jp = 0; jp < 4; jp++)
                b2[jp] = *(const ull*)&Bs[buf][kk][2 * tx + 32 * jp];
#pragma unroll
            for (int i = 0; i < 8; i++)
#pragma unroll
                for (int jp = 0; jp < 4; jp++)
                    ffma2(acc[i][jp], a2[i], b2[jp]);
        }

        // commit prefetch into alternate buffer
        if (tile + 1 < ntiles) {
            const int nb = buf ^ 1;
            As2[nb][ac + 0][ar] = make_float2(av.x, av.x);
            As2[nb][ac + 1][ar] = make_float2(av.y, av.y);
            As2[nb][ac + 2][ar] = make_float2(av.z, av.z);
            As2[nb][ac + 3][ar] = make_float2(av.w, av.w);
            *(float4*)&Bs[nb][br][bc] = bv;
        }
        __syncthreads();
        buf ^= 1;
    }

    // epilogue
#pragma unroll
    for (int i = 0; i < 8; i++) {
        const int m = m0 + ty * 8 + i;
        const float bi = bias[m];
        float scale = 1.f, shift = 0.f;
        if (BNRELU) {
            const float inv = rsqrtf(var[m] + 1e-3f);
            scale = gamma[m] * inv;
            shift = beta[m] - mean[m] * scale;
        }
        float* orow = outp + ((size_t)b * M + m) * Nw + n0;
#pragma unroll
        for (int jp = 0; jp < 4; jp++) {
            float v0, v1;
            unpack2(acc[i][jp], v0, v1);
            v0 += bi; v1 += bi;
            if (BNRELU) {
                v0 = fmaxf(fmaf(v0, scale, shift), 0.f);
                v1 = fmaxf(fmaf(v1, scale, shift), 0.f);
            }
            *(float2*)(orow + 2 * tx + 32 * jp) = make_float2(v0, v1);
        }
    }
}

// ---------------------------------------------------------------------------
// Linformer projection: C[r, c] += A[r, m] * P[m, c], r<4096, c<128.
// Split-K over m with atomicAdd (C pre-zeroed). Small (~1% of FLOPs).
// ---------------------------------------------------------------------------
__global__ void __launch_bounds__(256) proj_gemm(
    const float* __restrict__ A, const float* __restrict__ P, float* __restrict__ C)
{
    __shared__ float As[8][128];
    __shared__ float Bs[8][128];

    const int t  = threadIdx.x;
    const int ty = t >> 4;
    const int tx = t & 15;
    const int r0 = blockIdx.x * 128;
    const int chunk = NN / gridDim.y;
    const int c0 = blockIdx.y * chunk;

    const int ar = t >> 1, ac = (t & 1) * 4;
    const int br = t >> 5, bc = (t & 31) * 4;

    float acc[8][8];
#pragma unroll
    for (int i = 0; i < 8; i++)
#pragma unroll
        for (int j = 0; j < 8; j++) acc[i][j] = 0.f;

    for (int kt = 0; kt < chunk; kt += 8) {
        const int kb = c0 + kt;
        float4 av = *(const float4*)(A + (size_t)(r0 + ar) * NN + kb + ac);
        As[ac + 0][ar] = av.x;
        As[ac + 1][ar] = av.y;
        As[ac + 2][ar] = av.z;
        As[ac + 3][ar] = av.w;
        *(float4*)&Bs[br][bc] = *(const float4*)(P + (size_t)(kb + br) * KK + bc);
        __syncthreads();
#pragma unroll
        for (int kk = 0; kk < 8; kk++) {
            float a[8], bv[8];
#pragma unroll
            for (int i = 0; i < 8; i++) a[i] = As[kk][ty * 8 + i];
#pragma unroll
            for (int j = 0; j < 8; j++) bv[j] = Bs[kk][tx * 8 + j];
#pragma unroll
            for (int i = 0; i < 8; i++)
#pragma unroll
                for (int j = 0; j < 8; j++)
                    acc[i][j] = fmaf(a[i], bv[j], acc[i][j]);
        }
        __syncthreads();
    }

#pragma unroll
    for (int i = 0; i < 8; i++)
#pragma unroll
        for (int j = 0; j < 8; j++)
            atomicAdd(&C[(size_t)(r0 + ty * 8 + i) * KK + tx * 8 + j], acc[i][j]);
}

// ---------------------------------------------------------------------------
// Fused Linformer attention, f32x2 edition.
// K/V slice stored TRANSPOSED in smem: KsT[k][dh] (row stride 66 floats,
// conflict-free STS, 8B-aligned paired LDS for dh-pairs).
// scores: s2 += qv2[dhp] * KsT2[k][dhp]      (paired over dh)
// msg:    acc2[dhp] += dup(e_k) * KsT2[k][dhp]
// Dynamic smem: KsT 128*66*4 + Es 128*128*4 = 99328 B.
// ---------------------------------------------------------------------------
#define KST_STRIDE 66

__global__ void attn_kernel(const float* __restrict__ q,
                            const float* __restrict__ kp,
                            float* __restrict__ msg)
{
    extern __shared__ float sm[];
    float* KsT = sm;                         // [128 k][66 (dh, padded)]
    float* Es  = sm + KK * KST_STRIDE;       // [128 k][128 tid]

    const int tid = threadIdx.x;
    const int n = blockIdx.x * 128 + tid;
    const int h = blockIdx.y;
    const int b = blockIdx.z;

    // Load K/V slice transposed: KsT[k=tid][dh] = kp[(b*D + dh*H + h)*K + tid]
#pragma unroll 4
    for (int dh = 0; dh < DHH; dh++)
        KsT[tid * KST_STRIDE + dh] = kp[((size_t)b * DD + (size_t)dh * HH + h) * KK + tid];
    __syncthreads();

    // q vector for this (b, h, n), packed into dh-pairs
    const float* qb = q + ((size_t)b * DD + h) * NN + n;
    ull qv2[DHH / 2];
#pragma unroll
    for (int dhp = 0; dhp < DHH / 2; dhp++) {
        float x = qb[(size_t)(2 * dhp) * HH * NN];
        float y = qb[(size_t)(2 * dhp + 1) * HH * NN];
        qv2[dhp] = pack2(x, y);
    }

    // scores (scaled by 1/sqrt(DH)=0.125)
    float mx = -1e30f;
    for (int k = 0; k < KK; k++) {
        ull s2 = 0ULL;
        const float* krow = KsT + k * KST_STRIDE;
#pragma unroll
        for (int dhp = 0; dhp < DHH / 2; dhp++)
            ffma2(s2, qv2[dhp], *(const ull*)(krow + 2 * dhp));
        float lo, hi;
        unpack2(s2, lo, hi);
        float s = (lo + hi) * 0.125f;
        Es[k * 128 + tid] = s;
        mx = fmaxf(mx, s);
    }

    float sum = 0.f;
    for (int k = 0; k < KK; k++) {
        float e = __expf(Es[k * 128 + tid] - mx);
        Es[k * 128 + tid] = e;
        sum += e;
    }
    const float inv = 1.f / sum;

    // msg: acc2[dhp] (dh even in lo, dh odd in hi)
    ull acc2[DHH / 2];
#pragma unroll
    for (int dhp = 0; dhp < DHH / 2; dhp++) acc2[dhp] = 0ULL;

    for (int k = 0; k < KK; k++) {
        float e = Es[k * 128 + tid];
        ull e2 = pack2(e, e);
        const float* krow = KsT + k * KST_STRIDE;
#pragma unroll
        for (int dhp = 0; dhp < DHH / 2; dhp++)
            ffma2(acc2[dhp], e2, *(const ull*)(krow + 2 * dhp));
    }

    float* msgb = msg + ((size_t)b * DD + h) * NN + n;
#pragma unroll
    for (int dhp = 0; dhp < DHH / 2; dhp++) {
        float lo, hi;
        unpack2(acc2[dhp], lo, hi);
        msgb[(size_t)(2 * dhp) * HH * NN]     = lo * inv;
        msgb[(size_t)(2 * dhp + 1) * HH * NN] = hi * inv;
    }
}

// ---------------------------------------------------------------------------
extern "C" void kernel_launch(void* const* d_in, const int* in_sizes, int n_in,
                              void* d_out, int out_size)
{
    const float* x       = (const float*)d_in[0];
    const float* source  = (const float*)d_in[1];
    const float* to_q_w  = (const float*)d_in[2];
    const float* to_q_b  = (const float*)d_in[3];
    const float* to_k_w  = (const float*)d_in[4];
    const float* to_k_b  = (const float*)d_in[5];
    const float* proj_k  = (const float*)d_in[6];
    const float* merge_w = (const float*)d_in[7];
    const float* merge_b = (const float*)d_in[8];
    const float* mlp_w1  = (const float*)d_in[9];
    const float* mlp_b1  = (const float*)d_in[10];
    const float* bn_g    = (const float*)d_in[11];
    const float* bn_b    = (const float*)d_in[12];
    const float* bn_m    = (const float*)d_in[13];
    const float* bn_v    = (const float*)d_in[14];
    const float* mlp_w2  = (const float*)d_in[15];
    const float* mlp_b2  = (const float*)d_in[16];
    float* out = (float*)d_out;

    float *q, *k, *kp, *msg, *msg2, *hbuf;
    cudaGetSymbolAddress((void**)&q,    g_q);
    cudaGetSymbolAddress((void**)&k,    g_k);
    cudaGetSymbolAddress((void**)&kp,   g_kp);
    cudaGetSymbolAddress((void**)&msg,  g_msg);
    cudaGetSymbolAddress((void**)&msg2, g_msg2);
    cudaGetSymbolAddress((void**)&hbuf, g_h);

    const dim3 blk(256);

    // 1) q = W_q @ x + b_q
    conv_gemm<false, false><<<dim3(NN / 128, DD / 128, BB), blk>>>(
        to_q_w, x, nullptr, to_q_b, nullptr, nullptr, nullptr, nullptr,
        q, DD, DD, NN, DD);

    // 2) k = W_k @ source + b_k
    conv_gemm<false, false><<<dim3(NN / 128, DD / 128, BB), blk>>>(
        to_k_w, source, nullptr, to_k_b, nullptr, nullptr, nullptr, nullptr,
        k, DD, DD, NN, DD);

    // 3) kp = k @ proj_k   (split-K x8, atomic accumulate)
    cudaMemsetAsync(kp, 0, sizeof(float) * (size_t)BB * DD * KK);
    proj_gemm<<<dim3((BB * DD) / 128, 8), blk>>>(k, proj_k, kp);

    // 4) fused attention -> msg
    const int attn_smem = (KK * KST_STRIDE + 128 * KK) * (int)sizeof(float);
    cudaFuncSetAttribute(attn_kernel, cudaFuncAttributeMaxDynamicSharedMemorySize,
                         attn_smem);
    attn_kernel<<<dim3(NN / 128, HH, BB), dim3(128), attn_smem>>>(q, kp, msg);

    // 5) msg2 = W_merge @ msg + b_merge
    conv_gemm<false, false><<<dim3(NN / 128, DD / 128, BB), blk>>>(
        merge_w, msg, nullptr, merge_b, nullptr, nullptr, nullptr, nullptr,
        msg2, DD, DD, NN, DD);

    // 6) h = relu(BN(W1 @ concat(x, msg2) + b1))
    conv_gemm<true, true><<<dim3(NN / 128, (2 * DD) / 128, BB), blk>>>(
        mlp_w1, x, msg2, mlp_b1, bn_g, bn_b, bn_m, bn_v,
        hbuf, 2 * DD, 2 * DD, NN, DD);

    // 7) out = W2 @ h + b2
    conv_gemm<false, false><<<dim3(NN / 128, DD / 128, BB), blk>>>(
        mlp_w2, hbuf, nullptr, mlp_b2, nullptr, nullptr, nullptr, nullptr,
        out, DD, 2 * DD, NN, 2 * DD);
}

// round 4
// speedup vs baseline: 1.9801x; 1.9801x over previous
#include <cuda_runtime.h>
#include <cuda_bf16.h>
#include <math.h>
#include <stdint.h>

// Problem constants
#define BB 4
#define DD 1024
#define NN 4096
#define HH 16
#define KK 128
#define DHH 64

typedef unsigned long long ull;
typedef unsigned int uint;

// ---------------- scratch (device globals) ----------------
__device__ float g_q [(size_t)BB * DD * NN];
__device__ float g_k [(size_t)BB * DD * NN];
__device__ float g_kp[(size_t)BB * DD * KK];
__device__ float g_msg[(size_t)BB * DD * NN];

// packed bf16 (hi | lo<<16) buffers
__device__ uint g_ws_q[(size_t)DD * DD];
__device__ uint g_ws_k[(size_t)DD * DD];
__device__ uint g_ws_m[(size_t)DD * DD];
__device__ uint g_ws_1[(size_t)(2 * DD) * (2 * DD)];
__device__ uint g_ws_2[(size_t)DD * (2 * DD)];
__device__ uint g_xs   [(size_t)BB * NN * DD];      // [B,N,D] transposed packed
__device__ uint g_srcs [(size_t)BB * NN * DD];
__device__ uint g_msgs [(size_t)BB * NN * DD];
__device__ uint g_msg2s[(size_t)BB * NN * DD];
__device__ uint g_hs   [(size_t)BB * NN * 2 * DD];

// ---------------- helpers ----------------
__device__ __forceinline__ uint32_t smem_to_u32(const void* p) {
    uint32_t a;
    asm("{ .reg .u64 t; cvta.to.shared.u64 t, %1; cvt.u32.u64 %0, t; }"
        : "=r"(a) : "l"(p));
    return a;
}
__device__ __forceinline__ uint prmt(uint a, uint b, uint s) {
    uint r; asm("prmt.b32 %0, %1, %2, %3;" : "=r"(r) : "r"(a), "r"(b), "r"(s));
    return r;
}
__device__ __forceinline__ void sts_v2(uint32_t addr, uint x, uint y) {
    asm volatile("st.shared.v2.b32 [%0], {%1, %2};" :: "r"(addr), "r"(x), "r"(y));
}
__device__ __forceinline__ uint lds32(uint32_t addr) {
    uint r;
    asm volatile("ld.shared.b32 %0, [%1];" : "=r"(r) : "r"(addr));
    return r;
}

// HMMA m16n8k16 bf16: D(f32) += A(bf16) * B(bf16)
__device__ __forceinline__ void mma16816(float* c, const uint* a, uint b0, uint b1) {
    asm volatile(
        "mma.sync.aligned.m16n8k16.row.col.f32.bf16.bf16.f32 "
        "{%0,%1,%2,%3}, {%4,%5,%6,%7}, {%8,%9}, {%0,%1,%2,%3};"
        : "+f"(c[0]), "+f"(c[1]), "+f"(c[2]), "+f"(c[3])
        : "r"(a[0]), "r"(a[1]), "r"(a[2]), "r"(a[3]), "r"(b0), "r"(b1));
}

// ---- packed f32x2 helpers (attn) ----
__device__ __forceinline__ void ffma2(ull& d, ull a, ull b) {
    asm("fma.rn.f32x2 %0, %1, %2, %0;" : "+l"(d) : "l"(a), "l"(b));
}
__device__ __forceinline__ ull pack2(float x, float y) {
    ull r; asm("mov.b64 %0, {%1, %2};" : "=l"(r) : "f"(x), "f"(y)); return r;
}
__device__ __forceinline__ void unpack2(ull v, float& lo, float& hi) {
    asm("mov.b64 {%0, %1}, %2;" : "=f"(lo), "=f"(hi) : "l"(v));
}

__device__ __forceinline__ uint pack_split(float v) {
    __nv_bfloat16 h = __float2bfloat16(v);
    float hv = __bfloat162float(h);
    __nv_bfloat16 l = __float2bfloat16(v - hv);
    return (uint)__bfloat16_as_ushort(h) | ((uint)__bfloat16_as_ushort(l) << 16);
}

// ---------------------------------------------------------------------------
// Elementwise weight split: fp32 -> packed (bf16 hi | bf16 lo << 16)
// ---------------------------------------------------------------------------
__global__ void weight_split(const float* __restrict__ in, uint* __restrict__ out, int n) {
    int i = blockIdx.x * 256 + threadIdx.x;
    if (i < n) out[i] = pack_split(in[i]);
}

// ---------------------------------------------------------------------------
// Transpose + split: fp32 [B, C, N] -> packed uint [B, N, C]
// ---------------------------------------------------------------------------
__global__ void transpose_split(const float* __restrict__ in, uint* __restrict__ out,
                                int C, int Nw) {
    __shared__ float tile[32][33];
    const int b = blockIdx.z;
    const int n0 = blockIdx.x * 32, c0 = blockIdx.y * 32;
    const int tx = threadIdx.x, ty = threadIdx.y;
    const float* inb = in + ((size_t)b * C + c0) * Nw + n0;
#pragma unroll
    for (int i = 0; i < 32; i += 8)
        tile[ty + i][tx] = inb[(size_t)(ty + i) * Nw + tx];
    __syncthreads();
    uint* ob = out + ((size_t)b * Nw + n0) * C + c0;
#pragma unroll
    for (int i = 0; i < 32; i += 8)
        ob[(size_t)(ty + i) * C + tx] = pack_split(tile[tx][ty + i]);
}

// ---------------------------------------------------------------------------
// Warp-level HMMA bf16x3 GEMM.
//   out[b,m,n] = sum_k W[m,k] * In(b,k,n) + bias[m]
//   Asp: packed weights [M, Kd] (k-contiguous)
//   B1/B2: packed transposed activations [B, Nw, k] (k-contiguous);
//          concat on k: k < K1 -> B1 (row stride K1), else B2 (stride Kd-K1)
// CTA 128x128, KC=32, double-buffered smem hi/lo planes (row stride 80B).
// 8 warps as 4(M) x 2(N); warp tile 32x64; m16n8k16 fragments via lds.32.
// MODE: 0 = fp32 out [B,M,Nw]; 1 = +bias pack-transpose out [B,Nw,M];
//       2 = +bias, BN, ReLU, pack-transpose out.
// ---------------------------------------------------------------------------
#define PL_A_HI 0
#define PL_A_LO 10240
#define PL_B_HI 20480
#define PL_B_LO 30720
#define SM_BUF  40960
#define SM_TOTAL (2 * SM_BUF)

template <int MODE>
__global__ void __launch_bounds__(256) hmma_gemm(
    const uint* __restrict__ Asp,
    const uint* __restrict__ B1,
    const uint* __restrict__ B2,
    const float* __restrict__ bias,
    const float* __restrict__ gamma,
    const float* __restrict__ beta,
    const float* __restrict__ mean,
    const float* __restrict__ var,
    float* __restrict__ outF,
    uint* __restrict__ outT,
    int M, int Kd, int Nw, int K1)
{
    extern __shared__ char smem[];
    const uint32_t sb = smem_to_u32(smem);

    const int tid  = threadIdx.x;
    const int wid  = tid >> 5;
    const int lane = tid & 31;
    const int m0 = blockIdx.y * 128;
    const int n0 = blockIdx.x * 128;
    const int bb = blockIdx.z;

    const int wm = wid & 3;       // warp m tile (32 rows)
    const int wn = wid >> 2;      // warp n tile (64 cols)

    // loader indices: idx = it*256+tid; row = idx>>3 (0..127), kq = idx&7
    const int lrow = tid >> 3;
    const int lkq  = tid & 7;
    const int K2 = Kd - K1;

    float c[2][8][4];
#pragma unroll
    for (int mt = 0; mt < 2; mt++)
#pragma unroll
        for (int nt = 0; nt < 8; nt++)
#pragma unroll
            for (int j = 0; j < 4; j++) c[mt][nt][j] = 0.f;

    const uint* Abase = Asp + (size_t)m0 * Kd;
    const int nc = Kd >> 5;   // 32-wide k chunks

    // ---- tile loader ----
    auto load_tile = [&](int ch, int buf) {
        const int k0 = ch * 32;
        const uint32_t base = sb + buf * SM_BUF;
        // A: 128 rows x 32 k (4 row-groups of 32)
#pragma unroll
        for (int it = 0; it < 4; it++) {
            const int row = it * 32 + lrow;
            uint4 v = *(const uint4*)(Abase + (size_t)row * Kd + k0 + lkq * 4);
            uint h0 = prmt(v.x, v.y, 0x5410), h1 = prmt(v.z, v.w, 0x5410);
            uint l0 = prmt(v.x, v.y, 0x7632), l1 = prmt(v.z, v.w, 0x7632);
            const uint32_t off = row * 80 + lkq * 8;
            sts_v2(base + PL_A_HI + off, h0, h1);
            sts_v2(base + PL_A_LO + off, l0, l1);
        }
        // B: 128 n-rows x 32 k, concat select (chunk-uniform since K1 % 32 == 0)
        const uint* Bsrc; int kloc, kstride;
        if (k0 < K1) { Bsrc = B1; kloc = k0;      kstride = K1; }
        else         { Bsrc = B2; kloc = k0 - K1; kstride = K2; }
        const uint* Bb = Bsrc + ((size_t)bb * Nw + n0) * kstride + kloc;
#pragma unroll
        for (int it = 0; it < 4; it++) {
            const int row = it * 32 + lrow;
            uint4 v = *(const uint4*)(Bb + (size_t)row * kstride + lkq * 4);
            uint h0 = prmt(v.x, v.y, 0x5410), h1 = prmt(v.z, v.w, 0x5410);
            uint l0 = prmt(v.x, v.y, 0x7632), l1 = prmt(v.z, v.w, 0x7632);
            const uint32_t off = row * 80 + lkq * 8;
            sts_v2(base + PL_B_HI + off, h0, h1);
            sts_v2(base + PL_B_LO + off, l0, l1);
        }
    };

    load_tile(0, 0);
    __syncthreads();

    // fragment base addresses (byte): element (r, k) at r*80 + k*2
    const int fr = lane >> 2;            // group row / n-col
    const int fc = (lane & 3) * 2;       // k pair base
    const uint32_t aRow = (wm * 32) * 80 + fc * 2;   // + mt*16*80 + ks*2*?  (k bytes = k*2)
    const uint32_t bRow = (wn * 64) * 80 + fc * 2;

    for (int ch = 0; ch < nc; ch++) {
        const int buf = ch & 1;
        const uint32_t base = sb + buf * SM_BUF;
        // prefetch next chunk into other buffer AFTER compute? No:
        // simple scheme: compute current, then load next, sync.
#pragma unroll
        for (int ks = 0; ks < 32; ks += 16) {
            // A fragments (hi & lo), 2 m-tiles
            uint ah[2][4], al[2][4];
#pragma unroll
            for (int mt = 0; mt < 2; mt++) {
                const uint32_t a0 = base + aRow + (mt * 16 + fr) * 80 + ks * 2;
                ah[mt][0] = lds32(PL_A_HI + a0);
                ah[mt][1] = lds32(PL_A_HI + a0 + 8 * 80);
                ah[mt][2] = lds32(PL_A_HI + a0 + 16);
                ah[mt][3] = lds32(PL_A_HI + a0 + 8 * 80 + 16);
                al[mt][0] = lds32(PL_A_LO + a0);
                al[mt][1] = lds32(PL_A_LO + a0 + 8 * 80);
                al[mt][2] = lds32(PL_A_LO + a0 + 16);
                al[mt][3] = lds32(PL_A_LO + a0 + 8 * 80 + 16);
            }
#pragma unroll
            for (int nt = 0; nt < 8; nt++) {
                const uint32_t b0a = base + bRow + (nt * 8 + fr) * 80 + ks * 2;
                uint bh0 = lds32(PL_B_HI + b0a);
                uint bh1 = lds32(PL_B_HI + b0a + 16);
                uint bl0 = lds32(PL_B_LO + b0a);
                uint bl1 = lds32(PL_B_LO + b0a + 16);
#pragma unroll
                for (int mt = 0; mt < 2; mt++) {
                    mma16816(c[mt][nt], ah[mt], bh0, bh1);
                    mma16816(c[mt][nt], ah[mt], bl0, bl1);
                    mma16816(c[mt][nt], al[mt], bh0, bh1);
                }
            }
        }
        if (ch + 1 < nc) {
            __syncthreads();               // done reading buf^1 from prev load
            load_tile(ch + 1, buf ^ 1);
            __syncthreads();
        }
    }

    // ---- epilogue ----
    const int cm = m0 + wm * 32 + fr;        // +mt*16, +8 variants
    const int cn = n0 + wn * 64 + fc;        // +nt*8, +1 variants
#pragma unroll
    for (int mt = 0; mt < 2; mt++) {
        const int mlo = cm + mt * 16;
        const int mhi = mlo + 8;
        float bi0 = bias[mlo], bi1 = bias[mhi];
        float sc0 = 1.f, sh0 = 0.f, sc1 = 1.f, sh1 = 0.f;
        if (MODE == 2) {
            sc0 = gamma[mlo] * rsqrtf(var[mlo] + 1e-3f);
            sh0 = beta[mlo] - mean[mlo] * sc0 + bi0 * sc0;
            sc1 = gamma[mhi] * rsqrtf(var[mhi] + 1e-3f);
            sh1 = beta[mhi] - mean[mhi] * sc1 + bi1 * sc1;
        }
#pragma unroll
        for (int nt = 0; nt < 8; nt++) {
            const int n = cn + nt * 8;
            float v0 = c[mt][nt][0], v1 = c[mt][nt][1];
            float v2 = c[mt][nt][2], v3 = c[mt][nt][3];
            if (MODE == 2) {
                v0 = fmaxf(fmaf(v0, sc0, sh0), 0.f);
                v1 = fmaxf(fmaf(v1, sc0, sh0), 0.f);
                v2 = fmaxf(fmaf(v2, sc1, sh1), 0.f);
                v3 = fmaxf(fmaf(v3, sc1, sh1), 0.f);
            } else {
                v0 += bi0; v1 += bi0; v2 += bi1; v3 += bi1;
            }
            if (MODE == 0) {
                *(float2*)(outF + ((size_t)bb * M + mlo) * Nw + n) = make_float2(v0, v1);
                *(float2*)(outF + ((size_t)bb * M + mhi) * Nw + n) = make_float2(v2, v3);
            } else {
                uint* ob = outT + (size_t)bb * Nw * M;
                ob[(size_t)(n)     * M + mlo] = pack_split(v0);
                ob[(size_t)(n + 1) * M + mlo] = pack_split(v1);
                ob[(size_t)(n)     * M + mhi] = pack_split(v2);
                ob[(size_t)(n + 1) * M + mhi] = pack_split(v3);
            }
        }
    }
}

// ---------------------------------------------------------------------------
// Linformer projection (fp32, small): C[r,c] += A[r,m] * P[m,c]
// ---------------------------------------------------------------------------
__global__ void __launch_bounds__(256) proj_gemm(
    const float* __restrict__ A, const float* __restrict__ P, float* __restrict__ C)
{
    __shared__ float As[8][128];
    __shared__ float Bs[8][128];

    const int t  = threadIdx.x;
    const int ty = t >> 4;
    const int tx = t & 15;
    const int r0 = blockIdx.x * 128;
    const int chunk = NN / gridDim.y;
    const int c0 = blockIdx.y * chunk;

    const int ar = t >> 1, ac = (t & 1) * 4;
    const int br = t >> 5, bc = (t & 31) * 4;

    float acc[8][8];
#pragma unroll
    for (int i = 0; i < 8; i++)
#pragma unroll
        for (int j = 0; j < 8; j++) acc[i][j] = 0.f;

    for (int kt = 0; kt < chunk; kt += 8) {
        const int kb = c0 + kt;
        float4 av = *(const float4*)(A + (size_t)(r0 + ar) * NN + kb + ac);
        As[ac + 0][ar] = av.x;
        As[ac + 1][ar] = av.y;
        As[ac + 2][ar] = av.z;
        As[ac + 3][ar] = av.w;
        *(float4*)&Bs[br][bc] = *(const float4*)(P + (size_t)(kb + br) * KK + bc);
        __syncthreads();
#pragma unroll
        for (int kk = 0; kk < 8; kk++) {
            float a[8], bv[8];
#pragma unroll
            for (int i = 0; i < 8; i++) a[i] = As[kk][ty * 8 + i];
#pragma unroll
            for (int j = 0; j < 8; j++) bv[j] = Bs[kk][tx * 8 + j];
#pragma unroll
            for (int i = 0; i < 8; i++)
#pragma unroll
                for (int j = 0; j < 8; j++)
                    acc[i][j] = fmaf(a[i], bv[j], acc[i][j]);
        }
        __syncthreads();
    }

#pragma unroll
    for (int i = 0; i < 8; i++)
#pragma unroll
        for (int j = 0; j < 8; j++)
            atomicAdd(&C[(size_t)(r0 + ty * 8 + i) * KK + tx * 8 + j], acc[i][j]);
}

// ---------------------------------------------------------------------------
// Fused Linformer attention (f32x2, transposed K in smem).
// ---------------------------------------------------------------------------
#define KST_STRIDE 66

__global__ void attn_kernel(const float* __restrict__ q,
                            const float* __restrict__ kp,
                            float* __restrict__ msg)
{
    extern __shared__ float sm[];
    float* KsT = sm;
    float* Es  = sm + KK * KST_STRIDE;

    const int tid = threadIdx.x;
    const int n = blockIdx.x * 128 + tid;
    const int h = blockIdx.y;
    const int b = blockIdx.z;

#pragma unroll 4
    for (int dh = 0; dh < DHH; dh++)
        KsT[tid * KST_STRIDE + dh] = kp[((size_t)b * DD + (size_t)dh * HH + h) * KK + tid];
    __syncthreads();

    const float* qb = q + ((size_t)b * DD + h) * NN + n;
    ull qv2[DHH / 2];
#pragma unroll
    for (int dhp = 0; dhp < DHH / 2; dhp++) {
        float x = qb[(size_t)(2 * dhp) * HH * NN];
        float y = qb[(size_t)(2 * dhp + 1) * HH * NN];
        qv2[dhp] = pack2(x, y);
    }

    float mx = -1e30f;
    for (int k = 0; k < KK; k++) {
        ull s2 = 0ULL;
        const float* krow = KsT + k * KST_STRIDE;
#pragma unroll
        for (int dhp = 0; dhp < DHH / 2; dhp++)
            ffma2(s2, qv2[dhp], *(const ull*)(krow + 2 * dhp));
        float lo, hi;
        unpack2(s2, lo, hi);
        float s = (lo + hi) * 0.125f;
        Es[k * 128 + tid] = s;
        mx = fmaxf(mx, s);
    }

    float sum = 0.f;
    for (int k = 0; k < KK; k++) {
        float e = __expf(Es[k * 128 + tid] - mx);
        Es[k * 128 + tid] = e;
        sum += e;
    }
    const float inv = 1.f / sum;

    ull acc2[DHH / 2];
#pragma unroll
    for (int dhp = 0; dhp < DHH / 2; dhp++) acc2[dhp] = 0ULL;

    for (int k = 0; k < KK; k++) {
        float e = Es[k * 128 + tid];
        ull e2 = pack2(e, e);
        const float* krow = KsT + k * KST_STRIDE;
#pragma unroll
        for (int dhp = 0; dhp < DHH / 2; dhp++)
            ffma2(acc2[dhp], e2, *(const ull*)(krow + 2 * dhp));
    }

    float* msgb = msg + ((size_t)b * DD + h) * NN + n;
#pragma unroll
    for (int dhp = 0; dhp < DHH / 2; dhp++) {
        float lo, hi;
        unpack2(acc2[dhp], lo, hi);
        msgb[(size_t)(2 * dhp) * HH * NN]     = lo * inv;
        msgb[(size_t)(2 * dhp + 1) * HH * NN] = hi * inv;
    }
}

// ---------------------------------------------------------------------------
extern "C" void kernel_launch(void* const* d_in, const int* in_sizes, int n_in,
                              void* d_out, int out_size)
{
    const float* x       = (const float*)d_in[0];
    const float* source  = (const float*)d_in[1];
    const float* to_q_w  = (const float*)d_in[2];
    const float* to_q_b  = (const float*)d_in[3];
    const float* to_k_w  = (const float*)d_in[4];
    const float* to_k_b  = (const float*)d_in[5];
    const float* proj_k  = (const float*)d_in[6];
    const float* merge_w = (const float*)d_in[7];
    const float* merge_b = (const float*)d_in[8];
    const float* mlp_w1  = (const float*)d_in[9];
    const float* mlp_b1  = (const float*)d_in[10];
    const float* bn_g    = (const float*)d_in[11];
    const float* bn_b    = (const float*)d_in[12];
    const float* bn_m    = (const float*)d_in[13];
    const float* bn_v    = (const float*)d_in[14];
    const float* mlp_w2  = (const float*)d_in[15];
    const float* mlp_b2  = (const float*)d_in[16];
    float* out = (float*)d_out;

    float *q, *k, *kp, *msg;
    uint *wsq, *wsk, *wsm, *ws1, *ws2, *xs, *srcs, *msgs, *msg2s, *hs;
    cudaGetSymbolAddress((void**)&q,    g_q);
    cudaGetSymbolAddress((void**)&k,    g_k);
    cudaGetSymbolAddress((void**)&kp,   g_kp);
    cudaGetSymbolAddress((void**)&msg,  g_msg);
    cudaGetSymbolAddress((void**)&wsq,  g_ws_q);
    cudaGetSymbolAddress((void**)&wsk,  g_ws_k);
    cudaGetSymbolAddress((void**)&wsm,  g_ws_m);
    cudaGetSymbolAddress((void**)&ws1,  g_ws_1);
    cudaGetSymbolAddress((void**)&ws2,  g_ws_2);
    cudaGetSymbolAddress((void**)&xs,   g_xs);
    cudaGetSymbolAddress((void**)&srcs, g_srcs);
    cudaGetSymbolAddress((void**)&msgs, g_msgs);
    cudaGetSymbolAddress((void**)&msg2s,g_msg2s);
    cudaGetSymbolAddress((void**)&hs,   g_hs);

    cudaFuncSetAttribute(hmma_gemm<0>, cudaFuncAttributeMaxDynamicSharedMemorySize, SM_TOTAL);
    cudaFuncSetAttribute(hmma_gemm<1>, cudaFuncAttributeMaxDynamicSharedMemorySize, SM_TOTAL);
    cudaFuncSetAttribute(hmma_gemm<2>, cudaFuncAttributeMaxDynamicSharedMemorySize, SM_TOTAL);

    // 0) split weights into packed bf16(hi,lo)
    weight_split<<<(DD * DD + 255) / 256, 256>>>(to_q_w, wsq, DD * DD);
    weight_split<<<(DD * DD + 255) / 256, 256>>>(to_k_w, wsk, DD * DD);
    weight_split<<<(DD * DD + 255) / 256, 256>>>(merge_w, wsm, DD * DD);
    weight_split<<<(4 * DD * DD + 255) / 256, 256>>>(mlp_w1, ws1, 4 * DD * DD);
    weight_split<<<(2 * DD * DD + 255) / 256, 256>>>(mlp_w2, ws2, 2 * DD * DD);

    // 0b) transpose-split activations: x, source
    transpose_split<<<dim3(NN / 32, DD / 32, BB), dim3(32, 8)>>>(x, xs, DD, NN);
    transpose_split<<<dim3(NN / 32, DD / 32, BB), dim3(32, 8)>>>(source, srcs, DD, NN);

    // 1) q = Wq @ x + bq   (fp32 out)
    hmma_gemm<0><<<dim3(NN / 128, DD / 128, BB), 256, SM_TOTAL>>>(
        wsq, xs, xs, to_q_b, nullptr, nullptr, nullptr, nullptr,
        q, nullptr, DD, DD, NN, DD);

    // 2) k = Wk @ source + bk
    hmma_gemm<0><<<dim3(NN / 128, DD / 128, BB), 256, SM_TOTAL>>>(
        wsk, srcs, srcs, to_k_b, nullptr, nullptr, nullptr, nullptr,
        k, nullptr, DD, DD, NN, DD);

    // 3) kp = k @ proj_k   (split-K x8 fp32)
    cudaMemsetAsync(kp, 0, sizeof(float) * (size_t)BB * DD * KK);
    proj_gemm<<<dim3((BB * DD) / 128, 8), 256>>>(k, proj_k, kp);

    // 4) fused attention -> msg (fp32)
    const int attn_smem = (KK * KST_STRIDE + 128 * KK) * (int)sizeof(float);
    cudaFuncSetAttribute(attn_kernel, cudaFuncAttributeMaxDynamicSharedMemorySize, attn_smem);
    attn_kernel<<<dim3(NN / 128, HH, BB), dim3(128), attn_smem>>>(q, kp, msg);

    // 4b) transpose-split msg
    transpose_split<<<dim3(NN / 32, DD / 32, BB), dim3(32, 8)>>>(msg, msgs, DD, NN);

    // 5) msg2 = Wm @ msg + bm  (pack-transposed out)
    hmma_gemm<1><<<dim3(NN / 128, DD / 128, BB), 256, SM_TOTAL>>>(
        wsm, msgs, msgs, merge_b, nullptr, nullptr, nullptr, nullptr,
        nullptr, msg2s, DD, DD, NN, DD);

    // 6) h = relu(BN(W1 @ concat(x, msg2) + b1))  (pack-transposed out)
    hmma_gemm<2><<<dim3(NN / 128, (2 * DD) / 128, BB), 256, SM_TOTAL>>>(
        ws1, xs, msg2s, mlp_b1, bn_g, bn_b, bn_m, bn_v,
        nullptr, hs, 2 * DD, 2 * DD, NN, DD);

    // 7) out = W2 @ h + b2  (fp32 out)
    hmma_gemm<0><<<dim3(NN / 128, DD / 128, BB), 256, SM_TOTAL>>>(
        ws2, hs, hs, mlp_b2, nullptr, nullptr, nullptr, nullptr,
        out, nullptr, DD, 2 * DD, NN, 2 * DD);
}

// round 5
// speedup vs baseline: 2.6217x; 1.3240x over previous
#include <cuda_runtime.h>
#include <cuda_bf16.h>
#include <math.h>
#include <stdint.h>

// Problem constants
#define BB 4
#define DD 1024
#define NN 4096
#define HH 16
#define KK 128
#define DHH 64

typedef unsigned long long ull;
typedef unsigned int uint;

// ---------------- scratch (device globals) ----------------
__device__ float g_q   [(size_t)BB * DD * NN];   // fp32 q
__device__ float g_msg [(size_t)BB * DD * NN];   // fp32 msg
__device__ float g_kp  [(size_t)BB * DD * KK];   // projected k/v
__device__ float g_srcp[(size_t)BB * DD * KK];   // src @ proj
__device__ float g_scol[KK];                     // colsum(proj)

// packed bf16 (hi | lo<<16) buffers
__device__ uint g_ws_q[(size_t)DD * DD];
__device__ uint g_ws_m[(size_t)DD * DD];
__device__ uint g_ws_1[(size_t)(2 * DD) * (2 * DD)];
__device__ uint g_ws_2[(size_t)DD * (2 * DD)];
__device__ uint g_xs   [(size_t)BB * NN * DD];   // [B,N,D] packed
__device__ uint g_msgs [(size_t)BB * NN * DD];
__device__ uint g_msg2s[(size_t)BB * NN * DD];
__device__ uint g_hs   [(size_t)BB * NN * 2 * DD];

// ---------------- helpers ----------------
__device__ __forceinline__ uint32_t smem_to_u32(const void* p) {
    uint32_t a;
    asm("{ .reg .u64 t; cvta.to.shared.u64 t, %1; cvt.u32.u64 %0, t; }"
        : "=r"(a) : "l"(p));
    return a;
}
__device__ __forceinline__ uint prmt(uint a, uint b, uint s) {
    uint r; asm("prmt.b32 %0, %1, %2, %3;" : "=r"(r) : "r"(a), "r"(b), "r"(s));
    return r;
}
__device__ __forceinline__ void sts_v2(uint32_t addr, uint x, uint y) {
    asm volatile("st.shared.v2.b32 [%0], {%1, %2};" :: "r"(addr), "r"(x), "r"(y));
}
__device__ __forceinline__ void ldsm4(uint* r, uint32_t addr) {
    asm volatile("ldmatrix.sync.aligned.m8n8.x4.shared.b16 {%0,%1,%2,%3}, [%4];"
        : "=r"(r[0]), "=r"(r[1]), "=r"(r[2]), "=r"(r[3]) : "r"(addr));
}

// HMMA m16n8k16 bf16: D(f32) += A(bf16) * B(bf16)
__device__ __forceinline__ void mma16816(float* c, const uint* a, uint b0, uint b1) {
    asm volatile(
        "mma.sync.aligned.m16n8k16.row.col.f32.bf16.bf16.f32 "
        "{%0,%1,%2,%3}, {%4,%5,%6,%7}, {%8,%9}, {%0,%1,%2,%3};"
        : "+f"(c[0]), "+f"(c[1]), "+f"(c[2]), "+f"(c[3])
        : "r"(a[0]), "r"(a[1]), "r"(a[2]), "r"(a[3]), "r"(b0), "r"(b1));
}

// ---- packed f32x2 helpers ----
__device__ __forceinline__ void ffma2(ull& d, ull a, ull b) {
    asm("fma.rn.f32x2 %0, %1, %2, %0;" : "+l"(d) : "l"(a), "l"(b));
}
__device__ __forceinline__ ull pack2(float x, float y) {
    ull r; asm("mov.b64 %0, {%1, %2};" : "=l"(r) : "f"(x), "f"(y)); return r;
}
__device__ __forceinline__ void unpack2(ull v, float& lo, float& hi) {
    asm("mov.b64 {%0, %1}, %2;" : "=f"(lo), "=f"(hi) : "l"(v));
}
__device__ __forceinline__ uint pack_split(float v) {
    __nv_bfloat16 h = __float2bfloat16(v);
    float hv = __bfloat162float(h);
    __nv_bfloat16 l = __float2bfloat16(v - hv);
    return (uint)__bfloat16_as_ushort(h) | ((uint)__bfloat16_as_ushort(l) << 16);
}

// ---------------------------------------------------------------------------
__global__ void weight_split(const float* __restrict__ in, uint* __restrict__ out, int n) {
    int i = blockIdx.x * 256 + threadIdx.x;
    if (i < n) out[i] = pack_split(in[i]);
}

__global__ void transpose_split(const float* __restrict__ in, uint* __restrict__ out,
                                int C, int Nw) {
    __shared__ float tile[32][33];
    const int b = blockIdx.z;
    const int n0 = blockIdx.x * 32, c0 = blockIdx.y * 32;
    const int tx = threadIdx.x, ty = threadIdx.y;
    const float* inb = in + ((size_t)b * C + c0) * Nw + n0;
#pragma unroll
    for (int i = 0; i < 32; i += 8)
        tile[ty + i][tx] = inb[(size_t)(ty + i) * Nw + tx];
    __syncthreads();
    uint* ob = out + ((size_t)b * Nw + n0) * C + c0;
#pragma unroll
    for (int i = 0; i < 32; i += 8)
        ob[(size_t)(ty + i) * C + tx] = pack_split(tile[tx][ty + i]);
}

// colsum of proj: S[c] = sum_m proj[m, c]
__global__ void colsum_kernel(const float* __restrict__ proj, float* __restrict__ S) {
    const int c = threadIdx.x;
    float s = 0.f;
#pragma unroll 8
    for (int m = 0; m < NN; m++) s += proj[(size_t)m * KK + c];
    S[c] = s;
}

// kp init: kp[b,d,c] = bk[d] * S[c]
__global__ void kp_init(const float* __restrict__ bk, const float* __restrict__ S,
                        float* __restrict__ kp) {
    int i = blockIdx.x * 256 + threadIdx.x;
    int c = i & (KK - 1);
    int d = (i >> 7) & (DD - 1);
    kp[i] = bk[d] * S[c];
}

// ---------------------------------------------------------------------------
// Warp-level HMMA bf16x3 GEMM with ldmatrix fragments + LDG prefetch pipeline.
//   out[b,m,n] = sum_k W[m,k] * In(b,k,n) + bias[m]
// MODE 0: fp32 out [B,M,Nw]; 1: +bias pack-transpose out [B,Nw,M];
// MODE 2: +bias, BN, ReLU, pack-transpose out.
// CTA 128x128, KC=32, double-buffered planes (row stride 80B).
// ---------------------------------------------------------------------------
#define PL_A_HI 0
#define PL_A_LO 10240
#define PL_B_HI 20480
#define PL_B_LO 30720
#define SM_BUF  40960
#define SM_TOTAL (2 * SM_BUF)
#define STG_S 136   // staging stride (floats)

template <int MODE>
__global__ void __launch_bounds__(256, 1) hmma_gemm(
    const uint* __restrict__ Asp,
    const uint* __restrict__ B1,
    const uint* __restrict__ B2,
    const float* __restrict__ bias,
    const float* __restrict__ gamma,
    const float* __restrict__ beta,
    const float* __restrict__ mean,
    const float* __restrict__ var,
    float* __restrict__ outF,
    uint* __restrict__ outT,
    int M, int Kd, int Nw, int K1)
{
    extern __shared__ char smem[];
    const uint32_t sb = smem_to_u32(smem);

    const int tid  = threadIdx.x;
    const int wid  = tid >> 5;
    const int lane = tid & 31;
    const int m0 = blockIdx.y * 128;
    const int n0 = blockIdx.x * 128;
    const int bb = blockIdx.z;

    const int wm = wid & 3;
    const int wn = wid >> 2;
    const int lrow = tid >> 3;
    const int lkq  = tid & 7;
    const int K2 = Kd - K1;
    const int fr = lane >> 2;
    const int fc = (lane & 3) * 2;

    float c[2][8][4];
#pragma unroll
    for (int mt = 0; mt < 2; mt++)
#pragma unroll
        for (int nt = 0; nt < 8; nt++)
#pragma unroll
            for (int j = 0; j < 4; j++) c[mt][nt][j] = 0.f;

    const uint* Abase = Asp + (size_t)m0 * Kd;
    const int nc = Kd >> 5;

    uint4 pa[4], pb[4];

    auto ldg_tile = [&](int ch) {
        const int k0 = ch * 32;
#pragma unroll
        for (int it = 0; it < 4; it++)
            pa[it] = *(const uint4*)(Abase + (size_t)(it * 32 + lrow) * Kd + k0 + lkq * 4);
        const uint* Bsrc; int kloc, kstride;
        if (k0 < K1) { Bsrc = B1; kloc = k0;      kstride = K1; }
        else         { Bsrc = B2; kloc = k0 - K1; kstride = K2; }
        const uint* Bb = Bsrc + ((size_t)bb * Nw + n0) * kstride + kloc;
#pragma unroll
        for (int it = 0; it < 4; it++)
            pb[it] = *(const uint4*)(Bb + (size_t)(it * 32 + lrow) * kstride + lkq * 4);
    };
    auto sts_tile = [&](int buf) {
        const uint32_t base = sb + buf * SM_BUF;
#pragma unroll
        for (int it = 0; it < 4; it++) {
            const uint32_t off = (uint32_t)(it * 32 + lrow) * 80 + lkq * 8;
            uint4 v = pa[it];
            sts_v2(base + PL_A_HI + off, prmt(v.x, v.y, 0x5410), prmt(v.z, v.w, 0x5410));
            sts_v2(base + PL_A_LO + off, prmt(v.x, v.y, 0x7632), prmt(v.z, v.w, 0x7632));
            v = pb[it];
            sts_v2(base + PL_B_HI + off, prmt(v.x, v.y, 0x5410), prmt(v.z, v.w, 0x5410));
            sts_v2(base + PL_B_LO + off, prmt(v.x, v.y, 0x7632), prmt(v.z, v.w, 0x7632));
        }
    };

    ldg_tile(0);
    sts_tile(0);
    __syncthreads();

    const uint32_t aOff = (uint32_t)(wm * 32 + (lane & 15)) * 80 + ((lane >> 4) & 1) * 16;
    const uint32_t bOff = (uint32_t)(wn * 64 + (lane & 7) + ((lane & 16) ? 8 : 0)) * 80
                        + ((lane & 8) ? 16 : 0);

    for (int ch = 0; ch < nc; ch++) {
        const uint32_t base = sb + (ch & 1) * SM_BUF;
        if (ch + 1 < nc) ldg_tile(ch + 1);
#pragma unroll
        for (int ksb = 0; ksb <= 32; ksb += 32) {
            uint ah[2][4], al[2][4];
            ldsm4(ah[0], base + PL_A_HI + aOff + ksb);
            ldsm4(ah[1], base + PL_A_HI + aOff + 1280 + ksb);
            ldsm4(al[0], base + PL_A_LO + aOff + ksb);
            ldsm4(al[1], base + PL_A_LO + aOff + 1280 + ksb);
            uint bh[4][4], bl[4][4];
#pragma unroll
            for (int np = 0; np < 4; np++) {
                ldsm4(bh[np], base + PL_B_HI + bOff + np * 1280 + ksb);
                ldsm4(bl[np], base + PL_B_LO + bOff + np * 1280 + ksb);
            }
#pragma unroll
            for (int np = 0; np < 4; np++)
#pragma unroll
                for (int sub = 0; sub < 2; sub++) {
                    const int nt = np * 2 + sub;
                    const uint b0h = bh[np][sub * 2], b1h = bh[np][sub * 2 + 1];
                    const uint b0l = bl[np][sub * 2], b1l = bl[np][sub * 2 + 1];
#pragma unroll
                    for (int mt = 0; mt < 2; mt++) {
                        mma16816(c[mt][nt], ah[mt], b0h, b1h);
                        mma16816(c[mt][nt], ah[mt], b0l, b1l);
                        mma16816(c[mt][nt], al[mt], b0h, b1h);
                    }
                }
        }
        if (ch + 1 < nc) {
            sts_tile((ch + 1) & 1);
            __syncthreads();
        }
    }

    // ---- epilogue ----
    if (MODE == 0) {
        const int cm = m0 + wm * 32 + fr;
        const int cn = n0 + wn * 64 + fc;
#pragma unroll
        for (int mt = 0; mt < 2; mt++) {
            const int mlo = cm + mt * 16;
            const int mhi = mlo + 8;
            const float bi0 = bias[mlo], bi1 = bias[mhi];
#pragma unroll
            for (int nt = 0; nt < 8; nt++) {
                const int n = cn + nt * 8;
                *(float2*)(outF + ((size_t)bb * M + mlo) * Nw + n) =
                    make_float2(c[mt][nt][0] + bi0, c[mt][nt][1] + bi0);
                *(float2*)(outF + ((size_t)bb * M + mhi) * Nw + n) =
                    make_float2(c[mt][nt][2] + bi1, c[mt][nt][3] + bi1);
            }
        }
    } else {
        float* stg = (float*)smem;   // 64 x 136 fp32 staging (reuses gemm smem)
        uint* ob = outT + (size_t)bb * Nw * M;
#pragma unroll
        for (int p = 0; p < 2; p++) {
            __syncthreads();
            if (wn == p) {
#pragma unroll
                for (int mt = 0; mt < 2; mt++) {
                    const int mloL = wm * 32 + mt * 16 + fr;
                    const int mhiL = mloL + 8;
                    const int mlo = m0 + mloL, mhi = m0 + mhiL;
                    float sc0 = 1.f, sh0 = bias[mlo], sc1 = 1.f, sh1 = bias[mhi];
                    if (MODE == 2) {
                        sc0 = gamma[mlo] * rsqrtf(var[mlo] + 1e-3f);
                        sh0 = beta[mlo] + (sh0 - mean[mlo]) * sc0;
                        sc1 = gamma[mhi] * rsqrtf(var[mhi] + 1e-3f);
                        sh1 = beta[mhi] + (sh1 - mean[mhi]) * sc1;
                    }
#pragma unroll
                    for (int nt = 0; nt < 8; nt++) {
                        const int nl = fc + nt * 8;
                        float v0 = c[mt][nt][0], v1 = c[mt][nt][1];
                        float v2 = c[mt][nt][2], v3 = c[mt][nt][3];
                        if (MODE == 2) {
                            v0 = fmaxf(fmaf(v0, sc0, sh0), 0.f);
                            v1 = fmaxf(fmaf(v1, sc0, sh0), 0.f);
                            v2 = fmaxf(fmaf(v2, sc1, sh1), 0.f);
                            v3 = fmaxf(fmaf(v3, sc1, sh1), 0.f);
                        } else {
                            v0 += sh0; v1 += sh0; v2 += sh1; v3 += sh1;
                        }
                        stg[(nl)     * STG_S + mloL] = v0;
                        stg[(nl + 1) * STG_S + mloL] = v1;
                        stg[(nl)     * STG_S + mhiL] = v2;
                        stg[(nl + 1) * STG_S + mhiL] = v3;
                    }
                }
            }
            __syncthreads();
            const int nb = n0 + p * 64;
#pragma unroll 4
            for (int i = 0; i < 32; i++) {
                const int idx = i * 256 + tid;
                const int nn = idx >> 7;
                const int mm = idx & 127;
                ob[(size_t)(nb + nn) * M + m0 + mm] = pack_split(stg[nn * STG_S + mm]);
            }
        }
    }
}

// ---------------------------------------------------------------------------
// fp32 split-K GEMM: C[r,c] += A[r,m] * P[m,c]  (A rows x N reduce to K cols)
// used for srcp = source @ proj  (rows = B*D, reduce N)
// ---------------------------------------------------------------------------
__global__ void __launch_bounds__(256) proj_gemm(
    const float* __restrict__ A, const float* __restrict__ P, float* __restrict__ C)
{
    __shared__ float As[8][128];
    __shared__ float Bs[8][128];

    const int t  = threadIdx.x;
    const int ty = t >> 4;
    const int tx = t & 15;
    const int r0 = blockIdx.x * 128;
    const int chunk = NN / gridDim.y;
    const int c0 = blockIdx.y * chunk;

    const int ar = t >> 1, ac = (t & 1) * 4;
    const int br = t >> 5, bc = (t & 31) * 4;

    float acc[8][8];
#pragma unroll
    for (int i = 0; i < 8; i++)
#pragma unroll
        for (int j = 0; j < 8; j++) acc[i][j] = 0.f;

    for (int kt = 0; kt < chunk; kt += 8) {
        const int kb = c0 + kt;
        float4 av = *(const float4*)(A + (size_t)(r0 + ar) * NN + kb + ac);
        As[ac + 0][ar] = av.x;
        As[ac + 1][ar] = av.y;
        As[ac + 2][ar] = av.z;
        As[ac + 3][ar] = av.w;
        *(float4*)&Bs[br][bc] = *(const float4*)(P + (size_t)(kb + br) * KK + bc);
        __syncthreads();
#pragma unroll
        for (int kk = 0; kk < 8; kk++) {
            float a[8], bv[8];
#pragma unroll
            for (int i = 0; i < 8; i++) a[i] = As[kk][ty * 8 + i];
#pragma unroll
            for (int j = 0; j < 8; j++) bv[j] = Bs[kk][tx * 8 + j];
#pragma unroll
            for (int i = 0; i < 8; i++)
#pragma unroll
                for (int j = 0; j < 8; j++)
                    acc[i][j] = fmaf(a[i], bv[j], acc[i][j]);
        }
        __syncthreads();
    }

#pragma unroll
    for (int i = 0; i < 8; i++)
#pragma unroll
        for (int j = 0; j < 8; j++)
            atomicAdd(&C[(size_t)(r0 + ty * 8 + i) * KK + tx * 8 + j], acc[i][j]);
}

// ---------------------------------------------------------------------------
// kp = Wk @ srcp (per batch), accumulated atomically onto kp_init values.
// W [DD, DD], srcp [B][DD, KK], kp [B][DD, KK]; split reduce dim by gridDim.y.
// ---------------------------------------------------------------------------
__global__ void __launch_bounds__(256) kp_gemm(
    const float* __restrict__ W, const float* __restrict__ P, float* __restrict__ C)
{
    __shared__ float As[8][128];
    __shared__ float Bs[8][128];

    const int t  = threadIdx.x;
    const int ty = t >> 4;
    const int tx = t & 15;
    const int r0 = blockIdx.x * 128;
    const int chunk = DD / gridDim.y;
    const int c0 = blockIdx.y * chunk;
    const int b = blockIdx.z;

    const float* Pb = P + (size_t)b * DD * KK;
    float* Cb = C + (size_t)b * DD * KK;

    const int ar = t >> 1, ac = (t & 1) * 4;
    const int br = t >> 5, bc = (t & 31) * 4;

    float acc[8][8];
#pragma unroll
    for (int i = 0; i < 8; i++)
#pragma unroll
        for (int j = 0; j < 8; j++) acc[i][j] = 0.f;

    for (int kt = 0; kt < chunk; kt += 8) {
        const int kb = c0 + kt;
        float4 av = *(const float4*)(W + (size_t)(r0 + ar) * DD + kb + ac);
        As[ac + 0][ar] = av.x;
        As[ac + 1][ar] = av.y;
        As[ac + 2][ar] = av.z;
        As[ac + 3][ar] = av.w;
        *(float4*)&Bs[br][bc] = *(const float4*)(Pb + (size_t)(kb + br) * KK + bc);
        __syncthreads();
#pragma unroll
        for (int kk = 0; kk < 8; kk++) {
            float a[8], bv[8];
#pragma unroll
            for (int i = 0; i < 8; i++) a[i] = As[kk][ty * 8 + i];
#pragma unroll
            for (int j = 0; j < 8; j++) bv[j] = Bs[kk][tx * 8 + j];
#pragma unroll
            for (int i = 0; i < 8; i++)
#pragma unroll
                for (int j = 0; j < 8; j++)
                    acc[i][j] = fmaf(a[i], bv[j], acc[i][j]);
        }
        __syncthreads();
    }

#pragma unroll
    for (int i = 0; i < 8; i++)
#pragma unroll
        for (int j = 0; j < 8; j++)
            atomicAdd(&Cb[(size_t)(r0 + ty * 8 + i) * KK + tx * 8 + j], acc[i][j]);
}

// ---------------------------------------------------------------------------
// Fused Linformer attention, two-pass (scores recomputed), accumulators in regs.
// smem: only KsT [128 k][66 dh] (static, 33.8 KB) -> 2 CTAs/SM.
// ---------------------------------------------------------------------------
#define KST_STRIDE 66

__global__ void __launch_bounds__(128, 2) attn_kernel(
    const float* __restrict__ q,
    const float* __restrict__ kp,
    float* __restrict__ msg)
{
    __shared__ float KsT[KK * KST_STRIDE];

    const int tid = threadIdx.x;
    const int n = blockIdx.x * 128 + tid;
    const int h = blockIdx.y;
    const int b = blockIdx.z;

#pragma unroll 4
    for (int dh = 0; dh < DHH; dh++)
        KsT[tid * KST_STRIDE + dh] = kp[((size_t)b * DD + (size_t)dh * HH + h) * KK + tid];
    __syncthreads();

    const float* qb = q + ((size_t)b * DD + h) * NN + n;
    ull qv2[DHH / 2];
#pragma unroll
    for (int dhp = 0; dhp < DHH / 2; dhp++) {
        float x = qb[(size_t)(2 * dhp) * HH * NN];
        float y = qb[(size_t)(2 * dhp + 1) * HH * NN];
        qv2[dhp] = pack2(x, y);
    }

    // pass 1: running max of (lo+hi)
    float mraw = -1e30f;
#pragma unroll 2
    for (int k = 0; k < KK; k++) {
        ull s2 = 0ULL;
        const float* krow = KsT + k * KST_STRIDE;
#pragma unroll
        for (int dhp = 0; dhp < DHH / 2; dhp++)
            ffma2(s2, qv2[dhp], *(const ull*)(krow + 2 * dhp));
        float lo, hi;
        unpack2(s2, lo, hi);
        mraw = fmaxf(mraw, lo + hi);
    }
    const float mx = mraw * 0.125f;

    // pass 2: recompute scores, exp, sum, and accumulate msg
    float sum = 0.f;
    ull acc2[DHH / 2];
#pragma unroll
    for (int dhp = 0; dhp < DHH / 2; dhp++) acc2[dhp] = 0ULL;

#pragma unroll 2
    for (int k = 0; k < KK; k++) {
        ull s2 = 0ULL;
        const float* krow = KsT + k * KST_STRIDE;
#pragma unroll
        for (int dhp = 0; dhp < DHH / 2; dhp++)
            ffma2(s2, qv2[dhp], *(const ull*)(krow + 2 * dhp));
        float lo, hi;
        unpack2(s2, lo, hi);
        const float e = __expf(fmaf(lo + hi, 0.125f, -mx));
        sum += e;
        const ull e2 = pack2(e, e);
#pragma unroll
        for (int dhp = 0; dhp < DHH / 2; dhp++)
            ffma2(acc2[dhp], e2, *(const ull*)(krow + 2 * dhp));
    }
    const float inv = 1.f / sum;

    float* msgb = msg + ((size_t)b * DD + h) * NN + n;
#pragma unroll
    for (int dhp = 0; dhp < DHH / 2; dhp++) {
        float lo, hi;
        unpack2(acc2[dhp], lo, hi);
        msgb[(size_t)(2 * dhp) * HH * NN]     = lo * inv;
        msgb[(size_t)(2 * dhp + 1) * HH * NN] = hi * inv;
    }
}

// ---------------------------------------------------------------------------
extern "C" void kernel_launch(void* const* d_in, const int* in_sizes, int n_in,
                              void* d_out, int out_size)
{
    const float* x       = (const float*)d_in[0];
    const float* source  = (const float*)d_in[1];
    const float* to_q_w  = (const float*)d_in[2];
    const float* to_q_b  = (const float*)d_in[3];
    const float* to_k_w  = (const float*)d_in[4];
    const float* to_k_b  = (const float*)d_in[5];
    const float* proj_k  = (const float*)d_in[6];
    const float* merge_w = (const float*)d_in[7];
    const float* merge_b = (const float*)d_in[8];
    const float* mlp_w1  = (const float*)d_in[9];
    const float* mlp_b1  = (const float*)d_in[10];
    const float* bn_g    = (const float*)d_in[11];
    const float* bn_b    = (const float*)d_in[12];
    const float* bn_m    = (const float*)d_in[13];
    const float* bn_v    = (const float*)d_in[14];
    const float* mlp_w2  = (const float*)d_in[15];
    const float* mlp_b2  = (const float*)d_in[16];
    float* out = (float*)d_out;

    float *q, *msg, *kp, *srcp, *scol;
    uint *wsq, *wsm, *ws1, *ws2, *xs, *msgs, *msg2s, *hs;
    cudaGetSymbolAddress((void**)&q,    g_q);
    cudaGetSymbolAddress((void**)&msg,  g_msg);
    cudaGetSymbolAddress((void**)&kp,   g_kp);
    cudaGetSymbolAddress((void**)&srcp, g_srcp);
    cudaGetSymbolAddress((void**)&scol, g_scol);
    cudaGetSymbolAddress((void**)&wsq,  g_ws_q);
    cudaGetSymbolAddress((void**)&wsm,  g_ws_m);
    cudaGetSymbolAddress((void**)&ws1,  g_ws_1);
    cudaGetSymbolAddress((void**)&ws2,  g_ws_2);
    cudaGetSymbolAddress((void**)&xs,   g_xs);
    cudaGetSymbolAddress((void**)&msgs, g_msgs);
    cudaGetSymbolAddress((void**)&msg2s,g_msg2s);
    cudaGetSymbolAddress((void**)&hs,   g_hs);

    cudaFuncSetAttribute(hmma_gemm<0>, cudaFuncAttributeMaxDynamicSharedMemorySize, SM_TOTAL);
    cudaFuncSetAttribute(hmma_gemm<1>, cudaFuncAttributeMaxDynamicSharedMemorySize, SM_TOTAL);
    cudaFuncSetAttribute(hmma_gemm<2>, cudaFuncAttributeMaxDynamicSharedMemorySize, SM_TOTAL);

    // 0) weight splits + x transpose
    weight_split<<<(DD * DD + 255) / 256, 256>>>(to_q_w, wsq, DD * DD);
    weight_split<<<(DD * DD + 255) / 256, 256>>>(merge_w, wsm, DD * DD);
    weight_split<<<(4 * DD * DD + 255) / 256, 256>>>(mlp_w1, ws1, 4 * DD * DD);
    weight_split<<<(2 * DD * DD + 255) / 256, 256>>>(mlp_w2, ws2, 2 * DD * DD);
    transpose_split<<<dim3(NN / 32, DD / 32, BB), dim3(32, 8)>>>(x, xs, DD, NN);

    // 1) Linformer fold: kp = Wk @ (src @ proj) + bk * colsum(proj)
    colsum_kernel<<<1, KK>>>(proj_k, scol);
    cudaMemsetAsync(srcp, 0, sizeof(float) * (size_t)BB * DD * KK);
    proj_gemm<<<dim3((BB * DD) / 128, 8), 256>>>(source, proj_k, srcp);
    kp_init<<<(BB * DD * KK) / 256, 256>>>(to_k_b, scol, kp);
    kp_gemm<<<dim3(DD / 128, 4, BB), 256>>>(to_k_w, srcp, kp);

    // 2) q = Wq @ x + bq  (fp32 out)
    hmma_gemm<0><<<dim3(NN / 128, DD / 128, BB), 256, SM_TOTAL>>>(
        wsq, xs, xs, to_q_b, nullptr, nullptr, nullptr, nullptr,
        q, nullptr, DD, DD, NN, DD);

    // 3) fused attention -> msg (fp32)
    attn_kernel<<<dim3(NN / 128, HH, BB), dim3(128)>>>(q, kp, msg);

    // 4) transpose-split msg
    transpose_split<<<dim3(NN / 32, DD / 32, BB), dim3(32, 8)>>>(msg, msgs, DD, NN);

    // 5) msg2 = Wm @ msg + bm  (pack-transposed out)
    hmma_gemm<1><<<dim3(NN / 128, DD / 128, BB), 256, SM_TOTAL>>>(
        wsm, msgs, msgs, merge_b, nullptr, nullptr, nullptr, nullptr,
        nullptr, msg2s, DD, DD, NN, DD);

    // 6) h = relu(BN(W1 @ concat(x, msg2) + b1))  (pack-transposed out)
    hmma_gemm<2><<<dim3(NN / 128, (2 * DD) / 128, BB), 256, SM_TOTAL>>>(
        ws1, xs, msg2s, mlp_b1, bn_g, bn_b, bn_m, bn_v,
        nullptr, hs, 2 * DD, 2 * DD, NN, DD);

    // 7) out = W2 @ h + b2  (fp32 out)
    hmma_gemm<0><<<dim3(NN / 128, DD / 128, BB), 256, SM_TOTAL>>>(
        ws2, hs, hs, mlp_b2, nullptr, nullptr, nullptr, nullptr,
        out, nullptr, DD, 2 * DD, NN, 2 * DD);
}

// round 6
// speedup vs baseline: 3.6622x; 1.3969x over previous
#include <cuda_runtime.h>
#include <cuda_fp16.h>
#include <math.h>
#include <stdint.h>

// Problem constants
#define BB 4
#define DD 1024
#define NN 4096
#define HH 16
#define KK 128
#define DHH 64

typedef unsigned long long ull;
typedef unsigned int uint;
typedef unsigned short ushort;

// ---------------- scratch (device globals) ----------------
__device__ float g_q   [(size_t)BB * DD * NN];   // fp32 q
__device__ float g_msg [(size_t)BB * DD * NN];   // fp32 msg
__device__ float g_kp  [(size_t)BB * DD * KK];   // projected k/v
__device__ float g_srcp[(size_t)BB * DD * KK];   // src @ proj
__device__ float g_scol[KK];                     // colsum(proj)

// weights: packed fp16 (hi | lo<<16); activations: single fp16 plane
__device__ uint   g_ws_q[(size_t)DD * DD];
__device__ uint   g_ws_m[(size_t)DD * DD];
__device__ uint   g_ws_1[(size_t)(2 * DD) * (2 * DD)];
__device__ uint   g_ws_2[(size_t)DD * (2 * DD)];
__device__ ushort g_xs   [(size_t)BB * NN * DD];   // [B,N,D] fp16
__device__ ushort g_msgs [(size_t)BB * NN * DD];
__device__ ushort g_msg2s[(size_t)BB * NN * DD];
__device__ ushort g_hs   [(size_t)BB * NN * 2 * DD];

// ---------------- helpers ----------------
__device__ __forceinline__ uint32_t smem_to_u32(const void* p) {
    uint32_t a;
    asm("{ .reg .u64 t; cvta.to.shared.u64 t, %1; cvt.u32.u64 %0, t; }"
        : "=r"(a) : "l"(p));
    return a;
}
__device__ __forceinline__ uint prmt(uint a, uint b, uint s) {
    uint r; asm("prmt.b32 %0, %1, %2, %3;" : "=r"(r) : "r"(a), "r"(b), "r"(s));
    return r;
}
__device__ __forceinline__ void sts_v2(uint32_t addr, uint x, uint y) {
    asm volatile("st.shared.v2.b32 [%0], {%1, %2};" :: "r"(addr), "r"(x), "r"(y));
}
__device__ __forceinline__ void sts_v4(uint32_t addr, uint4 v) {
    asm volatile("st.shared.v4.b32 [%0], {%1, %2, %3, %4};"
                 :: "r"(addr), "r"(v.x), "r"(v.y), "r"(v.z), "r"(v.w));
}
__device__ __forceinline__ void ldsm4(uint* r, uint32_t addr) {
    asm volatile("ldmatrix.sync.aligned.m8n8.x4.shared.b16 {%0,%1,%2,%3}, [%4];"
        : "=r"(r[0]), "=r"(r[1]), "=r"(r[2]), "=r"(r[3]) : "r"(addr));
}

// HMMA m16n8k16 fp16 -> fp32
__device__ __forceinline__ void mma16816(float* c, const uint* a, uint b0, uint b1) {
    asm volatile(
        "mma.sync.aligned.m16n8k16.row.col.f32.f16.f16.f32 "
        "{%0,%1,%2,%3}, {%4,%5,%6,%7}, {%8,%9}, {%0,%1,%2,%3};"
        : "+f"(c[0]), "+f"(c[1]), "+f"(c[2]), "+f"(c[3])
        : "r"(a[0]), "r"(a[1]), "r"(a[2]), "r"(a[3]), "r"(b0), "r"(b1));
}

// ---- packed f32x2 helpers (attn) ----
__device__ __forceinline__ void ffma2(ull& d, ull a, ull b) {
    asm("fma.rn.f32x2 %0, %1, %2, %0;" : "+l"(d) : "l"(a), "l"(b));
}
__device__ __forceinline__ ull pack2(float x, float y) {
    ull r; asm("mov.b64 %0, {%1, %2};" : "=l"(r) : "f"(x), "f"(y)); return r;
}
__device__ __forceinline__ void unpack2(ull v, float& lo, float& hi) {
    asm("mov.b64 {%0, %1}, %2;" : "=f"(lo), "=f"(hi) : "l"(v));
}

// fp16 hi/lo exact split of a float: v = hi + lo (to ~2^-22)
__device__ __forceinline__ uint pack_split_h(float v) {
    __half h = __float2half_rn(v);
    float hv = __half2float(h);
    __half l = __float2half_rn(v - hv);
    return (uint)__half_as_ushort(h) | ((uint)__half_as_ushort(l) << 16);
}

// ---------------------------------------------------------------------------
__global__ void weight_split(const float* __restrict__ in, uint* __restrict__ out, int n) {
    int i = blockIdx.x * 256 + threadIdx.x;
    if (i < n) out[i] = pack_split_h(in[i]);
}

// fp32 [B, C, N] -> fp16 [B, N, C]
__global__ void transpose_half(const float* __restrict__ in, ushort* __restrict__ out,
                               int C, int Nw) {
    __shared__ float tile[32][33];
    const int b = blockIdx.z;
    const int n0 = blockIdx.x * 32, c0 = blockIdx.y * 32;
    const int tx = threadIdx.x, ty = threadIdx.y;
    const float* inb = in + ((size_t)b * C + c0) * Nw + n0;
#pragma unroll
    for (int i = 0; i < 32; i += 8)
        tile[ty + i][tx] = inb[(size_t)(ty + i) * Nw + tx];
    __syncthreads();
    ushort* ob = out + ((size_t)b * Nw + n0) * C + c0;
#pragma unroll
    for (int i = 0; i < 32; i += 8)
        ob[(size_t)(ty + i) * C + tx] = __half_as_ushort(__float2half_rn(tile[tx][ty + i]));
}

// colsum of proj: S[c] = sum_m proj[m, c]
__global__ void colsum_kernel(const float* __restrict__ proj, float* __restrict__ S) {
    const int c = threadIdx.x;
    float s = 0.f;
#pragma unroll 8
    for (int m = 0; m < NN; m++) s += proj[(size_t)m * KK + c];
    S[c] = s;
}

// kp init: kp[b,d,c] = bk[d] * S[c]
__global__ void kp_init(const float* __restrict__ bk, const float* __restrict__ S,
                        float* __restrict__ kp) {
    int i = blockIdx.x * 256 + threadIdx.x;
    int c = i & (KK - 1);
    int d = (i >> 7) & (DD - 1);
    kp[i] = bk[d] * S[c];
}

// ---------------------------------------------------------------------------
// Warp-level HMMA fp16x2 GEMM (A = weights, exact 2-plane split; B = activations,
// single fp16 plane).  out[b,m,n] = sum_k W[m,k] * In(b,k,n) + bias[m]
// CTA 128x128, KC=64, double-buffered smem, row stride 144B.
// MODE 0: fp32 out [B,M,Nw]; 1: +bias fp16-transpose out [B,Nw,M];
// MODE 2: +bias, BN, ReLU, fp16-transpose out.
// ---------------------------------------------------------------------------
#define PL_A_HI 0
#define PL_A_LO 18432
#define PL_B    36864
#define SM_BUF  55296
#define SM_TOTAL (2 * SM_BUF)
#define STG_S 136

template <int MODE>
__global__ void __launch_bounds__(256, 1) hmma_gemm(
    const uint* __restrict__ Asp,
    const ushort* __restrict__ B1,
    const ushort* __restrict__ B2,
    const float* __restrict__ bias,
    const float* __restrict__ gamma,
    const float* __restrict__ beta,
    const float* __restrict__ mean,
    const float* __restrict__ var,
    float* __restrict__ outF,
    ushort* __restrict__ outT,
    int M, int Kd, int Nw, int K1)
{
    extern __shared__ char smem[];
    const uint32_t sb = smem_to_u32(smem);

    const int tid  = threadIdx.x;
    const int wid  = tid >> 5;
    const int lane = tid & 31;
    const int m0 = blockIdx.y * 128;
    const int n0 = blockIdx.x * 128;
    const int bb = blockIdx.z;

    const int wm = wid & 3;
    const int wn = wid >> 2;
    const int K2 = Kd - K1;
    const int fr = lane >> 2;
    const int fc = (lane & 3) * 2;

    float c[2][8][4];
#pragma unroll
    for (int mt = 0; mt < 2; mt++)
#pragma unroll
        for (int nt = 0; nt < 8; nt++)
#pragma unroll
            for (int j = 0; j < 4; j++) c[mt][nt][j] = 0.f;

    const uint* Abase = Asp + (size_t)m0 * Kd;
    const int nc = Kd >> 6;   // 64-wide k chunks

    // A: 128 rows x 16 uint4 (64 packed k) -> 2048 uint4, 8/thread
    const int arow = tid >> 1;                 // base pattern: idx>>4
    const int aq4  = tid & 15;                 // only valid when combined below
    // B: 128 rows x 8 uint4 (64 halfs) -> 1024 uint4, 4/thread
    uint4 pa[8], pb[4];

    auto ldg_tile = [&](int ch) {
        const int k0 = ch * 64;
#pragma unroll
        for (int it = 0; it < 8; it++) {
            const int idx = it * 256 + tid;
            const int row = idx >> 4, q4 = idx & 15;
            pa[it] = *(const uint4*)(Abase + (size_t)row * Kd + k0 + q4 * 4);
        }
        const ushort* Bsrc; int kloc, kstride;
        if (k0 < K1) { Bsrc = B1; kloc = k0;      kstride = K1; }
        else         { Bsrc = B2; kloc = k0 - K1; kstride = K2; }
        const ushort* Bb = Bsrc + ((size_t)bb * Nw + n0) * kstride + kloc;
#pragma unroll
        for (int it = 0; it < 4; it++) {
            const int idx = it * 256 + tid;
            const int row = idx >> 3, q4 = idx & 7;
            pb[it] = *(const uint4*)(Bb + (size_t)row * kstride + q4 * 8);
        }
    };
    auto sts_tile = [&](int buf) {
        const uint32_t base = sb + buf * SM_BUF;
#pragma unroll
        for (int it = 0; it < 8; it++) {
            const int idx = it * 256 + tid;
            const int row = idx >> 4, q4 = idx & 15;
            const uint32_t off = (uint32_t)row * 144 + q4 * 8;
            uint4 v = pa[it];
            sts_v2(base + PL_A_HI + off, prmt(v.x, v.y, 0x5410), prmt(v.z, v.w, 0x5410));
            sts_v2(base + PL_A_LO + off, prmt(v.x, v.y, 0x7632), prmt(v.z, v.w, 0x7632));
        }
#pragma unroll
        for (int it = 0; it < 4; it++) {
            const int idx = it * 256 + tid;
            const int row = idx >> 3, q4 = idx & 7;
            sts_v4(base + PL_B + (uint32_t)row * 144 + q4 * 16, pb[it]);
        }
    };

    (void)arow; (void)aq4;

    ldg_tile(0);
    sts_tile(0);
    __syncthreads();

    const uint32_t aOff = (uint32_t)(wm * 32 + (lane & 15)) * 144 + ((lane >> 4) & 1) * 16;
    const uint32_t bOff = (uint32_t)(wn * 64 + (lane & 7) + ((lane & 16) ? 8 : 0)) * 144
                        + ((lane & 8) ? 16 : 0);

    for (int ch = 0; ch < nc; ch++) {
        const uint32_t base = sb + (ch & 1) * SM_BUF;
        if (ch + 1 < nc) ldg_tile(ch + 1);
#pragma unroll
        for (int ksb = 0; ksb < 128; ksb += 32) {   // 4 k-steps of 16 (32B each)
            uint ah[2][4], al[2][4];
            ldsm4(ah[0], base + PL_A_HI + aOff + ksb);
            ldsm4(ah[1], base + PL_A_HI + aOff + 2304 + ksb);
            ldsm4(al[0], base + PL_A_LO + aOff + ksb);
            ldsm4(al[1], base + PL_A_LO + aOff + 2304 + ksb);
            uint bh[4][4];
#pragma unroll
            for (int np = 0; np < 4; np++)
                ldsm4(bh[np], base + PL_B + bOff + np * 2304 + ksb);
#pragma unroll
            for (int np = 0; np < 4; np++)
#pragma unroll
                for (int sub = 0; sub < 2; sub++) {
                    const int nt = np * 2 + sub;
                    const uint b0 = bh[np][sub * 2], b1 = bh[np][sub * 2 + 1];
#pragma unroll
                    for (int mt = 0; mt < 2; mt++) {
                        mma16816(c[mt][nt], ah[mt], b0, b1);
                        mma16816(c[mt][nt], al[mt], b0, b1);
                    }
                }
        }
        if (ch + 1 < nc) {
            sts_tile((ch + 1) & 1);
            __syncthreads();
        }
    }

    // ---- epilogue ----
    if (MODE == 0) {
        const int cm = m0 + wm * 32 + fr;
        const int cn = n0 + wn * 64 + fc;
#pragma unroll
        for (int mt = 0; mt < 2; mt++) {
            const int mlo = cm + mt * 16;
            const int mhi = mlo + 8;
            const float bi0 = bias[mlo], bi1 = bias[mhi];
#pragma unroll
            for (int nt = 0; nt < 8; nt++) {
                const int n = cn + nt * 8;
                *(float2*)(outF + ((size_t)bb * M + mlo) * Nw + n) =
                    make_float2(c[mt][nt][0] + bi0, c[mt][nt][1] + bi0);
                *(float2*)(outF + ((size_t)bb * M + mhi) * Nw + n) =
                    make_float2(c[mt][nt][2] + bi1, c[mt][nt][3] + bi1);
            }
        }
    } else {
        float* stg = (float*)smem;   // 64 x 136 fp32 staging
        uint* ob = (uint*)(outT + (size_t)bb * Nw * M);
#pragma unroll
        for (int p = 0; p < 2; p++) {
            __syncthreads();
            if (wn == p) {
#pragma unroll
                for (int mt = 0; mt < 2; mt++) {
                    const int mloL = wm * 32 + mt * 16 + fr;
                    const int mhiL = mloL + 8;
                    const int mlo = m0 + mloL, mhi = m0 + mhiL;
                    float sc0 = 1.f, sh0 = bias[mlo], sc1 = 1.f, sh1 = bias[mhi];
                    if (MODE == 2) {
                        sc0 = gamma[mlo] * rsqrtf(var[mlo] + 1e-3f);
                        sh0 = beta[mlo] + (sh0 - mean[mlo]) * sc0;
                        sc1 = gamma[mhi] * rsqrtf(var[mhi] + 1e-3f);
                        sh1 = beta[mhi] + (sh1 - mean[mhi]) * sc1;
                    }
#pragma unroll
                    for (int nt = 0; nt < 8; nt++) {
                        const int nl = fc + nt * 8;
                        float v0 = c[mt][nt][0], v1 = c[mt][nt][1];
                        float v2 = c[mt][nt][2], v3 = c[mt][nt][3];
                        if (MODE == 2) {
                            v0 = fmaxf(fmaf(v0, sc0, sh0), 0.f);
                            v1 = fmaxf(fmaf(v1, sc0, sh0), 0.f);
                            v2 = fmaxf(fmaf(v2, sc1, sh1), 0.f);
                            v3 = fmaxf(fmaf(v3, sc1, sh1), 0.f);
                        } else {
                            v0 += sh0; v1 += sh0; v2 += sh1; v3 += sh1;
                        }
                        stg[(nl)     * STG_S + mloL] = v0;
                        stg[(nl + 1) * STG_S + mloL] = v1;
                        stg[(nl)     * STG_S + mhiL] = v2;
                        stg[(nl + 1) * STG_S + mhiL] = v3;
                    }
                }
            }
            __syncthreads();
            const int nb = n0 + p * 64;
            // 64 n-rows x 64 half2 -> 4096 uints, 16/thread
#pragma unroll 4
            for (int i = 0; i < 16; i++) {
                const int idx = i * 256 + tid;
                const int nn = idx >> 6;
                const int mp = idx & 63;
                const float* s = stg + nn * STG_S + mp * 2;
                const uint u = (uint)__half_as_ushort(__float2half_rn(s[0]))
                             | ((uint)__half_as_ushort(__float2half_rn(s[1])) << 16);
                ob[(size_t)(nb + nn) * (M >> 1) + (m0 >> 1) + mp] = u;
            }
        }
    }
}

// ---------------------------------------------------------------------------
// fp32 split-K GEMM: C[r,c] += A[r,m] * P[m,c]  (srcp = source @ proj)
// ---------------------------------------------------------------------------
__global__ void __launch_bounds__(256) proj_gemm(
    const float* __restrict__ A, const float* __restrict__ P, float* __restrict__ C)
{
    __shared__ float As[8][128];
    __shared__ float Bs[8][128];

    const int t  = threadIdx.x;
    const int ty = t >> 4;
    const int tx = t & 15;
    const int r0 = blockIdx.x * 128;
    const int chunk = NN / gridDim.y;
    const int c0 = blockIdx.y * chunk;

    const int ar = t >> 1, ac = (t & 1) * 4;
    const int br = t >> 5, bc = (t & 31) * 4;

    float acc[8][8];
#pragma unroll
    for (int i = 0; i < 8; i++)
#pragma unroll
        for (int j = 0; j < 8; j++) acc[i][j] = 0.f;

    for (int kt = 0; kt < chunk; kt += 8) {
        const int kb = c0 + kt;
        float4 av = *(const float4*)(A + (size_t)(r0 + ar) * NN + kb + ac);
        As[ac + 0][ar] = av.x;
        As[ac + 1][ar] = av.y;
        As[ac + 2][ar] = av.z;
        As[ac + 3][ar] = av.w;
        *(float4*)&Bs[br][bc] = *(const float4*)(P + (size_t)(kb + br) * KK + bc);
        __syncthreads();
#pragma unroll
        for (int kk = 0; kk < 8; kk++) {
            float a[8], bv[8];
#pragma unroll
            for (int i = 0; i < 8; i++) a[i] = As[kk][ty * 8 + i];
#pragma unroll
            for (int j = 0; j < 8; j++) bv[j] = Bs[kk][tx * 8 + j];
#pragma unroll
            for (int i = 0; i < 8; i++)
#pragma unroll
                for (int j = 0; j < 8; j++)
                    acc[i][j] = fmaf(a[i], bv[j], acc[i][j]);
        }
        __syncthreads();
    }

#pragma unroll
    for (int i = 0; i < 8; i++)
#pragma unroll
        for (int j = 0; j < 8; j++)
            atomicAdd(&C[(size_t)(r0 + ty * 8 + i) * KK + tx * 8 + j], acc[i][j]);
}

// ---------------------------------------------------------------------------
// kp = Wk @ srcp (per batch), accumulated onto kp_init values.
// ---------------------------------------------------------------------------
__global__ void __launch_bounds__(256) kp_gemm(
    const float* __restrict__ W, const float* __restrict__ P, float* __restrict__ C)
{
    __shared__ float As[8][128];
    __shared__ float Bs[8][128];

    const int t  = threadIdx.x;
    const int ty = t >> 4;
    const int tx = t & 15;
    const int r0 = blockIdx.x * 128;
    const int chunk = DD / gridDim.y;
    const int c0 = blockIdx.y * chunk;
    const int b = blockIdx.z;

    const float* Pb = P + (size_t)b * DD * KK;
    float* Cb = C + (size_t)b * DD * KK;

    const int ar = t >> 1, ac = (t & 1) * 4;
    const int br = t >> 5, bc = (t & 31) * 4;

    float acc[8][8];
#pragma unroll
    for (int i = 0; i < 8; i++)
#pragma unroll
        for (int j = 0; j < 8; j++) acc[i][j] = 0.f;

    for (int kt = 0; kt < chunk; kt += 8) {
        const int kb = c0 + kt;
        float4 av = *(const float4*)(W + (size_t)(r0 + ar) * DD + kb + ac);
        As[ac + 0][ar] = av.x;
        As[ac + 1][ar] = av.y;
        As[ac + 2][ar] = av.z;
        As[ac + 3][ar] = av.w;
        *(float4*)&Bs[br][bc] = *(const float4*)(Pb + (size_t)(kb + br) * KK + bc);
        __syncthreads();
#pragma unroll
        for (int kk = 0; kk < 8; kk++) {
            float a[8], bv[8];
#pragma unroll
            for (int i = 0; i < 8; i++) a[i] = As[kk][ty * 8 + i];
#pragma unroll
            for (int j = 0; j < 8; j++) bv[j] = Bs[kk][tx * 8 + j];
#pragma unroll
            for (int i = 0; i < 8; i++)
#pragma unroll
                for (int j = 0; j < 8; j++)
                    acc[i][j] = fmaf(a[i], bv[j], acc[i][j]);
        }
        __syncthreads();
    }

#pragma unroll
    for (int i = 0; i < 8; i++)
#pragma unroll
        for (int j = 0; j < 8; j++)
            atomicAdd(&Cb[(size_t)(r0 + ty * 8 + i) * KK + tx * 8 + j], acc[i][j]);
}

// ---------------------------------------------------------------------------
// Fused Linformer attention, two-pass, register accumulators.
// ---------------------------------------------------------------------------
#define KST_STRIDE 66

__global__ void __launch_bounds__(128, 2) attn_kernel(
    const float* __restrict__ q,
    const float* __restrict__ kp,
    float* __restrict__ msg)
{
    __shared__ float KsT[KK * KST_STRIDE];

    const int tid = threadIdx.x;
    const int n = blockIdx.x * 128 + tid;
    const int h = blockIdx.y;
    const int b = blockIdx.z;

#pragma unroll 4
    for (int dh = 0; dh < DHH; dh++)
        KsT[tid * KST_STRIDE + dh] = kp[((size_t)b * DD + (size_t)dh * HH + h) * KK + tid];
    __syncthreads();

    const float* qb = q + ((size_t)b * DD + h) * NN + n;
    ull qv2[DHH / 2];
#pragma unroll
    for (int dhp = 0; dhp < DHH / 2; dhp++) {
        float x = qb[(size_t)(2 * dhp) * HH * NN];
        float y = qb[(size_t)(2 * dhp + 1) * HH * NN];
        qv2[dhp] = pack2(x, y);
    }

    float mraw = -1e30f;
#pragma unroll 2
    for (int k = 0; k < KK; k++) {
        ull s2 = 0ULL;
        const float* krow = KsT + k * KST_STRIDE;
#pragma unroll
        for (int dhp = 0; dhp < DHH / 2; dhp++)
            ffma2(s2, qv2[dhp], *(const ull*)(krow + 2 * dhp));
        float lo, hi;
        unpack2(s2, lo, hi);
        mraw = fmaxf(mraw, lo + hi);
    }
    const float mx = mraw * 0.125f;

    float sum = 0.f;
    ull acc2[DHH / 2];
#pragma unroll
    for (int dhp = 0; dhp < DHH / 2; dhp++) acc2[dhp] = 0ULL;

#pragma unroll 2
    for (int k = 0; k < KK; k++) {
        ull s2 = 0ULL;
        const float* krow = KsT + k * KST_STRIDE;
#pragma unroll
        for (int dhp = 0; dhp < DHH / 2; dhp++)
            ffma2(s2, qv2[dhp], *(const ull*)(krow + 2 * dhp));
        float lo, hi;
        unpack2(s2, lo, hi);
        const float e = __expf(fmaf(lo + hi, 0.125f, -mx));
        sum += e;
        const ull e2 = pack2(e, e);
#pragma unroll
        for (int dhp = 0; dhp < DHH / 2; dhp++)
            ffma2(acc2[dhp], e2, *(const ull*)(krow + 2 * dhp));
    }
    const float inv = 1.f / sum;

    float* msgb = msg + ((size_t)b * DD + h) * NN + n;
#pragma unroll
    for (int dhp = 0; dhp < DHH / 2; dhp++) {
        float lo, hi;
        unpack2(acc2[dhp], lo, hi);
        msgb[(size_t)(2 * dhp) * HH * NN]     = lo * inv;
        msgb[(size_t)(2 * dhp + 1) * HH * NN] = hi * inv;
    }
}

// ---------------------------------------------------------------------------
extern "C" void kernel_launch(void* const* d_in, const int* in_sizes, int n_in,
                              void* d_out, int out_size)
{
    const float* x       = (const float*)d_in[0];
    const float* source  = (const float*)d_in[1];
    const float* to_q_w  = (const float*)d_in[2];
    const float* to_q_b  = (const float*)d_in[3];
    const float* to_k_w  = (const float*)d_in[4];
    const float* to_k_b  = (const float*)d_in[5];
    const float* proj_k  = (const float*)d_in[6];
    const float* merge_w = (const float*)d_in[7];
    const float* merge_b = (const float*)d_in[8];
    const float* mlp_w1  = (const float*)d_in[9];
    const float* mlp_b1  = (const float*)d_in[10];
    const float* bn_g    = (const float*)d_in[11];
    const float* bn_b    = (const float*)d_in[12];
    const float* bn_m    = (const float*)d_in[13];
    const float* bn_v    = (const float*)d_in[14];
    const float* mlp_w2  = (const float*)d_in[15];
    const float* mlp_b2  = (const float*)d_in[16];
    float* out = (float*)d_out;

    float *q, *msg, *kp, *srcp, *scol;
    uint *wsq, *wsm, *ws1, *ws2;
    ushort *xs, *msgs, *msg2s, *hs;
    cudaGetSymbolAddress((void**)&q,    g_q);
    cudaGetSymbolAddress((void**)&msg,  g_msg);
    cudaGetSymbolAddress((void**)&kp,   g_kp);
    cudaGetSymbolAddress((void**)&srcp, g_srcp);
    cudaGetSymbolAddress((void**)&scol, g_scol);
    cudaGetSymbolAddress((void**)&wsq,  g_ws_q);
    cudaGetSymbolAddress((void**)&wsm,  g_ws_m);
    cudaGetSymbolAddress((void**)&ws1,  g_ws_1);
    cudaGetSymbolAddress((void**)&ws2,  g_ws_2);
    cudaGetSymbolAddress((void**)&xs,   g_xs);
    cudaGetSymbolAddress((void**)&msgs, g_msgs);
    cudaGetSymbolAddress((void**)&msg2s,g_msg2s);
    cudaGetSymbolAddress((void**)&hs,   g_hs);

    cudaFuncSetAttribute(hmma_gemm<0>, cudaFuncAttributeMaxDynamicSharedMemorySize, SM_TOTAL);
    cudaFuncSetAttribute(hmma_gemm<1>, cudaFuncAttributeMaxDynamicSharedMemorySize, SM_TOTAL);
    cudaFuncSetAttribute(hmma_gemm<2>, cudaFuncAttributeMaxDynamicSharedMemorySize, SM_TOTAL);

    // 0) weight splits + x transpose
    weight_split<<<(DD * DD + 255) / 256, 256>>>(to_q_w, wsq, DD * DD);
    weight_split<<<(DD * DD + 255) / 256, 256>>>(merge_w, wsm, DD * DD);
    weight_split<<<(4 * DD * DD + 255) / 256, 256>>>(mlp_w1, ws1, 4 * DD * DD);
    weight_split<<<(2 * DD * DD + 255) / 256, 256>>>(mlp_w2, ws2, 2 * DD * DD);
    transpose_half<<<dim3(NN / 32, DD / 32, BB), dim3(32, 8)>>>(x, xs, DD, NN);

    // 1) Linformer fold: kp = Wk @ (src @ proj) + bk * colsum(proj)   (fp32)
    colsum_kernel<<<1, KK>>>(proj_k, scol);
    cudaMemsetAsync(srcp, 0, sizeof(float) * (size_t)BB * DD * KK);
    proj_gemm<<<dim3((BB * DD) / 128, 8), 256>>>(source, proj_k, srcp);
    kp_init<<<(BB * DD * KK) / 256, 256>>>(to_k_b, scol, kp);
    kp_gemm<<<dim3(DD / 128, 4, BB), 256>>>(to_k_w, srcp, kp);

    // 2) q = Wq @ x + bq  (fp32 out)
    hmma_gemm<0><<<dim3(NN / 128, DD / 128, BB), 256, SM_TOTAL>>>(
        wsq, xs, xs, to_q_b, nullptr, nullptr, nullptr, nullptr,
        q, nullptr, DD, DD, NN, DD);

    // 3) fused attention -> msg (fp32)
    attn_kernel<<<dim3(NN / 128, HH, BB), dim3(128)>>>(q, kp, msg);

    // 4) transpose msg -> fp16
    transpose_half<<<dim3(NN / 32, DD / 32, BB), dim3(32, 8)>>>(msg, msgs, DD, NN);

    // 5) msg2 = Wm @ msg + bm  (fp16-transposed out)
    hmma_gemm<1><<<dim3(NN / 128, DD / 128, BB), 256, SM_TOTAL>>>(
        wsm, msgs, msgs, merge_b, nullptr, nullptr, nullptr, nullptr,
        nullptr, msg2s, DD, DD, NN, DD);

    // 6) h = relu(BN(W1 @ concat(x, msg2) + b1))  (fp16-transposed out)
    hmma_gemm<2><<<dim3(NN / 128, (2 * DD) / 128, BB), 256, SM_TOTAL>>>(
        ws1, xs, msg2s, mlp_b1, bn_g, bn_b, bn_m, bn_v,
        nullptr, hs, 2 * DD, 2 * DD, NN, DD);

    // 7) out = W2 @ h + b2  (fp32 out)
    hmma_gemm<0><<<dim3(NN / 128, DD / 128, BB), 256, SM_TOTAL>>>(
        ws2, hs, hs, mlp_b2, nullptr, nullptr, nullptr, nullptr,
        out, nullptr, DD, 2 * DD, NN, 2 * DD);
}

// round 7
// speedup vs baseline: 3.9239x; 1.0714x over previous
#include <cuda_runtime.h>
#include <cuda_fp16.h>
#include <math.h>
#include <stdint.h>

// Problem constants
#define BB 4
#define DD 1024
#define NN 4096
#define HH 16
#define KK 128
#define DHH 64

typedef unsigned long long ull;
typedef unsigned int uint;
typedef unsigned short ushort;

// ---------------- scratch (device globals) ----------------
__device__ float g_q   [(size_t)BB * DD * NN];   // fp32 q
__device__ float g_msg [(size_t)BB * DD * NN];   // fp32 msg
__device__ float g_kp  [(size_t)BB * DD * KK];   // projected k/v
__device__ float g_srcp[(size_t)BB * DD * KK];   // src @ proj
__device__ float g_scol[KK];                     // colsum(proj)
__device__ float g_b1f [2 * DD];                 // folded mlp1 bias

// weights: packed fp16 (hi | lo<<16); activations: single fp16 plane
__device__ uint   g_ws_q [(size_t)DD * DD];
__device__ uint   g_ws_1f[(size_t)(2 * DD) * (2 * DD)];  // [W1a | W1b@Wm] fused
__device__ uint   g_ws_1b[(size_t)(2 * DD) * DD];        // W1b split (for precompute)
__device__ uint   g_ws_2 [(size_t)DD * (2 * DD)];
__device__ ushort g_wmT  [(size_t)DD * DD];              // Wm^T fp16
__device__ ushort g_xs   [(size_t)BB * NN * DD];         // [B,N,D] fp16
__device__ ushort g_msgs [(size_t)BB * NN * DD];
__device__ ushort g_hs   [(size_t)BB * NN * 2 * DD];

// ---------------- helpers ----------------
__device__ __forceinline__ uint32_t smem_to_u32(const void* p) {
    uint32_t a;
    asm("{ .reg .u64 t; cvta.to.shared.u64 t, %1; cvt.u32.u64 %0, t; }"
        : "=r"(a) : "l"(p));
    return a;
}
__device__ __forceinline__ uint prmt(uint a, uint b, uint s) {
    uint r; asm("prmt.b32 %0, %1, %2, %3;" : "=r"(r) : "r"(a), "r"(b), "r"(s));
    return r;
}
__device__ __forceinline__ void sts_v2(uint32_t addr, uint x, uint y) {
    asm volatile("st.shared.v2.b32 [%0], {%1, %2};" :: "r"(addr), "r"(x), "r"(y));
}
__device__ __forceinline__ void sts_v4(uint32_t addr, uint4 v) {
    asm volatile("st.shared.v4.b32 [%0], {%1, %2, %3, %4};"
                 :: "r"(addr), "r"(v.x), "r"(v.y), "r"(v.z), "r"(v.w));
}
__device__ __forceinline__ void ldsm4(uint* r, uint32_t addr) {
    asm volatile("ldmatrix.sync.aligned.m8n8.x4.shared.b16 {%0,%1,%2,%3}, [%4];"
        : "=r"(r[0]), "=r"(r[1]), "=r"(r[2]), "=r"(r[3]) : "r"(addr));
}

// HMMA m16n8k16 fp16 -> fp32
__device__ __forceinline__ void mma16816(float* c, const uint* a, uint b0, uint b1) {
    asm volatile(
        "mma.sync.aligned.m16n8k16.row.col.f32.f16.f16.f32 "
        "{%0,%1,%2,%3}, {%4,%5,%6,%7}, {%8,%9}, {%0,%1,%2,%3};"
        : "+f"(c[0]), "+f"(c[1]), "+f"(c[2]), "+f"(c[3])
        : "r"(a[0]), "r"(a[1]), "r"(a[2]), "r"(a[3]), "r"(b0), "r"(b1));
}

// ---- packed f32x2 helpers (attn) ----
__device__ __forceinline__ void ffma2(ull& d, ull a, ull b) {
    asm("fma.rn.f32x2 %0, %1, %2, %0;" : "+l"(d) : "l"(a), "l"(b));
}
__device__ __forceinline__ ull pack2(float x, float y) {
    ull r; asm("mov.b64 %0, {%1, %2};" : "=l"(r) : "f"(x), "f"(y)); return r;
}
__device__ __forceinline__ void unpack2(ull v, float& lo, float& hi) {
    asm("mov.b64 {%0, %1}, %2;" : "=f"(lo), "=f"(hi) : "l"(v));
}

// fp16 hi/lo exact split of a float
__device__ __forceinline__ uint pack_split_h(float v) {
    __half h = __float2half_rn(v);
    float hv = __half2float(h);
    __half l = __float2half_rn(v - hv);
    return (uint)__half_as_ushort(h) | ((uint)__half_as_ushort(l) << 16);
}

// ---------------------------------------------------------------------------
__global__ void weight_split(const float* __restrict__ in, uint* __restrict__ out, int n) {
    int i = blockIdx.x * 256 + threadIdx.x;
    if (i < n) out[i] = pack_split_h(in[i]);
}

// strided split: out[m*ostr + k] = split(in[m*istr + koff + k]), k < cols
__global__ void weight_split_off(const float* __restrict__ in, uint* __restrict__ out,
                                 int cols, int istr, int koff, int ostr) {
    int i = blockIdx.x * 256 + threadIdx.x;
    int m = i / cols, k = i - m * cols;
    out[(size_t)m * ostr + k] = pack_split_h(in[(size_t)m * istr + koff + k]);
}

// fp32 [B, C, N] -> fp16 [B, N, C]
__global__ void transpose_half(const float* __restrict__ in, ushort* __restrict__ out,
                               int C, int Nw) {
    __shared__ float tile[32][33];
    const int b = blockIdx.z;
    const int n0 = blockIdx.x * 32, c0 = blockIdx.y * 32;
    const int tx = threadIdx.x, ty = threadIdx.y;
    const float* inb = in + ((size_t)b * C + c0) * Nw + n0;
#pragma unroll
    for (int i = 0; i < 32; i += 8)
        tile[ty + i][tx] = inb[(size_t)(ty + i) * Nw + tx];
    __syncthreads();
    ushort* ob = out + ((size_t)b * Nw + n0) * C + c0;
#pragma unroll
    for (int i = 0; i < 32; i += 8)
        ob[(size_t)(ty + i) * C + tx] = __half_as_ushort(__float2half_rn(tile[tx][ty + i]));
}

// colsum of proj: S[c] = sum_m proj[m, c]
__global__ void colsum_kernel(const float* __restrict__ proj, float* __restrict__ S) {
    const int c = threadIdx.x;
    float s = 0.f;
#pragma unroll 8
    for (int m = 0; m < NN; m++) s += proj[(size_t)m * KK + c];
    S[c] = s;
}

// kp init: kp[b,d,c] = bk[d] * S[c]
__global__ void kp_init(const float* __restrict__ bk, const float* __restrict__ S,
                        float* __restrict__ kp) {
    int i = blockIdx.x * 256 + threadIdx.x;
    int c = i & (KK - 1);
    int d = (i >> 7) & (DD - 1);
    kp[i] = bk[d] * S[c];
}

// b1f[m] = b1[m] + dot(W1[m, 1024:2048], bm)   (one warp per m)
__global__ void bias_fold(const float* __restrict__ w1, const float* __restrict__ bm,
                          const float* __restrict__ b1, float* __restrict__ out) {
    const int m = blockIdx.x * 8 + (threadIdx.x >> 5);
    const int lane = threadIdx.x & 31;
    float s = 0.f;
#pragma unroll 4
    for (int c = lane; c < DD; c += 32)
        s += w1[(size_t)m * (2 * DD) + DD + c] * bm[c];
#pragma unroll
    for (int o = 16; o; o >>= 1) s += __shfl_xor_sync(0xFFFFFFFFu, s, o);
    if (lane == 0) out[m] = b1[m] + s;
}

// ---------------------------------------------------------------------------
// Warp-level HMMA fp16x2 GEMM (A weights 2-plane exact split, B fp16 plane).
//   out[b,m,n] = sum_k W[m,k] * In(b,k,n) (+ bias[m])
// MODE 0: fp32 out, row stride ostr; MODE 2: +bias/BN/ReLU fp16-transpose out;
// MODE 3: packed-split uint out, row stride ostr (weight precompute; no bias).
// CTA 128x128, KC=64, double-buffered smem (row stride 144B).
// ---------------------------------------------------------------------------
#define PL_A_HI 0
#define PL_A_LO 18432
#define PL_B    36864
#define SM_BUF  55296
#define SM_TOTAL (2 * SM_BUF)
#define STG_S 136

template <int MODE>
__global__ void __launch_bounds__(256, 1) hmma_gemm(
    const uint* __restrict__ Asp,
    const ushort* __restrict__ B1,
    const ushort* __restrict__ B2,
    const float* __restrict__ bias,
    const float* __restrict__ gamma,
    const float* __restrict__ beta,
    const float* __restrict__ mean,
    const float* __restrict__ var,
    float* __restrict__ outF,
    ushort* __restrict__ outT,
    int M, int Kd, int Nw, int K1, int ostr)
{
    extern __shared__ char smem[];
    const uint32_t sb = smem_to_u32(smem);

    const int tid  = threadIdx.x;
    const int wid  = tid >> 5;
    const int lane = tid & 31;
    const int m0 = blockIdx.y * 128;
    const int n0 = blockIdx.x * 128;
    const int bb = blockIdx.z;

    const int wm = wid & 3;
    const int wn = wid >> 2;
    const int K2 = Kd - K1;
    const int fr = lane >> 2;
    const int fc = (lane & 3) * 2;

    float c[2][8][4];
#pragma unroll
    for (int mt = 0; mt < 2; mt++)
#pragma unroll
        for (int nt = 0; nt < 8; nt++)
#pragma unroll
            for (int j = 0; j < 4; j++) c[mt][nt][j] = 0.f;

    const uint* Abase = Asp + (size_t)m0 * Kd;
    const int nc = Kd >> 6;   // 64-wide k chunks

    uint4 pa[8], pb[4];

    auto ldg_tile = [&](int ch) {
        const int k0 = ch * 64;
#pragma unroll
        for (int it = 0; it < 8; it++) {
            const int idx = it * 256 + tid;
            const int row = idx >> 4, q4 = idx & 15;
            pa[it] = *(const uint4*)(Abase + (size_t)row * Kd + k0 + q4 * 4);
        }
        const ushort* Bsrc; int kloc, kstride;
        if (k0 < K1) { Bsrc = B1; kloc = k0;      kstride = K1; }
        else         { Bsrc = B2; kloc = k0 - K1; kstride = K2; }
        const ushort* Bb = Bsrc + ((size_t)bb * Nw + n0) * kstride + kloc;
#pragma unroll
        for (int it = 0; it < 4; it++) {
            const int idx = it * 256 + tid;
            const int row = idx >> 3, q4 = idx & 7;
            pb[it] = *(const uint4*)(Bb + (size_t)row * kstride + q4 * 8);
        }
    };
    auto sts_tile = [&](int buf) {
        const uint32_t base = sb + buf * SM_BUF;
#pragma unroll
        for (int it = 0; it < 8; it++) {
            const int idx = it * 256 + tid;
            const int row = idx >> 4, q4 = idx & 15;
            const uint32_t off = (uint32_t)row * 144 + q4 * 8;
            uint4 v = pa[it];
            sts_v2(base + PL_A_HI + off, prmt(v.x, v.y, 0x5410), prmt(v.z, v.w, 0x5410));
            sts_v2(base + PL_A_LO + off, prmt(v.x, v.y, 0x7632), prmt(v.z, v.w, 0x7632));
        }
#pragma unroll
        for (int it = 0; it < 4; it++) {
            const int idx = it * 256 + tid;
            const int row = idx >> 3, q4 = idx & 7;
            sts_v4(base + PL_B + (uint32_t)row * 144 + q4 * 16, pb[it]);
        }
    };

    ldg_tile(0);
    sts_tile(0);
    __syncthreads();

    const uint32_t aOff = (uint32_t)(wm * 32 + (lane & 15)) * 144 + ((lane >> 4) & 1) * 16;
    const uint32_t bOff = (uint32_t)(wn * 64 + (lane & 7) + ((lane & 16) ? 8 : 0)) * 144
                        + ((lane & 8) ? 16 : 0);

    for (int ch = 0; ch < nc; ch++) {
        const uint32_t base = sb + (ch & 1) * SM_BUF;
        if (ch + 1 < nc) ldg_tile(ch + 1);
#pragma unroll
        for (int ksb = 0; ksb < 128; ksb += 32) {
            uint ah[2][4], al[2][4];
            ldsm4(ah[0], base + PL_A_HI + aOff + ksb);
            ldsm4(ah[1], base + PL_A_HI + aOff + 2304 + ksb);
            ldsm4(al[0], base + PL_A_LO + aOff + ksb);
            ldsm4(al[1], base + PL_A_LO + aOff + 2304 + ksb);
            uint bh[4][4];
#pragma unroll
            for (int np = 0; np < 4; np++)
                ldsm4(bh[np], base + PL_B + bOff + np * 2304 + ksb);
#pragma unroll
            for (int np = 0; np < 4; np++)
#pragma unroll
                for (int sub = 0; sub < 2; sub++) {
                    const int nt = np * 2 + sub;
                    const uint b0 = bh[np][sub * 2], b1 = bh[np][sub * 2 + 1];
#pragma unroll
                    for (int mt = 0; mt < 2; mt++) {
                        mma16816(c[mt][nt], ah[mt], b0, b1);
                        mma16816(c[mt][nt], al[mt], b0, b1);
                    }
                }
        }
        if (ch + 1 < nc) {
            sts_tile((ch + 1) & 1);
            __syncthreads();
        }
    }

    // ---- epilogue ----
    if (MODE == 0) {
        const int cm = m0 + wm * 32 + fr;
        const int cn = n0 + wn * 64 + fc;
#pragma unroll
        for (int mt = 0; mt < 2; mt++) {
            const int mlo = cm + mt * 16;
            const int mhi = mlo + 8;
            const float bi0 = bias[mlo], bi1 = bias[mhi];
#pragma unroll
            for (int nt = 0; nt < 8; nt++) {
                const int n = cn + nt * 8;
                *(float2*)(outF + ((size_t)bb * M + mlo) * ostr + n) =
                    make_float2(c[mt][nt][0] + bi0, c[mt][nt][1] + bi0);
                *(float2*)(outF + ((size_t)bb * M + mhi) * ostr + n) =
                    make_float2(c[mt][nt][2] + bi1, c[mt][nt][3] + bi1);
            }
        }
    } else if (MODE == 3) {
        uint* ob = (uint*)outF;
        const int cm = m0 + wm * 32 + fr;
        const int cn = n0 + wn * 64 + fc;
#pragma unroll
        for (int mt = 0; mt < 2; mt++) {
            const int mlo = cm + mt * 16;
            const int mhi = mlo + 8;
#pragma unroll
            for (int nt = 0; nt < 8; nt++) {
                const int n = cn + nt * 8;
                ob[(size_t)mlo * ostr + n]     = pack_split_h(c[mt][nt][0]);
                ob[(size_t)mlo * ostr + n + 1] = pack_split_h(c[mt][nt][1]);
                ob[(size_t)mhi * ostr + n]     = pack_split_h(c[mt][nt][2]);
                ob[(size_t)mhi * ostr + n + 1] = pack_split_h(c[mt][nt][3]);
            }
        }
    } else {  // MODE 2: BN+ReLU, fp16 transpose out
        float* stg = (float*)smem;
        uint* ob = (uint*)(outT + (size_t)bb * Nw * M);
#pragma unroll
        for (int p = 0; p < 2; p++) {
            __syncthreads();
            if (wn == p) {
#pragma unroll
                for (int mt = 0; mt < 2; mt++) {
                    const int mloL = wm * 32 + mt * 16 + fr;
                    const int mhiL = mloL + 8;
                    const int mlo = m0 + mloL, mhi = m0 + mhiL;
                    float sc0 = gamma[mlo] * rsqrtf(var[mlo] + 1e-3f);
                    float sh0 = beta[mlo] + (bias[mlo] - mean[mlo]) * sc0;
                    float sc1 = gamma[mhi] * rsqrtf(var[mhi] + 1e-3f);
                    float sh1 = beta[mhi] + (bias[mhi] - mean[mhi]) * sc1;
#pragma unroll
                    for (int nt = 0; nt < 8; nt++) {
                        const int nl = fc + nt * 8;
                        float v0 = fmaxf(fmaf(c[mt][nt][0], sc0, sh0), 0.f);
                        float v1 = fmaxf(fmaf(c[mt][nt][1], sc0, sh0), 0.f);
                        float v2 = fmaxf(fmaf(c[mt][nt][2], sc1, sh1), 0.f);
                        float v3 = fmaxf(fmaf(c[mt][nt][3], sc1, sh1), 0.f);
                        stg[(nl)     * STG_S + mloL] = v0;
                        stg[(nl + 1) * STG_S + mloL] = v1;
                        stg[(nl)     * STG_S + mhiL] = v2;
                        stg[(nl + 1) * STG_S + mhiL] = v3;
                    }
                }
            }
            __syncthreads();
            const int nb = n0 + p * 64;
#pragma unroll 4
            for (int i = 0; i < 16; i++) {
                const int idx = i * 256 + tid;
                const int nn = idx >> 6;
                const int mp = idx & 63;
                const float* s = stg + nn * STG_S + mp * 2;
                const uint u = (uint)__half_as_ushort(__float2half_rn(s[0]))
                             | ((uint)__half_as_ushort(__float2half_rn(s[1])) << 16);
                ob[(size_t)(nb + nn) * (M >> 1) + (m0 >> 1) + mp] = u;
            }
        }
    }
}

// ---------------------------------------------------------------------------
// fp32 split-K GEMM: C[r,c] += A[r,m] * P[m,c]  (srcp = source @ proj)
// ---------------------------------------------------------------------------
__global__ void __launch_bounds__(256) proj_gemm(
    const float* __restrict__ A, const float* __restrict__ P, float* __restrict__ C)
{
    __shared__ float As[8][128];
    __shared__ float Bs[8][128];

    const int t  = threadIdx.x;
    const int ty = t >> 4;
    const int tx = t & 15;
    const int r0 = blockIdx.x * 128;
    const int chunk = NN / gridDim.y;
    const int c0 = blockIdx.y * chunk;

    const int ar = t >> 1, ac = (t & 1) * 4;
    const int br = t >> 5, bc = (t & 31) * 4;

    float acc[8][8];
#pragma unroll
    for (int i = 0; i < 8; i++)
#pragma unroll
        for (int j = 0; j < 8; j++) acc[i][j] = 0.f;

    for (int kt = 0; kt < chunk; kt += 8) {
        const int kb = c0 + kt;
        float4 av = *(const float4*)(A + (size_t)(r0 + ar) * NN + kb + ac);
        As[ac + 0][ar] = av.x;
        As[ac + 1][ar] = av.y;
        As[ac + 2][ar] = av.z;
        As[ac + 3][ar] = av.w;
        *(float4*)&Bs[br][bc] = *(const float4*)(P + (size_t)(kb + br) * KK + bc);
        __syncthreads();
#pragma unroll
        for (int kk = 0; kk < 8; kk++) {
            float a[8], bv[8];
#pragma unroll
            for (int i = 0; i < 8; i++) a[i] = As[kk][ty * 8 + i];
#pragma unroll
            for (int j = 0; j < 8; j++) bv[j] = Bs[kk][tx * 8 + j];
#pragma unroll
            for (int i = 0; i < 8; i++)
#pragma unroll
                for (int j = 0; j < 8; j++)
                    acc[i][j] = fmaf(a[i], bv[j], acc[i][j]);
        }
        __syncthreads();
    }

#pragma unroll
    for (int i = 0; i < 8; i++)
#pragma unroll
        for (int j = 0; j < 8; j++)
            atomicAdd(&C[(size_t)(r0 + ty * 8 + i) * KK + tx * 8 + j], acc[i][j]);
}

// ---------------------------------------------------------------------------
// kp = Wk @ srcp (per batch), accumulated onto kp_init values.
// ---------------------------------------------------------------------------
__global__ void __launch_bounds__(256) kp_gemm(
    const float* __restrict__ W, const float* __restrict__ P, float* __restrict__ C)
{
    __shared__ float As[8][128];
    __shared__ float Bs[8][128];

    const int t  = threadIdx.x;
    const int ty = t >> 4;
    const int tx = t & 15;
    const int r0 = blockIdx.x * 128;
    const int chunk = DD / gridDim.y;
    const int c0 = blockIdx.y * chunk;
    const int b = blockIdx.z;

    const float* Pb = P + (size_t)b * DD * KK;
    float* Cb = C + (size_t)b * DD * KK;

    const int ar = t >> 1, ac = (t & 1) * 4;
    const int br = t >> 5, bc = (t & 31) * 4;

    float acc[8][8];
#pragma unroll
    for (int i = 0; i < 8; i++)
#pragma unroll
        for (int j = 0; j < 8; j++) acc[i][j] = 0.f;

    for (int kt = 0; kt < chunk; kt += 8) {
        const int kb = c0 + kt;
        float4 av = *(const float4*)(W + (size_t)(r0 + ar) * DD + kb + ac);
        As[ac + 0][ar] = av.x;
        As[ac + 1][ar] = av.y;
        As[ac + 2][ar] = av.z;
        As[ac + 3][ar] = av.w;
        *(float4*)&Bs[br][bc] = *(const float4*)(Pb + (size_t)(kb + br) * KK + bc);
        __syncthreads();
#pragma unroll
        for (int kk = 0; kk < 8; kk++) {
            float a[8], bv[8];
#pragma unroll
            for (int i = 0; i < 8; i++) a[i] = As[kk][ty * 8 + i];
#pragma unroll
            for (int j = 0; j < 8; j++) bv[j] = Bs[kk][tx * 8 + j];
#pragma unroll
            for (int i = 0; i < 8; i++)
#pragma unroll
                for (int j = 0; j < 8; j++)
                    acc[i][j] = fmaf(a[i], bv[j], acc[i][j]);
        }
        __syncthreads();
    }

#pragma unroll
    for (int i = 0; i < 8; i++)
#pragma unroll
        for (int j = 0; j < 8; j++)
            atomicAdd(&Cb[(size_t)(r0 + ty * 8 + i) * KK + tx * 8 + j], acc[i][j]);
}

// ---------------------------------------------------------------------------
// Fused Linformer attention, two-pass, register accumulators.
// ---------------------------------------------------------------------------
#define KST_STRIDE 66

__global__ void __launch_bounds__(128, 2) attn_kernel(
    const float* __restrict__ q,
    const float* __restrict__ kp,
    float* __restrict__ msg)
{
    __shared__ float KsT[KK * KST_STRIDE];

    const int tid = threadIdx.x;
    const int n = blockIdx.x * 128 + tid;
    const int h = blockIdx.y;
    const int b = blockIdx.z;

#pragma unroll 4
    for (int dh = 0; dh < DHH; dh++)
        KsT[tid * KST_STRIDE + dh] = kp[((size_t)b * DD + (size_t)dh * HH + h) * KK + tid];
    __syncthreads();

    const float* qb = q + ((size_t)b * DD + h) * NN + n;
    ull qv2[DHH / 2];
#pragma unroll
    for (int dhp = 0; dhp < DHH / 2; dhp++) {
        float x = qb[(size_t)(2 * dhp) * HH * NN];
        float y = qb[(size_t)(2 * dhp + 1) * HH * NN];
        qv2[dhp] = pack2(x, y);
    }

    float mraw = -1e30f;
#pragma unroll 2
    for (int k = 0; k < KK; k++) {
        ull s2 = 0ULL;
        const float* krow = KsT + k * KST_STRIDE;
#pragma unroll
        for (int dhp = 0; dhp < DHH / 2; dhp++)
            ffma2(s2, qv2[dhp], *(const ull*)(krow + 2 * dhp));
        float lo, hi;
        unpack2(s2, lo, hi);
        mraw = fmaxf(mraw, lo + hi);
    }
    const float mx = mraw * 0.125f;

    float sum = 0.f;
    ull acc2[DHH / 2];
#pragma unroll
    for (int dhp = 0; dhp < DHH / 2; dhp++) acc2[dhp] = 0ULL;

#pragma unroll 2
    for (int k = 0; k < KK; k++) {
        ull s2 = 0ULL;
        const float* krow = KsT + k * KST_STRIDE;
#pragma unroll
        for (int dhp = 0; dhp < DHH / 2; dhp++)
            ffma2(s2, qv2[dhp], *(const ull*)(krow + 2 * dhp));
        float lo, hi;
        unpack2(s2, lo, hi);
        const float e = __expf(fmaf(lo + hi, 0.125f, -mx));
        sum += e;
        const ull e2 = pack2(e, e);
#pragma unroll
        for (int dhp = 0; dhp < DHH / 2; dhp++)
            ffma2(acc2[dhp], e2, *(const ull*)(krow + 2 * dhp));
    }
    const float inv = 1.f / sum;

    float* msgb = msg + ((size_t)b * DD + h) * NN + n;
#pragma unroll
    for (int dhp = 0; dhp < DHH / 2; dhp++) {
        float lo, hi;
        unpack2(acc2[dhp], lo, hi);
        msgb[(size_t)(2 * dhp) * HH * NN]     = lo * inv;
        msgb[(size_t)(2 * dhp + 1) * HH * NN] = hi * inv;
    }
}

// ---------------------------------------------------------------------------
extern "C" void kernel_launch(void* const* d_in, const int* in_sizes, int n_in,
                              void* d_out, int out_size)
{
    const float* x       = (const float*)d_in[0];
    const float* source  = (const float*)d_in[1];
    const float* to_q_w  = (const float*)d_in[2];
    const float* to_q_b  = (const float*)d_in[3];
    const float* to_k_w  = (const float*)d_in[4];
    const float* to_k_b  = (const float*)d_in[5];
    const float* proj_k  = (const float*)d_in[6];
    const float* merge_w = (const float*)d_in[7];
    const float* merge_b = (const float*)d_in[8];
    const float* mlp_w1  = (const float*)d_in[9];
    const float* mlp_b1  = (const float*)d_in[10];
    const float* bn_g    = (const float*)d_in[11];
    const float* bn_b    = (const float*)d_in[12];
    const float* bn_m    = (const float*)d_in[13];
    const float* bn_v    = (const float*)d_in[14];
    const float* mlp_w2  = (const float*)d_in[15];
    const float* mlp_b2  = (const float*)d_in[16];
    float* out = (float*)d_out;

    float *q, *msg, *kp, *srcp, *scol, *b1f;
    uint *wsq, *ws1f, *ws1b, *ws2;
    ushort *wmT, *xs, *msgs, *hs;
    cudaGetSymbolAddress((void**)&q,    g_q);
    cudaGetSymbolAddress((void**)&msg,  g_msg);
    cudaGetSymbolAddress((void**)&kp,   g_kp);
    cudaGetSymbolAddress((void**)&srcp, g_srcp);
    cudaGetSymbolAddress((void**)&scol, g_scol);
    cudaGetSymbolAddress((void**)&b1f,  g_b1f);
    cudaGetSymbolAddress((void**)&wsq,  g_ws_q);
    cudaGetSymbolAddress((void**)&ws1f, g_ws_1f);
    cudaGetSymbolAddress((void**)&ws1b, g_ws_1b);
    cudaGetSymbolAddress((void**)&ws2,  g_ws_2);
    cudaGetSymbolAddress((void**)&wmT,  g_wmT);
    cudaGetSymbolAddress((void**)&xs,   g_xs);
    cudaGetSymbolAddress((void**)&msgs, g_msgs);
    cudaGetSymbolAddress((void**)&hs,   g_hs);

    cudaFuncSetAttribute(hmma_gemm<0>, cudaFuncAttributeMaxDynamicSharedMemorySize, SM_TOTAL);
    cudaFuncSetAttribute(hmma_gemm<2>, cudaFuncAttributeMaxDynamicSharedMemorySize, SM_TOTAL);
    cudaFuncSetAttribute(hmma_gemm<3>, cudaFuncAttributeMaxDynamicSharedMemorySize, SM_TOTAL);

    // 0) weight prep
    weight_split<<<(DD * DD + 255) / 256, 256>>>(to_q_w, wsq, DD * DD);
    weight_split<<<(2 * DD * DD + 255) / 256, 256>>>(mlp_w2, ws2, 2 * DD * DD);
    // W1a half of fused weight: ws1f[m][0:1024]
    weight_split_off<<<(2 * DD * DD) / 256, 256>>>(mlp_w1, ws1f, DD, 2 * DD, 0, 2 * DD);
    // W1b split for precompute: ws1b[m][0:1024]
    weight_split_off<<<(2 * DD * DD) / 256, 256>>>(mlp_w1, ws1b, DD, 2 * DD, DD, DD);
    // Wm^T fp16 (Wm viewed as [C=out, N=in] -> wmT[in][out])
    transpose_half<<<dim3(DD / 32, DD / 32, 1), dim3(32, 8)>>>(merge_w, wmT, DD, DD);
    // W1c = W1b @ Wm  -> ws1f[m][1024:2048]   (MODE3, packed-split out)
    hmma_gemm<3><<<dim3(DD / 128, (2 * DD) / 128, 1), 256, SM_TOTAL>>>(
        ws1b, wmT, wmT, nullptr, nullptr, nullptr, nullptr, nullptr,
        (float*)(ws1f + DD), nullptr, 2 * DD, DD, DD, DD, 2 * DD);
    // b1' = b1 + W1b @ bm
    bias_fold<<<(2 * DD) / 8, 256>>>(mlp_w1, merge_b, mlp_b1, b1f);

    // x transpose
    transpose_half<<<dim3(NN / 32, DD / 32, BB), dim3(32, 8)>>>(x, xs, DD, NN);

    // 1) Linformer fold: kp = Wk @ (src @ proj) + bk * colsum(proj)   (fp32)
    colsum_kernel<<<1, KK>>>(proj_k, scol);
    cudaMemsetAsync(srcp, 0, sizeof(float) * (size_t)BB * DD * KK);
    proj_gemm<<<dim3((BB * DD) / 128, 8), 256>>>(source, proj_k, srcp);
    kp_init<<<(BB * DD * KK) / 256, 256>>>(to_k_b, scol, kp);
    kp_gemm<<<dim3(DD / 128, 4, BB), 256>>>(to_k_w, srcp, kp);

    // 2) q = Wq @ x + bq  (fp32 out)
    hmma_gemm<0><<<dim3(NN / 128, DD / 128, BB), 256, SM_TOTAL>>>(
        wsq, xs, xs, to_q_b, nullptr, nullptr, nullptr, nullptr,
        q, nullptr, DD, DD, NN, DD, NN);

    // 3) fused attention -> msg (fp32)
    attn_kernel<<<dim3(NN / 128, HH, BB), dim3(128)>>>(q, kp, msg);

    // 4) transpose msg -> fp16
    transpose_half<<<dim3(NN / 32, DD / 32, BB), dim3(32, 8)>>>(msg, msgs, DD, NN);

    // 5) h = relu(BN([W1a | W1c] @ concat(x, msg) + b1'))  (fp16-transposed out)
    hmma_gemm<2><<<dim3(NN / 128, (2 * DD) / 128, BB), 256, SM_TOTAL>>>(
        ws1f, xs, msgs, b1f, bn_g, bn_b, bn_m, bn_v,
        nullptr, hs, 2 * DD, 2 * DD, NN, DD, 0);

    // 6) out = W2 @ h + b2  (fp32 out)
    hmma_gemm<0><<<dim3(NN / 128, DD / 128, BB), 256, SM_TOTAL>>>(
        ws2, hs, hs, mlp_b2, nullptr, nullptr, nullptr, nullptr,
        out, nullptr, DD, 2 * DD, NN, 2 * DD, NN);
}

// round 8
// speedup vs baseline: 5.5177x; 1.4062x over previous
#include <cuda_runtime.h>
#include <cuda_fp16.h>
#include <math.h>
#include <stdint.h>

// Problem constants
#define BB 4
#define DD 1024
#define NN 4096
#define HH 16
#define KK 128
#define DHH 64

typedef unsigned long long ull;
typedef unsigned int uint;
typedef unsigned short ushort;

// ---------------- scratch (device globals) ----------------
__device__ float g_q   [(size_t)BB * DD * NN];
__device__ float g_msg [(size_t)BB * DD * NN];
__device__ float g_kp  [(size_t)BB * DD * KK];
__device__ float g_srcp[(size_t)BB * DD * KK];
__device__ float g_scol[KK];
__device__ float g_b1f [2 * DD];

// single-plane fp16 weights
__device__ ushort g_wq_h  [(size_t)DD * DD];
__device__ ushort g_ws1f_h[(size_t)(2 * DD) * (2 * DD)];  // [W1a | W1b@Wm] fp16
// 2-plane packed weights
__device__ uint   g_ws_1b [(size_t)(2 * DD) * DD];        // W1b (for precompute)
__device__ uint   g_ws_2  [(size_t)DD * (2 * DD)];        // mlp2
__device__ ushort g_wmT   [(size_t)DD * DD];              // Wm^T fp16
// fp16 activations
__device__ ushort g_xs   [(size_t)BB * NN * DD];
__device__ ushort g_msgs [(size_t)BB * NN * DD];
__device__ ushort g_hs   [(size_t)BB * NN * 2 * DD];

// ---------------- helpers ----------------
__device__ __forceinline__ uint32_t smem_to_u32(const void* p) {
    uint32_t a;
    asm("{ .reg .u64 t; cvta.to.shared.u64 t, %1; cvt.u32.u64 %0, t; }"
        : "=r"(a) : "l"(p));
    return a;
}
__device__ __forceinline__ uint prmt(uint a, uint b, uint s) {
    uint r; asm("prmt.b32 %0, %1, %2, %3;" : "=r"(r) : "r"(a), "r"(b), "r"(s));
    return r;
}
__device__ __forceinline__ void sts_v2(uint32_t addr, uint x, uint y) {
    asm volatile("st.shared.v2.b32 [%0], {%1, %2};" :: "r"(addr), "r"(x), "r"(y));
}
__device__ __forceinline__ void sts_v4(uint32_t addr, uint4 v) {
    asm volatile("st.shared.v4.b32 [%0], {%1, %2, %3, %4};"
                 :: "r"(addr), "r"(v.x), "r"(v.y), "r"(v.z), "r"(v.w));
}
__device__ __forceinline__ void ldsm4(uint* r, uint32_t addr) {
    asm volatile("ldmatrix.sync.aligned.m8n8.x4.shared.b16 {%0,%1,%2,%3}, [%4];"
        : "=r"(r[0]), "=r"(r[1]), "=r"(r[2]), "=r"(r[3]) : "r"(addr));
}

// HMMA m16n8k16 fp16 -> fp32
__device__ __forceinline__ void mma16816(float* c, const uint* a, uint b0, uint b1) {
    asm volatile(
        "mma.sync.aligned.m16n8k16.row.col.f32.f16.f16.f32 "
        "{%0,%1,%2,%3}, {%4,%5,%6,%7}, {%8,%9}, {%0,%1,%2,%3};"
        : "+f"(c[0]), "+f"(c[1]), "+f"(c[2]), "+f"(c[3])
        : "r"(a[0]), "r"(a[1]), "r"(a[2]), "r"(a[3]), "r"(b0), "r"(b1));
}

// ---- packed f32x2 helpers (attn) ----
__device__ __forceinline__ void ffma2(ull& d, ull a, ull b) {
    asm("fma.rn.f32x2 %0, %1, %2, %0;" : "+l"(d) : "l"(a), "l"(b));
}
__device__ __forceinline__ ull pack2(float x, float y) {
    ull r; asm("mov.b64 %0, {%1, %2};" : "=l"(r) : "f"(x), "f"(y)); return r;
}
__device__ __forceinline__ void unpack2(ull v, float& lo, float& hi) {
    asm("mov.b64 {%0, %1}, %2;" : "=f"(lo), "=f"(hi) : "l"(v));
}
__device__ __forceinline__ uint pack_split_h(float v) {
    __half h = __float2half_rn(v);
    float hv = __half2float(h);
    __half l = __float2half_rn(v - hv);
    return (uint)__half_as_ushort(h) | ((uint)__half_as_ushort(l) << 16);
}

// ---------------------------------------------------------------------------
__global__ void weight_split(const float* __restrict__ in, uint* __restrict__ out, int n) {
    int i = blockIdx.x * 256 + threadIdx.x;
    if (i < n) out[i] = pack_split_h(in[i]);
}
__global__ void weight_half(const float* __restrict__ in, ushort* __restrict__ out, int n) {
    int i = blockIdx.x * 256 + threadIdx.x;
    if (i < n) out[i] = __half_as_ushort(__float2half_rn(in[i]));
}
__global__ void weight_split_off(const float* __restrict__ in, uint* __restrict__ out,
                                 int cols, int istr, int koff, int ostr) {
    int i = blockIdx.x * 256 + threadIdx.x;
    int m = i / cols, k = i - m * cols;
    out[(size_t)m * ostr + k] = pack_split_h(in[(size_t)m * istr + koff + k]);
}
__global__ void weight_half_off(const float* __restrict__ in, ushort* __restrict__ out,
                                int cols, int istr, int koff, int ostr) {
    int i = blockIdx.x * 256 + threadIdx.x;
    int m = i / cols, k = i - m * cols;
    out[(size_t)m * ostr + k] = __half_as_ushort(__float2half_rn(in[(size_t)m * istr + koff + k]));
}

// fp32 [B, C, N] -> fp16 [B, N, C]
__global__ void transpose_half(const float* __restrict__ in, ushort* __restrict__ out,
                               int C, int Nw) {
    __shared__ float tile[32][33];
    const int b = blockIdx.z;
    const int n0 = blockIdx.x * 32, c0 = blockIdx.y * 32;
    const int tx = threadIdx.x, ty = threadIdx.y;
    const float* inb = in + ((size_t)b * C + c0) * Nw + n0;
#pragma unroll
    for (int i = 0; i < 32; i += 8)
        tile[ty + i][tx] = inb[(size_t)(ty + i) * Nw + tx];
    __syncthreads();
    ushort* ob = out + ((size_t)b * Nw + n0) * C + c0;
#pragma unroll
    for (int i = 0; i < 32; i += 8)
        ob[(size_t)(ty + i) * C + tx] = __half_as_ushort(__float2half_rn(tile[tx][ty + i]));
}

// colsum of proj (coalesced, 32 CTAs): S[c] += sum over 128 rows
__global__ void colsum_kernel(const float* __restrict__ proj, float* __restrict__ S) {
    const int c = threadIdx.x;
    const float* p = proj + (size_t)blockIdx.x * 128 * KK + c;
    float s = 0.f;
#pragma unroll 8
    for (int m = 0; m < 128; m++) s += p[(size_t)m * KK];
    atomicAdd(&S[c], s);
}

// kp init: kp[b,d,c] = bk[d] * S[c]
__global__ void kp_init(const float* __restrict__ bk, const float* __restrict__ S,
                        float* __restrict__ kp) {
    int i = blockIdx.x * 256 + threadIdx.x;
    int c = i & (KK - 1);
    int d = (i >> 7) & (DD - 1);
    kp[i] = bk[d] * S[c];
}

// b1f[m] = b1[m] + dot(W1[m, 1024:2048], bm)
__global__ void bias_fold(const float* __restrict__ w1, const float* __restrict__ bm,
                          const float* __restrict__ b1, float* __restrict__ out) {
    const int m = blockIdx.x * 8 + (threadIdx.x >> 5);
    const int lane = threadIdx.x & 31;
    float s = 0.f;
#pragma unroll 4
    for (int c = lane; c < DD; c += 32)
        s += w1[(size_t)m * (2 * DD) + DD + c] * bm[c];
#pragma unroll
    for (int o = 16; o; o >>= 1) s += __shfl_xor_sync(0xFFFFFFFFu, s, o);
    if (lane == 0) out[m] = b1[m] + s;
}

// ---------------------------------------------------------------------------
// Warp-level HMMA GEMM.
// PLANES=2: A packed (hi|lo) uint, 2 MMAs/product.  PLANES=1: A plain fp16,
// 1 MMA/product, smaller smem, 2 CTAs/SM.
// MODE 0: fp32 out (+bias), row stride ostr
// MODE 2: +bias/BN/ReLU fp16-transpose out [B,Nw,M]
// MODE 3: plain-fp16 out [M, ostr] (weight precompute, no bias)
// CTA 128x128, KC=64, double-buffered smem (row stride 144B).
// ---------------------------------------------------------------------------
#define STG_S 136

template <int MODE, int PLANES>
__global__ void __launch_bounds__(256, 3 - PLANES) hmma_gemm(
    const void* __restrict__ Aptr,
    const ushort* __restrict__ B1,
    const ushort* __restrict__ B2,
    const float* __restrict__ bias,
    const float* __restrict__ gamma,
    const float* __restrict__ beta,
    const float* __restrict__ mean,
    const float* __restrict__ var,
    float* __restrict__ outF,
    ushort* __restrict__ outT,
    int M, int Kd, int Nw, int K1, int ostr)
{
    constexpr uint32_t PLA_LO = 18432;
    constexpr uint32_t PLB    = (PLANES == 2) ? 36864u : 18432u;
    constexpr uint32_t SMBUF  = (PLANES == 2) ? 55296u : 36864u;

    extern __shared__ char smem[];
    const uint32_t sb = smem_to_u32(smem);

    const int tid  = threadIdx.x;
    const int wid  = tid >> 5;
    const int lane = tid & 31;
    const int m0 = blockIdx.y * 128;
    const int n0 = blockIdx.x * 128;
    const int bb = blockIdx.z;

    const int wm = wid & 3;
    const int wn = wid >> 2;
    const int K2 = Kd - K1;
    const int fr = lane >> 2;
    const int fc = (lane & 3) * 2;

    float c[2][8][4];
#pragma unroll
    for (int mt = 0; mt < 2; mt++)
#pragma unroll
        for (int nt = 0; nt < 8; nt++)
#pragma unroll
            for (int j = 0; j < 4; j++) c[mt][nt][j] = 0.f;

    const int nc = Kd >> 6;
    uint4 pa[PLANES == 2 ? 8 : 4], pb[4];

    auto ldg_tile = [&](int ch) {
        const int k0 = ch * 64;
        if (PLANES == 2) {
            const uint* Ab = (const uint*)Aptr + (size_t)m0 * Kd;
#pragma unroll
            for (int it = 0; it < 8; it++) {
                const int idx = it * 256 + tid;
                const int row = idx >> 4, q4 = idx & 15;
                pa[it] = *(const uint4*)(Ab + (size_t)row * Kd + k0 + q4 * 4);
            }
        } else {
            const ushort* Ab = (const ushort*)Aptr + (size_t)m0 * Kd;
#pragma unroll
            for (int it = 0; it < 4; it++) {
                const int idx = it * 256 + tid;
                const int row = idx >> 3, q4 = idx & 7;
                pa[it] = *(const uint4*)(Ab + (size_t)row * Kd + k0 + q4 * 8);
            }
        }
        const ushort* Bsrc; int kloc, kstride;
        if (k0 < K1) { Bsrc = B1; kloc = k0;      kstride = K1; }
        else         { Bsrc = B2; kloc = k0 - K1; kstride = K2; }
        const ushort* Bb = Bsrc + ((size_t)bb * Nw + n0) * kstride + kloc;
#pragma unroll
        for (int it = 0; it < 4; it++) {
            const int idx = it * 256 + tid;
            const int row = idx >> 3, q4 = idx & 7;
            pb[it] = *(const uint4*)(Bb + (size_t)row * kstride + q4 * 8);
        }
    };
    auto sts_tile = [&](int buf) {
        const uint32_t base = sb + buf * SMBUF;
        if (PLANES == 2) {
#pragma unroll
            for (int it = 0; it < 8; it++) {
                const int idx = it * 256 + tid;
                const int row = idx >> 4, q4 = idx & 15;
                const uint32_t off = (uint32_t)row * 144 + q4 * 8;
                uint4 v = pa[it];
                sts_v2(base + off, prmt(v.x, v.y, 0x5410), prmt(v.z, v.w, 0x5410));
                sts_v2(base + PLA_LO + off, prmt(v.x, v.y, 0x7632), prmt(v.z, v.w, 0x7632));
            }
        } else {
#pragma unroll
            for (int it = 0; it < 4; it++) {
                const int idx = it * 256 + tid;
                const int row = idx >> 3, q4 = idx & 7;
                sts_v4(base + (uint32_t)row * 144 + q4 * 16, pa[it]);
            }
        }
#pragma unroll
        for (int it = 0; it < 4; it++) {
            const int idx = it * 256 + tid;
            const int row = idx >> 3, q4 = idx & 7;
            sts_v4(base + PLB + (uint32_t)row * 144 + q4 * 16, pb[it]);
        }
    };

    ldg_tile(0);
    sts_tile(0);
    __syncthreads();

    const uint32_t aOff = (uint32_t)(wm * 32 + (lane & 15)) * 144 + ((lane >> 4) & 1) * 16;
    const uint32_t bOff = (uint32_t)(wn * 64 + (lane & 7) + ((lane & 16) ? 8 : 0)) * 144
                        + ((lane & 8) ? 16 : 0);

    for (int ch = 0; ch < nc; ch++) {
        const uint32_t base = sb + (ch & 1) * SMBUF;
        if (ch + 1 < nc) ldg_tile(ch + 1);
#pragma unroll
        for (int ksb = 0; ksb < 128; ksb += 32) {
            uint ah[2][4], al[2][4];
            ldsm4(ah[0], base + aOff + ksb);
            ldsm4(ah[1], base + aOff + 2304 + ksb);
            if (PLANES == 2) {
                ldsm4(al[0], base + PLA_LO + aOff + ksb);
                ldsm4(al[1], base + PLA_LO + aOff + 2304 + ksb);
            }
            uint bh[4][4];
#pragma unroll
            for (int np = 0; np < 4; np++)
                ldsm4(bh[np], base + PLB + bOff + np * 2304 + ksb);
#pragma unroll
            for (int np = 0; np < 4; np++)
#pragma unroll
                for (int sub = 0; sub < 2; sub++) {
                    const int nt = np * 2 + sub;
                    const uint b0 = bh[np][sub * 2], b1 = bh[np][sub * 2 + 1];
#pragma unroll
                    for (int mt = 0; mt < 2; mt++) {
                        mma16816(c[mt][nt], ah[mt], b0, b1);
                        if (PLANES == 2) mma16816(c[mt][nt], al[mt], b0, b1);
                    }
                }
        }
        if (ch + 1 < nc) {
            sts_tile((ch + 1) & 1);
            __syncthreads();
        }
    }

    // ---- epilogue ----
    if (MODE == 0) {
        const int cm = m0 + wm * 32 + fr;
        const int cn = n0 + wn * 64 + fc;
#pragma unroll
        for (int mt = 0; mt < 2; mt++) {
            const int mlo = cm + mt * 16;
            const int mhi = mlo + 8;
            const float bi0 = bias[mlo], bi1 = bias[mhi];
#pragma unroll
            for (int nt = 0; nt < 8; nt++) {
                const int n = cn + nt * 8;
                *(float2*)(outF + ((size_t)bb * M + mlo) * ostr + n) =
                    make_float2(c[mt][nt][0] + bi0, c[mt][nt][1] + bi0);
                *(float2*)(outF + ((size_t)bb * M + mhi) * ostr + n) =
                    make_float2(c[mt][nt][2] + bi1, c[mt][nt][3] + bi1);
            }
        }
    } else if (MODE == 3) {
        ushort* ob = outT;  // [M, ostr] plain fp16
        const int cm = m0 + wm * 32 + fr;
        const int cn = n0 + wn * 64 + fc;
#pragma unroll
        for (int mt = 0; mt < 2; mt++) {
            const int mlo = cm + mt * 16;
            const int mhi = mlo + 8;
#pragma unroll
            for (int nt = 0; nt < 8; nt++) {
                const int n = cn + nt * 8;
                ob[(size_t)mlo * ostr + n]     = __half_as_ushort(__float2half_rn(c[mt][nt][0]));
                ob[(size_t)mlo * ostr + n + 1] = __half_as_ushort(__float2half_rn(c[mt][nt][1]));
                ob[(size_t)mhi * ostr + n]     = __half_as_ushort(__float2half_rn(c[mt][nt][2]));
                ob[(size_t)mhi * ostr + n + 1] = __half_as_ushort(__float2half_rn(c[mt][nt][3]));
            }
        }
    } else {  // MODE 2: BN+ReLU, fp16 transpose out
        float* stg = (float*)smem;
        uint* ob = (uint*)(outT + (size_t)bb * Nw * M);
#pragma unroll
        for (int p = 0; p < 2; p++) {
            __syncthreads();
            if (wn == p) {
#pragma unroll
                for (int mt = 0; mt < 2; mt++) {
                    const int mloL = wm * 32 + mt * 16 + fr;
                    const int mhiL = mloL + 8;
                    const int mlo = m0 + mloL, mhi = m0 + mhiL;
                    float sc0 = gamma[mlo] * rsqrtf(var[mlo] + 1e-3f);
                    float sh0 = beta[mlo] + (bias[mlo] - mean[mlo]) * sc0;
                    float sc1 = gamma[mhi] * rsqrtf(var[mhi] + 1e-3f);
                    float sh1 = beta[mhi] + (bias[mhi] - mean[mhi]) * sc1;
#pragma unroll
                    for (int nt = 0; nt < 8; nt++) {
                        const int nl = fc + nt * 8;
                        stg[(nl)     * STG_S + mloL] = fmaxf(fmaf(c[mt][nt][0], sc0, sh0), 0.f);
                        stg[(nl + 1) * STG_S + mloL] = fmaxf(fmaf(c[mt][nt][1], sc0, sh0), 0.f);
                        stg[(nl)     * STG_S + mhiL] = fmaxf(fmaf(c[mt][nt][2], sc1, sh1), 0.f);
                        stg[(nl + 1) * STG_S + mhiL] = fmaxf(fmaf(c[mt][nt][3], sc1, sh1), 0.f);
                    }
                }
            }
            __syncthreads();
            const int nb = n0 + p * 64;
#pragma unroll 4
            for (int i = 0; i < 16; i++) {
                const int idx = i * 256 + tid;
                const int nn = idx >> 6;
                const int mp = idx & 63;
                const float* s = stg + nn * STG_S + mp * 2;
                const uint u = (uint)__half_as_ushort(__float2half_rn(s[0]))
                             | ((uint)__half_as_ushort(__float2half_rn(s[1])) << 16);
                ob[(size_t)(nb + nn) * (M >> 1) + (m0 >> 1) + mp] = u;
            }
        }
    }
}

// ---------------------------------------------------------------------------
// fp32 split-K GEMM: C[r,c] += A[r,m] * P[m,c]  (srcp = source @ proj)
// ---------------------------------------------------------------------------
__global__ void __launch_bounds__(256) proj_gemm(
    const float* __restrict__ A, const float* __restrict__ P, float* __restrict__ C)
{
    __shared__ float As[8][128];
    __shared__ float Bs[8][128];

    const int t  = threadIdx.x;
    const int ty = t >> 4;
    const int tx = t & 15;
    const int r0 = blockIdx.x * 128;
    const int chunk = NN / gridDim.y;
    const int c0 = blockIdx.y * chunk;

    const int ar = t >> 1, ac = (t & 1) * 4;
    const int br = t >> 5, bc = (t & 31) * 4;

    float acc[8][8];
#pragma unroll
    for (int i = 0; i < 8; i++)
#pragma unroll
        for (int j = 0; j < 8; j++) acc[i][j] = 0.f;

    for (int kt = 0; kt < chunk; kt += 8) {
        const int kb = c0 + kt;
        float4 av = *(const float4*)(A + (size_t)(r0 + ar) * NN + kb + ac);
        As[ac + 0][ar] = av.x;
        As[ac + 1][ar] = av.y;
        As[ac + 2][ar] = av.z;
        As[ac + 3][ar] = av.w;
        *(float4*)&Bs[br][bc] = *(const float4*)(P + (size_t)(kb + br) * KK + bc);
        __syncthreads();
#pragma unroll
        for (int kk = 0; kk < 8; kk++) {
            float a[8], bv[8];
#pragma unroll
            for (int i = 0; i < 8; i++) a[i] = As[kk][ty * 8 + i];
#pragma unroll
            for (int j = 0; j < 8; j++) bv[j] = Bs[kk][tx * 8 + j];
#pragma unroll
            for (int i = 0; i < 8; i++)
#pragma unroll
                for (int j = 0; j < 8; j++)
                    acc[i][j] = fmaf(a[i], bv[j], acc[i][j]);
        }
        __syncthreads();
    }

#pragma unroll
    for (int i = 0; i < 8; i++)
#pragma unroll
        for (int j = 0; j < 8; j++)
            atomicAdd(&C[(size_t)(r0 + ty * 8 + i) * KK + tx * 8 + j], acc[i][j]);
}

// ---------------------------------------------------------------------------
// kp = Wk @ srcp (per batch), accumulated onto kp_init values.
// ---------------------------------------------------------------------------
__global__ void __launch_bounds__(256) kp_gemm(
    const float* __restrict__ W, const float* __restrict__ P, float* __restrict__ C)
{
    __shared__ float As[8][128];
    __shared__ float Bs[8][128];

    const int t  = threadIdx.x;
    const int ty = t >> 4;
    const int tx = t & 15;
    const int r0 = blockIdx.x * 128;
    const int chunk = DD / gridDim.y;
    const int c0 = blockIdx.y * chunk;
    const int b = blockIdx.z;

    const float* Pb = P + (size_t)b * DD * KK;
    float* Cb = C + (size_t)b * DD * KK;

    const int ar = t >> 1, ac = (t & 1) * 4;
    const int br = t >> 5, bc = (t & 31) * 4;

    float acc[8][8];
#pragma unroll
    for (int i = 0; i < 8; i++)
#pragma unroll
        for (int j = 0; j < 8; j++) acc[i][j] = 0.f;

    for (int kt = 0; kt < chunk; kt += 8) {
        const int kb = c0 + kt;
        float4 av = *(const float4*)(W + (size_t)(r0 + ar) * DD + kb + ac);
        As[ac + 0][ar] = av.x;
        As[ac + 1][ar] = av.y;
        As[ac + 2][ar] = av.z;
        As[ac + 3][ar] = av.w;
        *(float4*)&Bs[br][bc] = *(const float4*)(Pb + (size_t)(kb + br) * KK + bc);
        __syncthreads();
#pragma unroll
        for (int kk = 0; kk < 8; kk++) {
            float a[8], bv[8];
#pragma unroll
            for (int i = 0; i < 8; i++) a[i] = As[kk][ty * 8 + i];
#pragma unroll
            for (int j = 0; j < 8; j++) bv[j] = Bs[kk][tx * 8 + j];
#pragma unroll
            for (int i = 0; i < 8; i++)
#pragma unroll
                for (int j = 0; j < 8; j++)
                    acc[i][j] = fmaf(a[i], bv[j], acc[i][j]);
        }
        __syncthreads();
    }

#pragma unroll
    for (int i = 0; i < 8; i++)
#pragma unroll
        for (int j = 0; j < 8; j++)
            atomicAdd(&Cb[(size_t)(r0 + ty * 8 + i) * KK + tx * 8 + j], acc[i][j]);
}

// ---------------------------------------------------------------------------
// Fused Linformer attention, two-pass, register accumulators.
// ---------------------------------------------------------------------------
#define KST_STRIDE 66

__global__ void __launch_bounds__(128, 2) attn_kernel(
    const float* __restrict__ q,
    const float* __restrict__ kp,
    float* __restrict__ msg)
{
    __shared__ float KsT[KK * KST_STRIDE];

    const int tid = threadIdx.x;
    const int n = blockIdx.x * 128 + tid;
    const int h = blockIdx.y;
    const int b = blockIdx.z;

#pragma unroll 4
    for (int dh = 0; dh < DHH; dh++)
        KsT[tid * KST_STRIDE + dh] = kp[((size_t)b * DD + (size_t)dh * HH + h) * KK + tid];
    __syncthreads();

    const float* qb = q + ((size_t)b * DD + h) * NN + n;
    ull qv2[DHH / 2];
#pragma unroll
    for (int dhp = 0; dhp < DHH / 2; dhp++) {
        float x = qb[(size_t)(2 * dhp) * HH * NN];
        float y = qb[(size_t)(2 * dhp + 1) * HH * NN];
        qv2[dhp] = pack2(x, y);
    }

    float mraw = -1e30f;
#pragma unroll 2
    for (int k = 0; k < KK; k++) {
        ull s2 = 0ULL;
        const float* krow = KsT + k * KST_STRIDE;
#pragma unroll
        for (int dhp = 0; dhp < DHH / 2; dhp++)
            ffma2(s2, qv2[dhp], *(const ull*)(krow + 2 * dhp));
        float lo, hi;
        unpack2(s2, lo, hi);
        mraw = fmaxf(mraw, lo + hi);
    }
    const float mx = mraw * 0.125f;

    float sum = 0.f;
    ull acc2[DHH / 2];
#pragma unroll
    for (int dhp = 0; dhp < DHH / 2; dhp++) acc2[dhp] = 0ULL;

#pragma unroll 2
    for (int k = 0; k < KK; k++) {
        ull s2 = 0ULL;
        const float* krow = KsT + k * KST_STRIDE;
#pragma unroll
        for (int dhp = 0; dhp < DHH / 2; dhp++)
            ffma2(s2, qv2[dhp], *(const ull*)(krow + 2 * dhp));
        float lo, hi;
        unpack2(s2, lo, hi);
        const float e = __expf(fmaf(lo + hi, 0.125f, -mx));
        sum += e;
        const ull e2 = pack2(e, e);
#pragma unroll
        for (int dhp = 0; dhp < DHH / 2; dhp++)
            ffma2(acc2[dhp], e2, *(const ull*)(krow + 2 * dhp));
    }
    const float inv = 1.f / sum;

    float* msgb = msg + ((size_t)b * DD + h) * NN + n;
#pragma unroll
    for (int dhp = 0; dhp < DHH / 2; dhp++) {
        float lo, hi;
        unpack2(acc2[dhp], lo, hi);
        msgb[(size_t)(2 * dhp) * HH * NN]     = lo * inv;
        msgb[(size_t)(2 * dhp + 1) * HH * NN] = hi * inv;
    }
}

// ---------------------------------------------------------------------------
extern "C" void kernel_launch(void* const* d_in, const int* in_sizes, int n_in,
                              void* d_out, int out_size)
{
    const float* x       = (const float*)d_in[0];
    const float* source  = (const float*)d_in[1];
    const float* to_q_w  = (const float*)d_in[2];
    const float* to_q_b  = (const float*)d_in[3];
    const float* to_k_w  = (const float*)d_in[4];
    const float* to_k_b  = (const float*)d_in[5];
    const float* proj_k  = (const float*)d_in[6];
    const float* merge_w = (const float*)d_in[7];
    const float* merge_b = (const float*)d_in[8];
    const float* mlp_w1  = (const float*)d_in[9];
    const float* mlp_b1  = (const float*)d_in[10];
    const float* bn_g    = (const float*)d_in[11];
    const float* bn_b    = (const float*)d_in[12];
    const float* bn_m    = (const float*)d_in[13];
    const float* bn_v    = (const float*)d_in[14];
    const float* mlp_w2  = (const float*)d_in[15];
    const float* mlp_b2  = (const float*)d_in[16];
    float* out = (float*)d_out;

    float *q, *msg, *kp, *srcp, *scol, *b1f;
    uint *ws1b, *ws2;
    ushort *wqh, *ws1fh, *wmT, *xs, *msgs, *hs;
    cudaGetSymbolAddress((void**)&q,    g_q);
    cudaGetSymbolAddress((void**)&msg,  g_msg);
    cudaGetSymbolAddress((void**)&kp,   g_kp);
    cudaGetSymbolAddress((void**)&srcp, g_srcp);
    cudaGetSymbolAddress((void**)&scol, g_scol);
    cudaGetSymbolAddress((void**)&b1f,  g_b1f);
    cudaGetSymbolAddress((void**)&wqh,  g_wq_h);
    cudaGetSymbolAddress((void**)&ws1fh,g_ws1f_h);
    cudaGetSymbolAddress((void**)&ws1b, g_ws_1b);
    cudaGetSymbolAddress((void**)&ws2,  g_ws_2);
    cudaGetSymbolAddress((void**)&wmT,  g_wmT);
    cudaGetSymbolAddress((void**)&xs,   g_xs);
    cudaGetSymbolAddress((void**)&msgs, g_msgs);
    cudaGetSymbolAddress((void**)&hs,   g_hs);

    const int SM2 = 2 * 55296;   // 2-plane smem
    const int SM1 = 2 * 36864;   // 1-plane smem
    cudaFuncSetAttribute(hmma_gemm<0, 1>, cudaFuncAttributeMaxDynamicSharedMemorySize, SM1);
    cudaFuncSetAttribute(hmma_gemm<2, 1>, cudaFuncAttributeMaxDynamicSharedMemorySize, SM1);
    cudaFuncSetAttribute(hmma_gemm<0, 2>, cudaFuncAttributeMaxDynamicSharedMemorySize, SM2);
    cudaFuncSetAttribute(hmma_gemm<3, 2>, cudaFuncAttributeMaxDynamicSharedMemorySize, SM2);

    // 0) weight prep
    weight_half<<<(DD * DD + 255) / 256, 256>>>(to_q_w, wqh, DD * DD);
    weight_split<<<(2 * DD * DD + 255) / 256, 256>>>(mlp_w2, ws2, 2 * DD * DD);
    // W1a half of fused fp16 weight
    weight_half_off<<<(2 * DD * DD) / 256, 256>>>(mlp_w1, ws1fh, DD, 2 * DD, 0, 2 * DD);
    // W1b 2-plane (for precompute)
    weight_split_off<<<(2 * DD * DD) / 256, 256>>>(mlp_w1, ws1b, DD, 2 * DD, DD, DD);
    // Wm^T fp16
    transpose_half<<<dim3(DD / 32, DD / 32, 1), dim3(32, 8)>>>(merge_w, wmT, DD, DD);
    // W1c = W1b @ Wm -> ws1fh[m][1024:2048]  (MODE3, plain fp16 out)
    hmma_gemm<3, 2><<<dim3(DD / 128, (2 * DD) / 128, 1), 256, SM2>>>(
        ws1b, wmT, wmT, nullptr, nullptr, nullptr, nullptr, nullptr,
        nullptr, ws1fh + DD, 2 * DD, DD, DD, DD, 2 * DD);
    // b1' = b1 + W1b @ bm
    bias_fold<<<(2 * DD) / 8, 256>>>(mlp_w1, merge_b, mlp_b1, b1f);

    // x transpose
    transpose_half<<<dim3(NN / 32, DD / 32, BB), dim3(32, 8)>>>(x, xs, DD, NN);

    // 1) Linformer fold: kp = Wk @ (src @ proj) + bk * colsum(proj)
    cudaMemsetAsync(scol, 0, sizeof(float) * KK);
    colsum_kernel<<<NN / 128, KK>>>(proj_k, scol);
    cudaMemsetAsync(srcp, 0, sizeof(float) * (size_t)BB * DD * KK);
    proj_gemm<<<dim3((BB * DD) / 128, 8), 256>>>(source, proj_k, srcp);
    kp_init<<<(BB * DD * KK) / 256, 256>>>(to_k_b, scol, kp);
    kp_gemm<<<dim3(DD / 128, 4, BB), 256>>>(to_k_w, srcp, kp);

    // 2) q = Wq @ x + bq  (single-plane, fp32 out)
    hmma_gemm<0, 1><<<dim3(NN / 128, DD / 128, BB), 256, SM1>>>(
        wqh, xs, xs, to_q_b, nullptr, nullptr, nullptr, nullptr,
        q, nullptr, DD, DD, NN, DD, NN);

    // 3) fused attention -> msg (fp32)
    attn_kernel<<<dim3(NN / 128, HH, BB), dim3(128)>>>(q, kp, msg);

    // 4) transpose msg -> fp16
    transpose_half<<<dim3(NN / 32, DD / 32, BB), dim3(32, 8)>>>(msg, msgs, DD, NN);

    // 5) h = relu(BN([W1a | W1c] @ concat(x, msg) + b1'))  (single-plane)
    hmma_gemm<2, 1><<<dim3(NN / 128, (2 * DD) / 128, BB), 256, SM1>>>(
        ws1fh, xs, msgs, b1f, bn_g, bn_b, bn_m, bn_v,
        nullptr, hs, 2 * DD, 2 * DD, NN, DD, 0);

    // 6) out = W2 @ h + b2  (2-plane, fp32 out)
    hmma_gemm<0, 2><<<dim3(NN / 128, DD / 128, BB), 256, SM2>>>(
        ws2, hs, hs, mlp_b2, nullptr, nullptr, nullptr, nullptr,
        out, nullptr, DD, 2 * DD, NN, 2 * DD, NN);
}

// round 9
// speedup vs baseline: 6.5329x; 1.1840x over previous
#include <cuda_runtime.h>
#include <cuda_fp16.h>
#include <math.h>
#include <stdint.h>

// Problem constants
#define BB 4
#define DD 1024
#define NN 4096
#define HH 16
#define KK 128
#define DHH 64

typedef unsigned long long ull;
typedef unsigned int uint;
typedef unsigned short ushort;

// ---------------- scratch (device globals) ----------------
__device__ float g_q   [(size_t)BB * DD * NN];
__device__ float g_msg [(size_t)BB * DD * NN];
__device__ float g_kp  [(size_t)BB * DD * KK];
__device__ float g_srcp[(size_t)BB * DD * KK];
__device__ float g_scol[KK];
__device__ float g_b1f [2 * DD];

// single-plane fp16 weights
__device__ ushort g_wq_h  [(size_t)DD * DD];
__device__ ushort g_ws1f_h[(size_t)(2 * DD) * (2 * DD)];  // [W1a | W1b@Wm] fp16
__device__ ushort g_ws2_h [(size_t)DD * (2 * DD)];        // mlp2 fp16
// 2-plane packed weights (precompute only)
__device__ uint   g_ws_1b [(size_t)(2 * DD) * DD];        // W1b
__device__ ushort g_wmT   [(size_t)DD * DD];              // Wm^T fp16
// fp16 activations
__device__ ushort g_xs   [(size_t)BB * NN * DD];
__device__ ushort g_msgs [(size_t)BB * NN * DD];
__device__ ushort g_hs   [(size_t)BB * NN * 2 * DD];

// ---------------- helpers ----------------
__device__ __forceinline__ uint32_t smem_to_u32(const void* p) {
    uint32_t a;
    asm("{ .reg .u64 t; cvta.to.shared.u64 t, %1; cvt.u32.u64 %0, t; }"
        : "=r"(a) : "l"(p));
    return a;
}
__device__ __forceinline__ uint prmt(uint a, uint b, uint s) {
    uint r; asm("prmt.b32 %0, %1, %2, %3;" : "=r"(r) : "r"(a), "r"(b), "r"(s));
    return r;
}
__device__ __forceinline__ void sts_v2(uint32_t addr, uint x, uint y) {
    asm volatile("st.shared.v2.b32 [%0], {%1, %2};" :: "r"(addr), "r"(x), "r"(y));
}
__device__ __forceinline__ void sts_v4(uint32_t addr, uint4 v) {
    asm volatile("st.shared.v4.b32 [%0], {%1, %2, %3, %4};"
                 :: "r"(addr), "r"(v.x), "r"(v.y), "r"(v.z), "r"(v.w));
}
__device__ __forceinline__ void ldsm4(uint* r, uint32_t addr) {
    asm volatile("ldmatrix.sync.aligned.m8n8.x4.shared.b16 {%0,%1,%2,%3}, [%4];"
        : "=r"(r[0]), "=r"(r[1]), "=r"(r[2]), "=r"(r[3]) : "r"(addr));
}

// HMMA m16n8k16 fp16 -> fp32
__device__ __forceinline__ void mma16816(float* c, const uint* a, uint b0, uint b1) {
    asm volatile(
        "mma.sync.aligned.m16n8k16.row.col.f32.f16.f16.f32 "
        "{%0,%1,%2,%3}, {%4,%5,%6,%7}, {%8,%9}, {%0,%1,%2,%3};"
        : "+f"(c[0]), "+f"(c[1]), "+f"(c[2]), "+f"(c[3])
        : "r"(a[0]), "r"(a[1]), "r"(a[2]), "r"(a[3]), "r"(b0), "r"(b1));
}

// ---- packed f32x2 helpers (attn) ----
__device__ __forceinline__ void ffma2(ull& d, ull a, ull b) {
    asm("fma.rn.f32x2 %0, %1, %2, %0;" : "+l"(d) : "l"(a), "l"(b));
}
__device__ __forceinline__ ull pack2(float x, float y) {
    ull r; asm("mov.b64 %0, {%1, %2};" : "=l"(r) : "f"(x), "f"(y)); return r;
}
__device__ __forceinline__ void unpack2(ull v, float& lo, float& hi) {
    asm("mov.b64 {%0, %1}, %2;" : "=f"(lo), "=f"(hi) : "l"(v));
}
__device__ __forceinline__ uint pack_split_h(float v) {
    __half h = __float2half_rn(v);
    float hv = __half2float(h);
    __half l = __float2half_rn(v - hv);
    return (uint)__half_as_ushort(h) | ((uint)__half_as_ushort(l) << 16);
}

// ---------------------------------------------------------------------------
__global__ void weight_half(const float* __restrict__ in, ushort* __restrict__ out, int n) {
    int i = blockIdx.x * 256 + threadIdx.x;
    if (i < n) out[i] = __half_as_ushort(__float2half_rn(in[i]));
}
__global__ void weight_split_off(const float* __restrict__ in, uint* __restrict__ out,
                                 int cols, int istr, int koff, int ostr) {
    int i = blockIdx.x * 256 + threadIdx.x;
    int m = i / cols, k = i - m * cols;
    out[(size_t)m * ostr + k] = pack_split_h(in[(size_t)m * istr + koff + k]);
}
__global__ void weight_half_off(const float* __restrict__ in, ushort* __restrict__ out,
                                int cols, int istr, int koff, int ostr) {
    int i = blockIdx.x * 256 + threadIdx.x;
    int m = i / cols, k = i - m * cols;
    out[(size_t)m * ostr + k] = __half_as_ushort(__float2half_rn(in[(size_t)m * istr + koff + k]));
}

// fp32 [B, C, N] -> fp16 [B, N, C]
__global__ void transpose_half(const float* __restrict__ in, ushort* __restrict__ out,
                               int C, int Nw) {
    __shared__ float tile[32][33];
    const int b = blockIdx.z;
    const int n0 = blockIdx.x * 32, c0 = blockIdx.y * 32;
    const int tx = threadIdx.x, ty = threadIdx.y;
    const float* inb = in + ((size_t)b * C + c0) * Nw + n0;
#pragma unroll
    for (int i = 0; i < 32; i += 8)
        tile[ty + i][tx] = inb[(size_t)(ty + i) * Nw + tx];
    __syncthreads();
    ushort* ob = out + ((size_t)b * Nw + n0) * C + c0;
#pragma unroll
    for (int i = 0; i < 32; i += 8)
        ob[(size_t)(ty + i) * C + tx] = __half_as_ushort(__float2half_rn(tile[tx][ty + i]));
}

// colsum of proj (coalesced, 32 CTAs): S[c] += sum over 128 rows
__global__ void colsum_kernel(const float* __restrict__ proj, float* __restrict__ S) {
    const int c = threadIdx.x;
    const float* p = proj + (size_t)blockIdx.x * 128 * KK + c;
    float s = 0.f;
#pragma unroll 8
    for (int m = 0; m < 128; m++) s += p[(size_t)m * KK];
    atomicAdd(&S[c], s);
}

// kp init: kp[b,d,c] = bk[d] * S[c]
__global__ void kp_init(const float* __restrict__ bk, const float* __restrict__ S,
                        float* __restrict__ kp) {
    int i = blockIdx.x * 256 + threadIdx.x;
    int c = i & (KK - 1);
    int d = (i >> 7) & (DD - 1);
    kp[i] = bk[d] * S[c];
}

// b1f[m] = b1[m] + dot(W1[m, 1024:2048], bm)
__global__ void bias_fold(const float* __restrict__ w1, const float* __restrict__ bm,
                          const float* __restrict__ b1, float* __restrict__ out) {
    const int m = blockIdx.x * 8 + (threadIdx.x >> 5);
    const int lane = threadIdx.x & 31;
    float s = 0.f;
#pragma unroll 4
    for (int c = lane; c < DD; c += 32)
        s += w1[(size_t)m * (2 * DD) + DD + c] * bm[c];
#pragma unroll
    for (int o = 16; o; o >>= 1) s += __shfl_xor_sync(0xFFFFFFFFu, s, o);
    if (lane == 0) out[m] = b1[m] + s;
}

// ---------------------------------------------------------------------------
// Warp-level HMMA GEMM.
// PLANES=2: A packed (hi|lo) uint, 2 MMAs/product.  PLANES=1: A plain fp16.
// MODE 0: fp32 out (+bias); MODE 2: +bias/BN/ReLU fp16-transpose out;
// MODE 3: plain-fp16 out (weight precompute).
// CTA 128x128, KC=64, double-buffered smem (row stride 144B).
// ---------------------------------------------------------------------------
#define STG_S 136

template <int MODE, int PLANES>
__global__ void __launch_bounds__(256, 3 - PLANES) hmma_gemm(
    const void* __restrict__ Aptr,
    const ushort* __restrict__ B1,
    const ushort* __restrict__ B2,
    const float* __restrict__ bias,
    const float* __restrict__ gamma,
    const float* __restrict__ beta,
    const float* __restrict__ mean,
    const float* __restrict__ var,
    float* __restrict__ outF,
    ushort* __restrict__ outT,
    int M, int Kd, int Nw, int K1, int ostr)
{
    constexpr uint32_t PLA_LO = 18432;
    constexpr uint32_t PLB    = (PLANES == 2) ? 36864u : 18432u;
    constexpr uint32_t SMBUF  = (PLANES == 2) ? 55296u : 36864u;

    extern __shared__ char smem[];
    const uint32_t sb = smem_to_u32(smem);

    const int tid  = threadIdx.x;
    const int wid  = tid >> 5;
    const int lane = tid & 31;
    const int m0 = blockIdx.y * 128;
    const int n0 = blockIdx.x * 128;
    const int bb = blockIdx.z;

    const int wm = wid & 3;
    const int wn = wid >> 2;
    const int K2 = Kd - K1;
    const int fr = lane >> 2;
    const int fc = (lane & 3) * 2;

    float c[2][8][4];
#pragma unroll
    for (int mt = 0; mt < 2; mt++)
#pragma unroll
        for (int nt = 0; nt < 8; nt++)
#pragma unroll
            for (int j = 0; j < 4; j++) c[mt][nt][j] = 0.f;

    const int nc = Kd >> 6;
    uint4 pa[PLANES == 2 ? 8 : 4], pb[4];

    auto ldg_tile = [&](int ch) {
        const int k0 = ch * 64;
        if (PLANES == 2) {
            const uint* Ab = (const uint*)Aptr + (size_t)m0 * Kd;
#pragma unroll
            for (int it = 0; it < 8; it++) {
                const int idx = it * 256 + tid;
                const int row = idx >> 4, q4 = idx & 15;
                pa[it] = *(const uint4*)(Ab + (size_t)row * Kd + k0 + q4 * 4);
            }
        } else {
            const ushort* Ab = (const ushort*)Aptr + (size_t)m0 * Kd;
#pragma unroll
            for (int it = 0; it < 4; it++) {
                const int idx = it * 256 + tid;
                const int row = idx >> 3, q4 = idx & 7;
                pa[it] = *(const uint4*)(Ab + (size_t)row * Kd + k0 + q4 * 8);
            }
        }
        const ushort* Bsrc; int kloc, kstride;
        if (k0 < K1) { Bsrc = B1; kloc = k0;      kstride = K1; }
        else         { Bsrc = B2; kloc = k0 - K1; kstride = K2; }
        const ushort* Bb = Bsrc + ((size_t)bb * Nw + n0) * kstride + kloc;
#pragma unroll
        for (int it = 0; it < 4; it++) {
            const int idx = it * 256 + tid;
            const int row = idx >> 3, q4 = idx & 7;
            pb[it] = *(const uint4*)(Bb + (size_t)row * kstride + q4 * 8);
        }
    };
    auto sts_tile = [&](int buf) {
        const uint32_t base = sb + buf * SMBUF;
        if (PLANES == 2) {
#pragma unroll
            for (int it = 0; it < 8; it++) {
                const int idx = it * 256 + tid;
                const int row = idx >> 4, q4 = idx & 15;
                const uint32_t off = (uint32_t)row * 144 + q4 * 8;
                uint4 v = pa[it];
                sts_v2(base + off, prmt(v.x, v.y, 0x5410), prmt(v.z, v.w, 0x5410));
                sts_v2(base + PLA_LO + off, prmt(v.x, v.y, 0x7632), prmt(v.z, v.w, 0x7632));
            }
        } else {
#pragma unroll
            for (int it = 0; it < 4; it++) {
                const int idx = it * 256 + tid;
                const int row = idx >> 3, q4 = idx & 7;
                sts_v4(base + (uint32_t)row * 144 + q4 * 16, pa[it]);
            }
        }
#pragma unroll
        for (int it = 0; it < 4; it++) {
            const int idx = it * 256 + tid;
            const int row = idx >> 3, q4 = idx & 7;
            sts_v4(base + PLB + (uint32_t)row * 144 + q4 * 16, pb[it]);
        }
    };

    ldg_tile(0);
    sts_tile(0);
    __syncthreads();

    const uint32_t aOff = (uint32_t)(wm * 32 + (lane & 15)) * 144 + ((lane >> 4) & 1) * 16;
    const uint32_t bOff = (uint32_t)(wn * 64 + (lane & 7) + ((lane & 16) ? 8 : 0)) * 144
                        + ((lane & 8) ? 16 : 0);

    for (int ch = 0; ch < nc; ch++) {
        const uint32_t base = sb + (ch & 1) * SMBUF;
        if (ch + 1 < nc) ldg_tile(ch + 1);
#pragma unroll
        for (int ksb = 0; ksb < 128; ksb += 32) {
            uint ah[2][4], al[2][4];
            ldsm4(ah[0], base + aOff + ksb);
            ldsm4(ah[1], base + aOff + 2304 + ksb);
            if (PLANES == 2) {
                ldsm4(al[0], base + PLA_LO + aOff + ksb);
                ldsm4(al[1], base + PLA_LO + aOff + 2304 + ksb);
            }
            uint bh[4][4];
#pragma unroll
            for (int np = 0; np < 4; np++)
                ldsm4(bh[np], base + PLB + bOff + np * 2304 + ksb);
#pragma unroll
            for (int np = 0; np < 4; np++)
#pragma unroll
                for (int sub = 0; sub < 2; sub++) {
                    const int nt = np * 2 + sub;
                    const uint b0 = bh[np][sub * 2], b1 = bh[np][sub * 2 + 1];
#pragma unroll
                    for (int mt = 0; mt < 2; mt++) {
                        mma16816(c[mt][nt], ah[mt], b0, b1);
                        if (PLANES == 2) mma16816(c[mt][nt], al[mt], b0, b1);
                    }
                }
        }
        if (ch + 1 < nc) {
            sts_tile((ch + 1) & 1);
            __syncthreads();
        }
    }

    // ---- epilogue ----
    if (MODE == 0) {
        const int cm = m0 + wm * 32 + fr;
        const int cn = n0 + wn * 64 + fc;
#pragma unroll
        for (int mt = 0; mt < 2; mt++) {
            const int mlo = cm + mt * 16;
            const int mhi = mlo + 8;
            const float bi0 = bias[mlo], bi1 = bias[mhi];
#pragma unroll
            for (int nt = 0; nt < 8; nt++) {
                const int n = cn + nt * 8;
                *(float2*)(outF + ((size_t)bb * M + mlo) * ostr + n) =
                    make_float2(c[mt][nt][0] + bi0, c[mt][nt][1] + bi0);
                *(float2*)(outF + ((size_t)bb * M + mhi) * ostr + n) =
                    make_float2(c[mt][nt][2] + bi1, c[mt][nt][3] + bi1);
            }
        }
    } else if (MODE == 3) {
        ushort* ob = outT;  // [M, ostr] plain fp16
        const int cm = m0 + wm * 32 + fr;
        const int cn = n0 + wn * 64 + fc;
#pragma unroll
        for (int mt = 0; mt < 2; mt++) {
            const int mlo = cm + mt * 16;
            const int mhi = mlo + 8;
#pragma unroll
            for (int nt = 0; nt < 8; nt++) {
                const int n = cn + nt * 8;
                ob[(size_t)mlo * ostr + n]     = __half_as_ushort(__float2half_rn(c[mt][nt][0]));
                ob[(size_t)mlo * ostr + n + 1] = __half_as_ushort(__float2half_rn(c[mt][nt][1]));
                ob[(size_t)mhi * ostr + n]     = __half_as_ushort(__float2half_rn(c[mt][nt][2]));
                ob[(size_t)mhi * ostr + n + 1] = __half_as_ushort(__float2half_rn(c[mt][nt][3]));
            }
        }
    } else {  // MODE 2: BN+ReLU, fp16 transpose out
        float* stg = (float*)smem;
        uint* ob = (uint*)(outT + (size_t)bb * Nw * M);
#pragma unroll
        for (int p = 0; p < 2; p++) {
            __syncthreads();
            if (wn == p) {
#pragma unroll
                for (int mt = 0; mt < 2; mt++) {
                    const int mloL = wm * 32 + mt * 16 + fr;
                    const int mhiL = mloL + 8;
                    const int mlo = m0 + mloL, mhi = m0 + mhiL;
                    float sc0 = gamma[mlo] * rsqrtf(var[mlo] + 1e-3f);
                    float sh0 = beta[mlo] + (bias[mlo] - mean[mlo]) * sc0;
                    float sc1 = gamma[mhi] * rsqrtf(var[mhi] + 1e-3f);
                    float sh1 = beta[mhi] + (bias[mhi] - mean[mhi]) * sc1;
#pragma unroll
                    for (int nt = 0; nt < 8; nt++) {
                        const int nl = fc + nt * 8;
                        stg[(nl)     * STG_S + mloL] = fmaxf(fmaf(c[mt][nt][0], sc0, sh0), 0.f);
                        stg[(nl + 1) * STG_S + mloL] = fmaxf(fmaf(c[mt][nt][1], sc0, sh0), 0.f);
                        stg[(nl)     * STG_S + mhiL] = fmaxf(fmaf(c[mt][nt][2], sc1, sh1), 0.f);
                        stg[(nl + 1) * STG_S + mhiL] = fmaxf(fmaf(c[mt][nt][3], sc1, sh1), 0.f);
                    }
                }
            }
            __syncthreads();
            const int nb = n0 + p * 64;
#pragma unroll 4
            for (int i = 0; i < 16; i++) {
                const int idx = i * 256 + tid;
                const int nn = idx >> 6;
                const int mp = idx & 63;
                const float* s = stg + nn * STG_S + mp * 2;
                const uint u = (uint)__half_as_ushort(__float2half_rn(s[0]))
                             | ((uint)__half_as_ushort(__float2half_rn(s[1])) << 16);
                ob[(size_t)(nb + nn) * (M >> 1) + (m0 >> 1) + mp] = u;
            }
        }
    }
}

// ---------------------------------------------------------------------------
// fp32 split-K GEMM: C[r,c] += A[r,m] * P[m,c]  (srcp = source @ proj)
// ---------------------------------------------------------------------------
__global__ void __launch_bounds__(256) proj_gemm(
    const float* __restrict__ A, const float* __restrict__ P, float* __restrict__ C)
{
    __shared__ float As[8][128];
    __shared__ float Bs[8][128];

    const int t  = threadIdx.x;
    const int ty = t >> 4;
    const int tx = t & 15;
    const int r0 = blockIdx.x * 128;
    const int chunk = NN / gridDim.y;
    const int c0 = blockIdx.y * chunk;

    const int ar = t >> 1, ac = (t & 1) * 4;
    const int br = t >> 5, bc = (t & 31) * 4;

    float acc[8][8];
#pragma unroll
    for (int i = 0; i < 8; i++)
#pragma unroll
        for (int j = 0; j < 8; j++) acc[i][j] = 0.f;

    for (int kt = 0; kt < chunk; kt += 8) {
        const int kb = c0 + kt;
        float4 av = *(const float4*)(A + (size_t)(r0 + ar) * NN + kb + ac);
        As[ac + 0][ar] = av.x;
        As[ac + 1][ar] = av.y;
        As[ac + 2][ar] = av.z;
        As[ac + 3][ar] = av.w;
        *(float4*)&Bs[br][bc] = *(const float4*)(P + (size_t)(kb + br) * KK + bc);
        __syncthreads();
#pragma unroll
        for (int kk = 0; kk < 8; kk++) {
            float a[8], bv[8];
#pragma unroll
            for (int i = 0; i < 8; i++) a[i] = As[kk][ty * 8 + i];
#pragma unroll
            for (int j = 0; j < 8; j++) bv[j] = Bs[kk][tx * 8 + j];
#pragma unroll
            for (int i = 0; i < 8; i++)
#pragma unroll
                for (int j = 0; j < 8; j++)
                    acc[i][j] = fmaf(a[i], bv[j], acc[i][j]);
        }
        __syncthreads();
    }

#pragma unroll
    for (int i = 0; i < 8; i++)
#pragma unroll
        for (int j = 0; j < 8; j++)
            atomicAdd(&C[(size_t)(r0 + ty * 8 + i) * KK + tx * 8 + j], acc[i][j]);
}

// ---------------------------------------------------------------------------
// kp = Wk @ srcp (per batch), accumulated onto kp_init values.
// ---------------------------------------------------------------------------
__global__ void __launch_bounds__(256) kp_gemm(
    const float* __restrict__ W, const float* __restrict__ P, float* __restrict__ C)
{
    __shared__ float As[8][128];
    __shared__ float Bs[8][128];

    const int t  = threadIdx.x;
    const int ty = t >> 4;
    const int tx = t & 15;
    const int r0 = blockIdx.x * 128;
    const int chunk = DD / gridDim.y;
    const int c0 = blockIdx.y * chunk;
    const int b = blockIdx.z;

    const float* Pb = P + (size_t)b * DD * KK;
    float* Cb = C + (size_t)b * DD * KK;

    const int ar = t >> 1, ac = (t & 1) * 4;
    const int br = t >> 5, bc = (t & 31) * 4;

    float acc[8][8];
#pragma unroll
    for (int i = 0; i < 8; i++)
#pragma unroll
        for (int j = 0; j < 8; j++) acc[i][j] = 0.f;

    for (int kt = 0; kt < chunk; kt += 8) {
        const int kb = c0 + kt;
        float4 av = *(const float4*)(W + (size_t)(r0 + ar) * DD + kb + ac);
        As[ac + 0][ar] = av.x;
        As[ac + 1][ar] = av.y;
        As[ac + 2][ar] = av.z;
        As[ac + 3][ar] = av.w;
        *(float4*)&Bs[br][bc] = *(const float4*)(Pb + (size_t)(kb + br) * KK + bc);
        __syncthreads();
#pragma unroll
        for (int kk = 0; kk < 8; kk++) {
            float a[8], bv[8];
#pragma unroll
            for (int i = 0; i < 8; i++) a[i] = As[kk][ty * 8 + i];
#pragma unroll
            for (int j = 0; j < 8; j++) bv[j] = Bs[kk][tx * 8 + j];
#pragma unroll
            for (int i = 0; i < 8; i++)
#pragma unroll
                for (int j = 0; j < 8; j++)
                    acc[i][j] = fmaf(a[i], bv[j], acc[i][j]);
        }
        __syncthreads();
    }

#pragma unroll
    for (int i = 0; i < 8; i++)
#pragma unroll
        for (int j = 0; j < 8; j++)
            atomicAdd(&Cb[(size_t)(r0 + ty * 8 + i) * KK + tx * 8 + j], acc[i][j]);
}

// ---------------------------------------------------------------------------
// Fused Linformer attention: pass1 computes scores once, caches them as fp16
// in smem; pass2 reads cached scores (no recompute). Dynamic smem:
// KsT 128*66*4 = 33792 B + Es 128*128*2 = 32768 B -> 66560 B, 2 CTAs/SM.
// ---------------------------------------------------------------------------
#define KST_STRIDE 66
#define ES_S 128
#define ATTN_SMEM (KK * KST_STRIDE * 4 + KK * ES_S * 2)

__global__ void __launch_bounds__(128, 2) attn_kernel(
    const float* __restrict__ q,
    const float* __restrict__ kp,
    float* __restrict__ msg)
{
    extern __shared__ float dsm[];
    float* KsT = dsm;                                   // [128 k][66 dh]
    ushort* Es = (ushort*)(dsm + KK * KST_STRIDE);      // [128 k][128 n]

    const int tid = threadIdx.x;
    const int n = blockIdx.x * 128 + tid;
    const int h = blockIdx.y;
    const int b = blockIdx.z;

#pragma unroll 4
    for (int dh = 0; dh < DHH; dh++)
        KsT[tid * KST_STRIDE + dh] = kp[((size_t)b * DD + (size_t)dh * HH + h) * KK + tid];
    __syncthreads();

    const float* qb = q + ((size_t)b * DD + h) * NN + n;
    ull qv2[DHH / 2];
#pragma unroll
    for (int dhp = 0; dhp < DHH / 2; dhp++) {
        float x = qb[(size_t)(2 * dhp) * HH * NN];
        float y = qb[(size_t)(2 * dhp + 1) * HH * NN];
        qv2[dhp] = pack2(x, y);
    }

    // pass 1: scores once, cache fp16, track raw max
    float mraw = -1e30f;
#pragma unroll 2
    for (int k = 0; k < KK; k++) {
        ull s2 = 0ULL;
        const float* krow = KsT + k * KST_STRIDE;
#pragma unroll
        for (int dhp = 0; dhp < DHH / 2; dhp++)
            ffma2(s2, qv2[dhp], *(const ull*)(krow + 2 * dhp));
        float lo, hi;
        unpack2(s2, lo, hi);
        const float sraw = lo + hi;
        Es[k * ES_S + tid] = __half_as_ushort(__float2half_rn(sraw));
        mraw = fmaxf(mraw, sraw);
    }
    const float mx = mraw * 0.125f;

    // pass 2: exp from cached scores, accumulate msg
    float sum = 0.f;
    ull acc2[DHH / 2];
#pragma unroll
    for (int dhp = 0; dhp < DHH / 2; dhp++) acc2[dhp] = 0ULL;

#pragma unroll 2
    for (int k = 0; k < KK; k++) {
        const float sraw = __half2float(__ushort_as_half(Es[k * ES_S + tid]));
        const float e = __expf(fmaf(sraw, 0.125f, -mx));
        sum += e;
        const ull e2 = pack2(e, e);
        const float* krow = KsT + k * KST_STRIDE;
#pragma unroll
        for (int dhp = 0; dhp < DHH / 2; dhp++)
            ffma2(acc2[dhp], e2, *(const ull*)(krow + 2 * dhp));
    }
    const float inv = 1.f / sum;

    float* msgb = msg + ((size_t)b * DD + h) * NN + n;
#pragma unroll
    for (int dhp = 0; dhp < DHH / 2; dhp++) {
        float lo, hi;
        unpack2(acc2[dhp], lo, hi);
        msgb[(size_t)(2 * dhp) * HH * NN]     = lo * inv;
        msgb[(size_t)(2 * dhp + 1) * HH * NN] = hi * inv;
    }
}

// ---------------------------------------------------------------------------
extern "C" void kernel_launch(void* const* d_in, const int* in_sizes, int n_in,
                              void* d_out, int out_size)
{
    const float* x       = (const float*)d_in[0];
    const float* source  = (const float*)d_in[1];
    const float* to_q_w  = (const float*)d_in[2];
    const float* to_q_b  = (const float*)d_in[3];
    const float* to_k_w  = (const float*)d_in[4];
    const float* to_k_b  = (const float*)d_in[5];
    const float* proj_k  = (const float*)d_in[6];
    const float* merge_w = (const float*)d_in[7];
    const float* merge_b = (const float*)d_in[8];
    const float* mlp_w1  = (const float*)d_in[9];
    const float* mlp_b1  = (const float*)d_in[10];
    const float* bn_g    = (const float*)d_in[11];
    const float* bn_b    = (const float*)d_in[12];
    const float* bn_m    = (const float*)d_in[13];
    const float* bn_v    = (const float*)d_in[14];
    const float* mlp_w2  = (const float*)d_in[15];
    const float* mlp_b2  = (const float*)d_in[16];
    float* out = (float*)d_out;

    float *q, *msg, *kp, *srcp, *scol, *b1f;
    uint *ws1b;
    ushort *wqh, *ws1fh, *ws2h, *wmT, *xs, *msgs, *hs;
    cudaGetSymbolAddress((void**)&q,    g_q);
    cudaGetSymbolAddress((void**)&msg,  g_msg);
    cudaGetSymbolAddress((void**)&kp,   g_kp);
    cudaGetSymbolAddress((void**)&srcp, g_srcp);
    cudaGetSymbolAddress((void**)&scol, g_scol);
    cudaGetSymbolAddress((void**)&b1f,  g_b1f);
    cudaGetSymbolAddress((void**)&wqh,  g_wq_h);
    cudaGetSymbolAddress((void**)&ws1fh,g_ws1f_h);
    cudaGetSymbolAddress((void**)&ws2h, g_ws2_h);
    cudaGetSymbolAddress((void**)&ws1b, g_ws_1b);
    cudaGetSymbolAddress((void**)&wmT,  g_wmT);
    cudaGetSymbolAddress((void**)&xs,   g_xs);
    cudaGetSymbolAddress((void**)&msgs, g_msgs);
    cudaGetSymbolAddress((void**)&hs,   g_hs);

    const int SM2 = 2 * 55296;   // 2-plane smem
    const int SM1 = 2 * 36864;   // 1-plane smem
    cudaFuncSetAttribute(hmma_gemm<0, 1>, cudaFuncAttributeMaxDynamicSharedMemorySize, SM1);
    cudaFuncSetAttribute(hmma_gemm<2, 1>, cudaFuncAttributeMaxDynamicSharedMemorySize, SM1);
    cudaFuncSetAttribute(hmma_gemm<3, 2>, cudaFuncAttributeMaxDynamicSharedMemorySize, SM2);
    cudaFuncSetAttribute(attn_kernel, cudaFuncAttributeMaxDynamicSharedMemorySize, ATTN_SMEM);

    // 0) weight prep
    weight_half<<<(DD * DD + 255) / 256, 256>>>(to_q_w, wqh, DD * DD);
    weight_half<<<(2 * DD * DD + 255) / 256, 256>>>(mlp_w2, ws2h, 2 * DD * DD);
    // W1a half of fused fp16 weight
    weight_half_off<<<(2 * DD * DD) / 256, 256>>>(mlp_w1, ws1fh, DD, 2 * DD, 0, 2 * DD);
    // W1b 2-plane (for precompute)
    weight_split_off<<<(2 * DD * DD) / 256, 256>>>(mlp_w1, ws1b, DD, 2 * DD, DD, DD);
    // Wm^T fp16
    transpose_half<<<dim3(DD / 32, DD / 32, 1), dim3(32, 8)>>>(merge_w, wmT, DD, DD);
    // W1c = W1b @ Wm -> ws1fh[m][1024:2048]  (MODE3, plain fp16 out)
    hmma_gemm<3, 2><<<dim3(DD / 128, (2 * DD) / 128, 1), 256, SM2>>>(
        ws1b, wmT, wmT, nullptr, nullptr, nullptr, nullptr, nullptr,
        nullptr, ws1fh + DD, 2 * DD, DD, DD, DD, 2 * DD);
    // b1' = b1 + W1b @ bm
    bias_fold<<<(2 * DD) / 8, 256>>>(mlp_w1, merge_b, mlp_b1, b1f);

    // x transpose
    transpose_half<<<dim3(NN / 32, DD / 32, BB), dim3(32, 8)>>>(x, xs, DD, NN);

    // 1) Linformer fold: kp = Wk @ (src @ proj) + bk * colsum(proj)
    cudaMemsetAsync(scol, 0, sizeof(float) * KK);
    colsum_kernel<<<NN / 128, KK>>>(proj_k, scol);
    cudaMemsetAsync(srcp, 0, sizeof(float) * (size_t)BB * DD * KK);
    proj_gemm<<<dim3((BB * DD) / 128, 8), 256>>>(source, proj_k, srcp);
    kp_init<<<(BB * DD * KK) / 256, 256>>>(to_k_b, scol, kp);
    kp_gemm<<<dim3(DD / 128, 4, BB), 256>>>(to_k_w, srcp, kp);

    // 2) q = Wq @ x + bq  (single-plane, fp32 out)
    hmma_gemm<0, 1><<<dim3(NN / 128, DD / 128, BB), 256, SM1>>>(
        wqh, xs, xs, to_q_b, nullptr, nullptr, nullptr, nullptr,
        q, nullptr, DD, DD, NN, DD, NN);

    // 3) fused attention -> msg (fp32)
    attn_kernel<<<dim3(NN / 128, HH, BB), dim3(128), ATTN_SMEM>>>(q, kp, msg);

    // 4) transpose msg -> fp16
    transpose_half<<<dim3(NN / 32, DD / 32, BB), dim3(32, 8)>>>(msg, msgs, DD, NN);

    // 5) h = relu(BN([W1a | W1c] @ concat(x, msg) + b1'))  (single-plane)
    hmma_gemm<2, 1><<<dim3(NN / 128, (2 * DD) / 128, BB), 256, SM1>>>(
        ws1fh, xs, msgs, b1f, bn_g, bn_b, bn_m, bn_v,
        nullptr, hs, 2 * DD, 2 * DD, NN, DD, 0);

    // 6) out = W2 @ h + b2  (single-plane, fp32 out)
    hmma_gemm<0, 1><<<dim3(NN / 128, DD / 128, BB), 256, SM1>>>(
        ws2h, hs, hs, mlp_b2, nullptr, nullptr, nullptr, nullptr,
        out, nullptr, DD, 2 * DD, NN, 2 * DD, NN);
}

// round 10
// speedup vs baseline: 7.0631x; 1.0812x over previous
#include <cuda_runtime.h>
#include <cuda_fp16.h>
#include <math.h>
#include <stdint.h>

// Problem constants
#define BB 4
#define DD 1024
#define NN 4096
#define HH 16
#define KK 128
#define DHH 64

typedef unsigned long long ull;
typedef unsigned int uint;
typedef unsigned short ushort;

// ---------------- scratch (device globals) ----------------
__device__ float g_q   [(size_t)BB * DD * NN];
__device__ float g_kp  [(size_t)BB * DD * KK];
__device__ float g_srcp[(size_t)BB * DD * KK];
__device__ float g_scol[KK];
__device__ float g_b1f [2 * DD];

// single-plane fp16 weights
__device__ ushort g_wq_h  [(size_t)DD * DD];
__device__ ushort g_ws1f_h[(size_t)(2 * DD) * (2 * DD)];  // [W1a | W1c-perm] fp16
__device__ ushort g_ws2_h [(size_t)DD * (2 * DD)];
// precompute operands
__device__ uint   g_ws_1b [(size_t)(2 * DD) * DD];        // W1b 2-plane
__device__ ushort g_wmTp  [(size_t)DD * DD];              // perm-row merge^T fp16
// fp16 activations / operands
__device__ ushort g_xs   [(size_t)BB * NN * DD];
__device__ ushort g_msgs [(size_t)BB * NN * DD];          // head-major channels
__device__ ushort g_hs   [(size_t)BB * NN * 2 * DD];
__device__ ushort g_srch [(size_t)BB * DD * NN];          // source fp16 (row-major)
__device__ ushort g_projT[(size_t)KK * NN];               // proj^T fp16

// ---------------- helpers ----------------
__device__ __forceinline__ uint32_t smem_to_u32(const void* p) {
    uint32_t a;
    asm("{ .reg .u64 t; cvta.to.shared.u64 t, %1; cvt.u32.u64 %0, t; }"
        : "=r"(a) : "l"(p));
    return a;
}
__device__ __forceinline__ uint prmt(uint a, uint b, uint s) {
    uint r; asm("prmt.b32 %0, %1, %2, %3;" : "=r"(r) : "r"(a), "r"(b), "r"(s));
    return r;
}
__device__ __forceinline__ void sts_v2(uint32_t addr, uint x, uint y) {
    asm volatile("st.shared.v2.b32 [%0], {%1, %2};" :: "r"(addr), "r"(x), "r"(y));
}
__device__ __forceinline__ void sts_v4(uint32_t addr, uint4 v) {
    asm volatile("st.shared.v4.b32 [%0], {%1, %2, %3, %4};"
                 :: "r"(addr), "r"(v.x), "r"(v.y), "r"(v.z), "r"(v.w));
}
__device__ __forceinline__ void ldsm4(uint* r, uint32_t addr) {
    asm volatile("ldmatrix.sync.aligned.m8n8.x4.shared.b16 {%0,%1,%2,%3}, [%4];"
        : "=r"(r[0]), "=r"(r[1]), "=r"(r[2]), "=r"(r[3]) : "r"(addr));
}

// HMMA m16n8k16 fp16 -> fp32
__device__ __forceinline__ void mma16816(float* c, const uint* a, uint b0, uint b1) {
    asm volatile(
        "mma.sync.aligned.m16n8k16.row.col.f32.f16.f16.f32 "
        "{%0,%1,%2,%3}, {%4,%5,%6,%7}, {%8,%9}, {%0,%1,%2,%3};"
        : "+f"(c[0]), "+f"(c[1]), "+f"(c[2]), "+f"(c[3])
        : "r"(a[0]), "r"(a[1]), "r"(a[2]), "r"(a[3]), "r"(b0), "r"(b1));
}

// ---- packed f32x2 helpers (attn) ----
__device__ __forceinline__ void ffma2(ull& d, ull a, ull b) {
    asm("fma.rn.f32x2 %0, %1, %2, %0;" : "+l"(d) : "l"(a), "l"(b));
}
__device__ __forceinline__ ull pack2(float x, float y) {
    ull r; asm("mov.b64 %0, {%1, %2};" : "=l"(r) : "f"(x), "f"(y)); return r;
}
__device__ __forceinline__ void unpack2(ull v, float& lo, float& hi) {
    asm("mov.b64 {%0, %1}, %2;" : "=f"(lo), "=f"(hi) : "l"(v));
}
__device__ __forceinline__ uint pack_split_h(float v) {
    __half h = __float2half_rn(v);
    float hv = __half2float(h);
    __half l = __float2half_rn(v - hv);
    return (uint)__half_as_ushort(h) | ((uint)__half_as_ushort(l) << 16);
}

// ---------------------------------------------------------------------------
__global__ void weight_half(const float* __restrict__ in, ushort* __restrict__ out, int n) {
    int i = blockIdx.x * 256 + threadIdx.x;
    if (i < n) out[i] = __half_as_ushort(__float2half_rn(in[i]));
}
__global__ void weight_split_off(const float* __restrict__ in, uint* __restrict__ out,
                                 int cols, int istr, int koff, int ostr) {
    int i = blockIdx.x * 256 + threadIdx.x;
    int m = i / cols, k = i - m * cols;
    out[(size_t)m * ostr + k] = pack_split_h(in[(size_t)m * istr + koff + k]);
}
__global__ void weight_half_off(const float* __restrict__ in, ushort* __restrict__ out,
                                int cols, int istr, int koff, int ostr) {
    int i = blockIdx.x * 256 + threadIdx.x;
    int m = i / cols, k = i - m * cols;
    out[(size_t)m * ostr + k] = __half_as_ushort(__float2half_rn(in[(size_t)m * istr + koff + k]));
}

// fp32 [B, C, N] -> fp16 [B, N, C]
__global__ void transpose_half(const float* __restrict__ in, ushort* __restrict__ out,
                               int C, int Nw) {
    __shared__ float tile[32][33];
    const int b = blockIdx.z;
    const int n0 = blockIdx.x * 32, c0 = blockIdx.y * 32;
    const int tx = threadIdx.x, ty = threadIdx.y;
    const float* inb = in + ((size_t)b * C + c0) * Nw + n0;
#pragma unroll
    for (int i = 0; i < 32; i += 8)
        tile[ty + i][tx] = inb[(size_t)(ty + i) * Nw + tx];
    __syncthreads();
    ushort* ob = out + ((size_t)b * Nw + n0) * C + c0;
#pragma unroll
    for (int i = 0; i < 32; i += 8)
        ob[(size_t)(ty + i) * C + tx] = __half_as_ushort(__float2half_rn(tile[tx][ty + i]));
}

// Permuted merge transpose: out[p][j] = fp16(merge_w[j][c(p)]),
// p = h*64+dh  <->  c = dh*16+h   (i.e. out row for in-column r is (r%16)*64 + r/16)
__global__ void transpose_perm(const float* __restrict__ in, ushort* __restrict__ out) {
    __shared__ float tile[32][33];
    const int n0 = blockIdx.x * 32, c0 = blockIdx.y * 32;  // n = in-col, c = in-row (j)
    const int tx = threadIdx.x, ty = threadIdx.y;
    const float* inb = in + (size_t)(c0) * DD + n0;
#pragma unroll
    for (int i = 0; i < 32; i += 8)
        tile[ty + i][tx] = inb[(size_t)(ty + i) * DD + tx];
    __syncthreads();
#pragma unroll
    for (int i = 0; i < 32; i += 8) {
        const int r = n0 + ty + i;                 // in-column index (msg channel c)
        const int p = (r & 15) * 64 + (r >> 4);    // permuted row
        out[(size_t)p * DD + c0 + tx] =
            __half_as_ushort(__float2half_rn(tile[tx][ty + i]));
    }
}

// colsum of proj (coalesced, 32 CTAs)
__global__ void colsum_kernel(const float* __restrict__ proj, float* __restrict__ S) {
    const int c = threadIdx.x;
    const float* p = proj + (size_t)blockIdx.x * 128 * KK + c;
    float s = 0.f;
#pragma unroll 8
    for (int m = 0; m < 128; m++) s += p[(size_t)m * KK];
    atomicAdd(&S[c], s);
}

// kp init: kp[b,d,c] = bk[d] * S[c]
__global__ void kp_init(const float* __restrict__ bk, const float* __restrict__ S,
                        float* __restrict__ kp) {
    int i = blockIdx.x * 256 + threadIdx.x;
    int c = i & (KK - 1);
    int d = (i >> 7) & (DD - 1);
    kp[i] = bk[d] * S[c];
}

// b1f[m] = b1[m] + dot(W1[m, 1024:2048], bm)
__global__ void bias_fold(const float* __restrict__ w1, const float* __restrict__ bm,
                          const float* __restrict__ b1, float* __restrict__ out) {
    const int m = blockIdx.x * 8 + (threadIdx.x >> 5);
    const int lane = threadIdx.x & 31;
    float s = 0.f;
#pragma unroll 4
    for (int c = lane; c < DD; c += 32)
        s += w1[(size_t)m * (2 * DD) + DD + c] * bm[c];
#pragma unroll
    for (int o = 16; o; o >>= 1) s += __shfl_xor_sync(0xFFFFFFFFu, s, o);
    if (lane == 0) out[m] = b1[m] + s;
}

// ---------------------------------------------------------------------------
// Warp-level HMMA GEMM (PLANES=1 fp16 A / PLANES=2 packed split A).
// MODE 0: fp32 out (+bias); MODE 2: +bias/BN/ReLU fp16-transpose out;
// MODE 3: plain-fp16 out (weight precompute).
// ---------------------------------------------------------------------------
#define STG_S 136

template <int MODE, int PLANES>
__global__ void __launch_bounds__(256, 3 - PLANES) hmma_gemm(
    const void* __restrict__ Aptr,
    const ushort* __restrict__ B1,
    const ushort* __restrict__ B2,
    const float* __restrict__ bias,
    const float* __restrict__ gamma,
    const float* __restrict__ beta,
    const float* __restrict__ mean,
    const float* __restrict__ var,
    float* __restrict__ outF,
    ushort* __restrict__ outT,
    int M, int Kd, int Nw, int K1, int ostr)
{
    constexpr uint32_t PLA_LO = 18432;
    constexpr uint32_t PLB    = (PLANES == 2) ? 36864u : 18432u;
    constexpr uint32_t SMBUF  = (PLANES == 2) ? 55296u : 36864u;

    extern __shared__ char smem[];
    const uint32_t sb = smem_to_u32(smem);

    const int tid  = threadIdx.x;
    const int wid  = tid >> 5;
    const int lane = tid & 31;
    const int m0 = blockIdx.y * 128;
    const int n0 = blockIdx.x * 128;
    const int bb = blockIdx.z;

    const int wm = wid & 3;
    const int wn = wid >> 2;
    const int K2 = Kd - K1;
    const int fr = lane >> 2;
    const int fc = (lane & 3) * 2;

    float c[2][8][4];
#pragma unroll
    for (int mt = 0; mt < 2; mt++)
#pragma unroll
        for (int nt = 0; nt < 8; nt++)
#pragma unroll
            for (int j = 0; j < 4; j++) c[mt][nt][j] = 0.f;

    const int nc = Kd >> 6;
    uint4 pa[PLANES == 2 ? 8 : 4], pb[4];

    auto ldg_tile = [&](int ch) {
        const int k0 = ch * 64;
        if (PLANES == 2) {
            const uint* Ab = (const uint*)Aptr + (size_t)m0 * Kd;
#pragma unroll
            for (int it = 0; it < 8; it++) {
                const int idx = it * 256 + tid;
                const int row = idx >> 4, q4 = idx & 15;
                pa[it] = *(const uint4*)(Ab + (size_t)row * Kd + k0 + q4 * 4);
            }
        } else {
            const ushort* Ab = (const ushort*)Aptr + (size_t)m0 * Kd;
#pragma unroll
            for (int it = 0; it < 4; it++) {
                const int idx = it * 256 + tid;
                const int row = idx >> 3, q4 = idx & 7;
                pa[it] = *(const uint4*)(Ab + (size_t)row * Kd + k0 + q4 * 8);
            }
        }
        const ushort* Bsrc; int kloc, kstride;
        if (k0 < K1) { Bsrc = B1; kloc = k0;      kstride = K1; }
        else         { Bsrc = B2; kloc = k0 - K1; kstride = K2; }
        const ushort* Bb = Bsrc + ((size_t)bb * Nw + n0) * kstride + kloc;
#pragma unroll
        for (int it = 0; it < 4; it++) {
            const int idx = it * 256 + tid;
            const int row = idx >> 3, q4 = idx & 7;
            pb[it] = *(const uint4*)(Bb + (size_t)row * kstride + q4 * 8);
        }
    };
    auto sts_tile = [&](int buf) {
        const uint32_t base = sb + buf * SMBUF;
        if (PLANES == 2) {
#pragma unroll
            for (int it = 0; it < 8; it++) {
                const int idx = it * 256 + tid;
                const int row = idx >> 4, q4 = idx & 15;
                const uint32_t off = (uint32_t)row * 144 + q4 * 8;
                uint4 v = pa[it];
                sts_v2(base + off, prmt(v.x, v.y, 0x5410), prmt(v.z, v.w, 0x5410));
                sts_v2(base + PLA_LO + off, prmt(v.x, v.y, 0x7632), prmt(v.z, v.w, 0x7632));
            }
        } else {
#pragma unroll
            for (int it = 0; it < 4; it++) {
                const int idx = it * 256 + tid;
                const int row = idx >> 3, q4 = idx & 7;
                sts_v4(base + (uint32_t)row * 144 + q4 * 16, pa[it]);
            }
        }
#pragma unroll
        for (int it = 0; it < 4; it++) {
            const int idx = it * 256 + tid;
            const int row = idx >> 3, q4 = idx & 7;
            sts_v4(base + PLB + (uint32_t)row * 144 + q4 * 16, pb[it]);
        }
    };

    ldg_tile(0);
    sts_tile(0);
    __syncthreads();

    const uint32_t aOff = (uint32_t)(wm * 32 + (lane & 15)) * 144 + ((lane >> 4) & 1) * 16;
    const uint32_t bOff = (uint32_t)(wn * 64 + (lane & 7) + ((lane & 16) ? 8 : 0)) * 144
                        + ((lane & 8) ? 16 : 0);

    for (int ch = 0; ch < nc; ch++) {
        const uint32_t base = sb + (ch & 1) * SMBUF;
        if (ch + 1 < nc) ldg_tile(ch + 1);
#pragma unroll
        for (int ksb = 0; ksb < 128; ksb += 32) {
            uint ah[2][4], al[2][4];
            ldsm4(ah[0], base + aOff + ksb);
            ldsm4(ah[1], base + aOff + 2304 + ksb);
            if (PLANES == 2) {
                ldsm4(al[0], base + PLA_LO + aOff + ksb);
                ldsm4(al[1], base + PLA_LO + aOff + 2304 + ksb);
            }
            uint bh[4][4];
#pragma unroll
            for (int np = 0; np < 4; np++)
                ldsm4(bh[np], base + PLB + bOff + np * 2304 + ksb);
#pragma unroll
            for (int np = 0; np < 4; np++)
#pragma unroll
                for (int sub = 0; sub < 2; sub++) {
                    const int nt = np * 2 + sub;
                    const uint b0 = bh[np][sub * 2], b1 = bh[np][sub * 2 + 1];
#pragma unroll
                    for (int mt = 0; mt < 2; mt++) {
                        mma16816(c[mt][nt], ah[mt], b0, b1);
                        if (PLANES == 2) mma16816(c[mt][nt], al[mt], b0, b1);
                    }
                }
        }
        if (ch + 1 < nc) {
            sts_tile((ch + 1) & 1);
            __syncthreads();
        }
    }

    // ---- epilogue ----
    if (MODE == 0) {
        const int cm = m0 + wm * 32 + fr;
        const int cn = n0 + wn * 64 + fc;
#pragma unroll
        for (int mt = 0; mt < 2; mt++) {
            const int mlo = cm + mt * 16;
            const int mhi = mlo + 8;
            const float bi0 = bias[mlo], bi1 = bias[mhi];
#pragma unroll
            for (int nt = 0; nt < 8; nt++) {
                const int n = cn + nt * 8;
                *(float2*)(outF + ((size_t)bb * M + mlo) * ostr + n) =
                    make_float2(c[mt][nt][0] + bi0, c[mt][nt][1] + bi0);
                *(float2*)(outF + ((size_t)bb * M + mhi) * ostr + n) =
                    make_float2(c[mt][nt][2] + bi1, c[mt][nt][3] + bi1);
            }
        }
    } else if (MODE == 3) {
        ushort* ob = outT;
        const int cm = m0 + wm * 32 + fr;
        const int cn = n0 + wn * 64 + fc;
#pragma unroll
        for (int mt = 0; mt < 2; mt++) {
            const int mlo = cm + mt * 16;
            const int mhi = mlo + 8;
#pragma unroll
            for (int nt = 0; nt < 8; nt++) {
                const int n = cn + nt * 8;
                ob[(size_t)mlo * ostr + n]     = __half_as_ushort(__float2half_rn(c[mt][nt][0]));
                ob[(size_t)mlo * ostr + n + 1] = __half_as_ushort(__float2half_rn(c[mt][nt][1]));
                ob[(size_t)mhi * ostr + n]     = __half_as_ushort(__float2half_rn(c[mt][nt][2]));
                ob[(size_t)mhi * ostr + n + 1] = __half_as_ushort(__float2half_rn(c[mt][nt][3]));
            }
        }
    } else {  // MODE 2
        float* stg = (float*)smem;
        uint* ob = (uint*)(outT + (size_t)bb * Nw * M);
#pragma unroll
        for (int p = 0; p < 2; p++) {
            __syncthreads();
            if (wn == p) {
#pragma unroll
                for (int mt = 0; mt < 2; mt++) {
                    const int mloL = wm * 32 + mt * 16 + fr;
                    const int mhiL = mloL + 8;
                    const int mlo = m0 + mloL, mhi = m0 + mhiL;
                    float sc0 = gamma[mlo] * rsqrtf(var[mlo] + 1e-3f);
                    float sh0 = beta[mlo] + (bias[mlo] - mean[mlo]) * sc0;
                    float sc1 = gamma[mhi] * rsqrtf(var[mhi] + 1e-3f);
                    float sh1 = beta[mhi] + (bias[mhi] - mean[mhi]) * sc1;
#pragma unroll
                    for (int nt = 0; nt < 8; nt++) {
                        const int nl = fc + nt * 8;
                        stg[(nl)     * STG_S + mloL] = fmaxf(fmaf(c[mt][nt][0], sc0, sh0), 0.f);
                        stg[(nl + 1) * STG_S + mloL] = fmaxf(fmaf(c[mt][nt][1], sc0, sh0), 0.f);
                        stg[(nl)     * STG_S + mhiL] = fmaxf(fmaf(c[mt][nt][2], sc1, sh1), 0.f);
                        stg[(nl + 1) * STG_S + mhiL] = fmaxf(fmaf(c[mt][nt][3], sc1, sh1), 0.f);
                    }
                }
            }
            __syncthreads();
            const int nb = n0 + p * 64;
#pragma unroll 4
            for (int i = 0; i < 16; i++) {
                const int idx = i * 256 + tid;
                const int nn = idx >> 6;
                const int mp = idx & 63;
                const float* s = stg + nn * STG_S + mp * 2;
                const uint u = (uint)__half_as_ushort(__float2half_rn(s[0]))
                             | ((uint)__half_as_ushort(__float2half_rn(s[1])) << 16);
                ob[(size_t)(nb + nn) * (M >> 1) + (m0 >> 1) + mp] = u;
            }
        }
    }
}

// ---------------------------------------------------------------------------
// Split-K fp16 HMMA: C[r,c] += srch[r, :] . projT[c, :]
// A = srch [B*D=4096, 4096] fp16, B = projT [128, 4096] fp16,
// C = srcp [4096, 128] fp32 (pre-zeroed, atomicAdd).
// grid (kslices=8, mtiles=32); each slice reduces 512 k.
// ---------------------------------------------------------------------------
__global__ void __launch_bounds__(256, 2) hmma_splitk(
    const ushort* __restrict__ A,
    const ushort* __restrict__ Bp,
    float* __restrict__ C)
{
    constexpr uint32_t PLB = 18432;
    constexpr uint32_t SMBUF = 36864;
    extern __shared__ char smem[];
    const uint32_t sb = smem_to_u32(smem);

    const int tid  = threadIdx.x;
    const int wid  = tid >> 5;
    const int lane = tid & 31;
    const int m0 = blockIdx.y * 128;
    const int kbase = blockIdx.x * 512;
    const int Kd = NN;

    const int wm = wid & 3;
    const int wn = wid >> 2;
    const int fr = lane >> 2;
    const int fc = (lane & 3) * 2;

    float c[2][8][4];
#pragma unroll
    for (int mt = 0; mt < 2; mt++)
#pragma unroll
        for (int nt = 0; nt < 8; nt++)
#pragma unroll
            for (int j = 0; j < 4; j++) c[mt][nt][j] = 0.f;

    uint4 pa[4], pb[4];
    auto ldg_tile = [&](int ch) {
        const int k0 = kbase + ch * 64;
        const ushort* Ab = A + (size_t)m0 * Kd;
#pragma unroll
        for (int it = 0; it < 4; it++) {
            const int idx = it * 256 + tid;
            const int row = idx >> 3, q4 = idx & 7;
            pa[it] = *(const uint4*)(Ab + (size_t)row * Kd + k0 + q4 * 8);
        }
#pragma unroll
        for (int it = 0; it < 4; it++) {
            const int idx = it * 256 + tid;
            const int row = idx >> 3, q4 = idx & 7;
            pb[it] = *(const uint4*)(Bp + (size_t)row * Kd + k0 + q4 * 8);
        }
    };
    auto sts_tile = [&](int buf) {
        const uint32_t base = sb + buf * SMBUF;
#pragma unroll
        for (int it = 0; it < 4; it++) {
            const int idx = it * 256 + tid;
            const int row = idx >> 3, q4 = idx & 7;
            sts_v4(base + (uint32_t)row * 144 + q4 * 16, pa[it]);
            sts_v4(base + PLB + (uint32_t)row * 144 + q4 * 16, pb[it]);
        }
    };

    ldg_tile(0);
    sts_tile(0);
    __syncthreads();

    const uint32_t aOff = (uint32_t)(wm * 32 + (lane & 15)) * 144 + ((lane >> 4) & 1) * 16;
    const uint32_t bOff = (uint32_t)(wn * 64 + (lane & 7) + ((lane & 16) ? 8 : 0)) * 144
                        + ((lane & 8) ? 16 : 0);

    for (int ch = 0; ch < 8; ch++) {
        const uint32_t base = sb + (ch & 1) * SMBUF;
        if (ch + 1 < 8) ldg_tile(ch + 1);
#pragma unroll
        for (int ksb = 0; ksb < 128; ksb += 32) {
            uint ah[2][4];
            ldsm4(ah[0], base + aOff + ksb);
            ldsm4(ah[1], base + aOff + 2304 + ksb);
            uint bh[4][4];
#pragma unroll
            for (int np = 0; np < 4; np++)
                ldsm4(bh[np], base + PLB + bOff + np * 2304 + ksb);
#pragma unroll
            for (int np = 0; np < 4; np++)
#pragma unroll
                for (int sub = 0; sub < 2; sub++) {
                    const int nt = np * 2 + sub;
#pragma unroll
                    for (int mt = 0; mt < 2; mt++)
                        mma16816(c[mt][nt], ah[mt], bh[np][sub * 2], bh[np][sub * 2 + 1]);
                }
        }
        if (ch + 1 < 8) {
            sts_tile((ch + 1) & 1);
            __syncthreads();
        }
    }

    const int cm = m0 + wm * 32 + fr;
    const int cn = wn * 64 + fc;
#pragma unroll
    for (int mt = 0; mt < 2; mt++) {
        const int mlo = cm + mt * 16;
        const int mhi = mlo + 8;
#pragma unroll
        for (int nt = 0; nt < 8; nt++) {
            const int n = cn + nt * 8;
            atomicAdd(&C[(size_t)mlo * KK + n],     c[mt][nt][0]);
            atomicAdd(&C[(size_t)mlo * KK + n + 1], c[mt][nt][1]);
            atomicAdd(&C[(size_t)mhi * KK + n],     c[mt][nt][2]);
            atomicAdd(&C[(size_t)mhi * KK + n + 1], c[mt][nt][3]);
        }
    }
}

// ---------------------------------------------------------------------------
// kp = Wk @ srcp (per batch), accumulated onto kp_init values. (fp32, small)
// ---------------------------------------------------------------------------
__global__ void __launch_bounds__(256) kp_gemm(
    const float* __restrict__ W, const float* __restrict__ P, float* __restrict__ C)
{
    __shared__ float As[8][128];
    __shared__ float Bs[8][128];

    const int t  = threadIdx.x;
    const int ty = t >> 4;
    const int tx = t & 15;
    const int r0 = blockIdx.x * 128;
    const int chunk = DD / gridDim.y;
    const int c0 = blockIdx.y * chunk;
    const int b = blockIdx.z;

    const float* Pb = P + (size_t)b * DD * KK;
    float* Cb = C + (size_t)b * DD * KK;

    const int ar = t >> 1, ac = (t & 1) * 4;
    const int br = t >> 5, bc = (t & 31) * 4;

    float acc[8][8];
#pragma unroll
    for (int i = 0; i < 8; i++)
#pragma unroll
        for (int j = 0; j < 8; j++) acc[i][j] = 0.f;

    for (int kt = 0; kt < chunk; kt += 8) {
        const int kb = c0 + kt;
        float4 av = *(const float4*)(W + (size_t)(r0 + ar) * DD + kb + ac);
        As[ac + 0][ar] = av.x;
        As[ac + 1][ar] = av.y;
        As[ac + 2][ar] = av.z;
        As[ac + 3][ar] = av.w;
        *(float4*)&Bs[br][bc] = *(const float4*)(Pb + (size_t)(kb + br) * KK + bc);
        __syncthreads();
#pragma unroll
        for (int kk = 0; kk < 8; kk++) {
            float a[8], bv[8];
#pragma unroll
            for (int i = 0; i < 8; i++) a[i] = As[kk][ty * 8 + i];
#pragma unroll
            for (int j = 0; j < 8; j++) bv[j] = Bs[kk][tx * 8 + j];
#pragma unroll
            for (int i = 0; i < 8; i++)
#pragma unroll
                for (int j = 0; j < 8; j++)
                    acc[i][j] = fmaf(a[i], bv[j], acc[i][j]);
        }
        __syncthreads();
    }

#pragma unroll
    for (int i = 0; i < 8; i++)
#pragma unroll
        for (int j = 0; j < 8; j++)
            atomicAdd(&Cb[(size_t)(r0 + ty * 8 + i) * KK + tx * 8 + j], acc[i][j]);
}

// ---------------------------------------------------------------------------
// Fused Linformer attention: fp16 score cache + direct fp16 head-major output.
// Output: msgs[b][n][p], p = h*64 + dh (contiguous per CTA).
// smem: KsT 33792 B + Es 32768 B = 66560 B (staging reuses Es).
// ---------------------------------------------------------------------------
#define KST_STRIDE 66
#define ES_S 128
#define ATTN_SMEM (KK * KST_STRIDE * 4 + KK * ES_S * 2)

__global__ void __launch_bounds__(128, 2) attn_kernel(
    const float* __restrict__ q,
    const float* __restrict__ kp,
    ushort* __restrict__ msgs)
{
    extern __shared__ float dsm[];
    float* KsT = dsm;                                   // [128 k][66 dh]
    ushort* Es = (ushort*)(dsm + KK * KST_STRIDE);      // [128 k][128 n] / staging

    const int tid = threadIdx.x;
    const int n0 = blockIdx.x * 128;
    const int n = n0 + tid;
    const int h = blockIdx.y;
    const int b = blockIdx.z;

#pragma unroll 4
    for (int dh = 0; dh < DHH; dh++)
        KsT[tid * KST_STRIDE + dh] = kp[((size_t)b * DD + (size_t)dh * HH + h) * KK + tid];
    __syncthreads();

    const float* qb = q + ((size_t)b * DD + h) * NN + n;
    ull qv2[DHH / 2];
#pragma unroll
    for (int dhp = 0; dhp < DHH / 2; dhp++) {
        float x = qb[(size_t)(2 * dhp) * HH * NN];
        float y = qb[(size_t)(2 * dhp + 1) * HH * NN];
        qv2[dhp] = pack2(x, y);
    }

    // pass 1: scores once, cache fp16, track raw max
    float mraw = -1e30f;
#pragma unroll 2
    for (int k = 0; k < KK; k++) {
        ull s2 = 0ULL;
        const float* krow = KsT + k * KST_STRIDE;
#pragma unroll
        for (int dhp = 0; dhp < DHH / 2; dhp++)
            ffma2(s2, qv2[dhp], *(const ull*)(krow + 2 * dhp));
        float lo, hi;
        unpack2(s2, lo, hi);
        const float sraw = lo + hi;
        Es[k * ES_S + tid] = __half_as_ushort(__float2half_rn(sraw));
        mraw = fmaxf(mraw, sraw);
    }
    const float mx = mraw * 0.125f;

    // pass 2: exp from cache, accumulate msg
    float sum = 0.f;
    ull acc2[DHH / 2];
#pragma unroll
    for (int dhp = 0; dhp < DHH / 2; dhp++) acc2[dhp] = 0ULL;

#pragma unroll 2
    for (int k = 0; k < KK; k++) {
        const float sraw = __half2float(__ushort_as_half(Es[k * ES_S + tid]));
        const float e = __expf(fmaf(sraw, 0.125f, -mx));
        sum += e;
        const ull e2 = pack2(e, e);
        const float* krow = KsT + k * KST_STRIDE;
#pragma unroll
        for (int dhp = 0; dhp < DHH / 2; dhp++)
            ffma2(acc2[dhp], e2, *(const ull*)(krow + 2 * dhp));
    }
    const float inv = 1.f / sum;

    // stage [128 n][66 dh] fp16 (reuse Es region), then coalesced write
    __syncthreads();   // all pass-2 Es reads complete before overwrite
    uint* Stg = (uint*)Es;   // row stride 33 uints
#pragma unroll
    for (int dhp = 0; dhp < DHH / 2; dhp++) {
        float lo, hi;
        unpack2(acc2[dhp], lo, hi);
        const uint u = (uint)__half_as_ushort(__float2half_rn(lo * inv))
                     | ((uint)__half_as_ushort(__float2half_rn(hi * inv)) << 16);
        Stg[tid * 33 + dhp] = u;
    }
    __syncthreads();

    uint* ob = (uint*)(msgs + ((size_t)b * NN + n0) * DD + (size_t)h * DHH);
#pragma unroll 4
    for (int i = 0; i < 32; i++) {
        const int idx = i * 128 + tid;
        const int nn = idx >> 5;
        const int dq = idx & 31;
        ob[(size_t)nn * (DD / 2) + dq] = Stg[nn * 33 + dq];
    }
}

// ---------------------------------------------------------------------------
extern "C" void kernel_launch(void* const* d_in, const int* in_sizes, int n_in,
                              void* d_out, int out_size)
{
    const float* x       = (const float*)d_in[0];
    const float* source  = (const float*)d_in[1];
    const float* to_q_w  = (const float*)d_in[2];
    const float* to_q_b  = (const float*)d_in[3];
    const float* to_k_w  = (const float*)d_in[4];
    const float* to_k_b  = (const float*)d_in[5];
    const float* proj_k  = (const float*)d_in[6];
    const float* merge_w = (const float*)d_in[7];
    const float* merge_b = (const float*)d_in[8];
    const float* mlp_w1  = (const float*)d_in[9];
    const float* mlp_b1  = (const float*)d_in[10];
    const float* bn_g    = (const float*)d_in[11];
    const float* bn_b    = (const float*)d_in[12];
    const float* bn_m    = (const float*)d_in[13];
    const float* bn_v    = (const float*)d_in[14];
    const float* mlp_w2  = (const float*)d_in[15];
    const float* mlp_b2  = (const float*)d_in[16];
    float* out = (float*)d_out;

    float *q, *kp, *srcp, *scol, *b1f;
    uint *ws1b;
    ushort *wqh, *ws1fh, *ws2h, *wmTp, *xs, *msgs, *hs, *srch, *projT;
    cudaGetSymbolAddress((void**)&q,    g_q);
    cudaGetSymbolAddress((void**)&kp,   g_kp);
    cudaGetSymbolAddress((void**)&srcp, g_srcp);
    cudaGetSymbolAddress((void**)&scol, g_scol);
    cudaGetSymbolAddress((void**)&b1f,  g_b1f);
    cudaGetSymbolAddress((void**)&wqh,  g_wq_h);
    cudaGetSymbolAddress((void**)&ws1fh,g_ws1f_h);
    cudaGetSymbolAddress((void**)&ws2h, g_ws2_h);
    cudaGetSymbolAddress((void**)&ws1b, g_ws_1b);
    cudaGetSymbolAddress((void**)&wmTp, g_wmTp);
    cudaGetSymbolAddress((void**)&xs,   g_xs);
    cudaGetSymbolAddress((void**)&msgs, g_msgs);
    cudaGetSymbolAddress((void**)&hs,   g_hs);
    cudaGetSymbolAddress((void**)&srch, g_srch);
    cudaGetSymbolAddress((void**)&projT,g_projT);

    const int SM2 = 2 * 55296;
    const int SM1 = 2 * 36864;
    cudaFuncSetAttribute(hmma_gemm<0, 1>, cudaFuncAttributeMaxDynamicSharedMemorySize, SM1);
    cudaFuncSetAttribute(hmma_gemm<2, 1>, cudaFuncAttributeMaxDynamicSharedMemorySize, SM1);
    cudaFuncSetAttribute(hmma_gemm<3, 2>, cudaFuncAttributeMaxDynamicSharedMemorySize, SM2);
    cudaFuncSetAttribute(hmma_splitk, cudaFuncAttributeMaxDynamicSharedMemorySize, SM1);
    cudaFuncSetAttribute(attn_kernel, cudaFuncAttributeMaxDynamicSharedMemorySize, ATTN_SMEM);

    // 0) weight prep
    weight_half<<<(DD * DD + 255) / 256, 256>>>(to_q_w, wqh, DD * DD);
    weight_half<<<(2 * DD * DD + 255) / 256, 256>>>(mlp_w2, ws2h, 2 * DD * DD);
    weight_half_off<<<(2 * DD * DD) / 256, 256>>>(mlp_w1, ws1fh, DD, 2 * DD, 0, 2 * DD);
    weight_split_off<<<(2 * DD * DD) / 256, 256>>>(mlp_w1, ws1b, DD, 2 * DD, DD, DD);
    // permuted merge^T (rows in head-major order)
    transpose_perm<<<dim3(DD / 32, DD / 32), dim3(32, 8)>>>(merge_w, wmTp);
    // W1c' = W1b @ Wm (columns permuted) -> ws1fh[m][1024:2048]
    hmma_gemm<3, 2><<<dim3(DD / 128, (2 * DD) / 128, 1), 256, SM2>>>(
        ws1b, wmTp, wmTp, nullptr, nullptr, nullptr, nullptr, nullptr,
        nullptr, ws1fh + DD, 2 * DD, DD, DD, DD, 2 * DD);
    bias_fold<<<(2 * DD) / 8, 256>>>(mlp_w1, merge_b, mlp_b1, b1f);

    // x transpose, source fp16 convert, proj transpose
    transpose_half<<<dim3(NN / 32, DD / 32, BB), dim3(32, 8)>>>(x, xs, DD, NN);
    weight_half<<<(int)(((size_t)BB * DD * NN + 255) / 256), 256>>>(source, srch,
                                                                    BB * DD * NN);
    transpose_half<<<dim3(KK / 32, NN / 32, 1), dim3(32, 8)>>>(proj_k, projT, NN, KK);

    // 1) Linformer fold: kp = Wk @ (src @ proj) + bk * colsum(proj)
    cudaMemsetAsync(scol, 0, sizeof(float) * KK);
    colsum_kernel<<<NN / 128, KK>>>(proj_k, scol);
    cudaMemsetAsync(srcp, 0, sizeof(float) * (size_t)BB * DD * KK);
    hmma_splitk<<<dim3(8, (BB * DD) / 128), 256, SM1>>>(srch, projT, srcp);
    kp_init<<<(BB * DD * KK) / 256, 256>>>(to_k_b, scol, kp);
    kp_gemm<<<dim3(DD / 128, 4, BB), 256>>>(to_k_w, srcp, kp);

    // 2) q = Wq @ x + bq  (fp32 out)
    hmma_gemm<0, 1><<<dim3(NN / 128, DD / 128, BB), 256, SM1>>>(
        wqh, xs, xs, to_q_b, nullptr, nullptr, nullptr, nullptr,
        q, nullptr, DD, DD, NN, DD, NN);

    // 3) fused attention -> msgs fp16 head-major (direct)
    attn_kernel<<<dim3(NN / 128, HH, BB), dim3(128), ATTN_SMEM>>>(q, kp, msgs);

    // 4) h = relu(BN([W1a | W1c'] @ concat(x, msg) + b1'))
    hmma_gemm<2, 1><<<dim3(NN / 128, (2 * DD) / 128, BB), 256, SM1>>>(
        ws1fh, xs, msgs, b1f, bn_g, bn_b, bn_m, bn_v,
        nullptr, hs, 2 * DD, 2 * DD, NN, DD, 0);

    // 5) out = W2 @ h + b2  (fp32 out)
    hmma_gemm<0, 1><<<dim3(NN / 128, DD / 128, BB), 256, SM1>>>(
        ws2h, hs, hs, mlp_b2, nullptr, nullptr, nullptr, nullptr,
        out, nullptr, DD, 2 * DD, NN, 2 * DD, NN);
}

// round 11
// speedup vs baseline: 7.3322x; 1.0381x over previous
#include <cuda_runtime.h>
#include <cuda_fp16.h>
#include <math.h>
#include <stdint.h>

// Problem constants
#define BB 4
#define DD 1024
#define NN 4096
#define HH 16
#define KK 128
#define DHH 64

typedef unsigned long long ull;
typedef unsigned int uint;
typedef unsigned short ushort;

// ---------------- scratch (device globals) ----------------
__device__ float g_kp  [(size_t)BB * DD * KK];
__device__ float g_srcp[(size_t)BB * DD * KK];
__device__ float g_scol[KK];
__device__ float g_b1f [2 * DD];
__device__ float g_bqp [DD];                              // permuted q bias

// single-plane fp16 weights
__device__ ushort g_wqp_h [(size_t)DD * DD];              // Wq rows permuted
__device__ ushort g_ws1f_h[(size_t)(2 * DD) * (2 * DD)];  // [W1a | W1c-perm]
__device__ ushort g_ws2_h [(size_t)DD * (2 * DD)];
__device__ ushort g_w1b_h [(size_t)(2 * DD) * DD];        // W1b fp16 (precompute)
__device__ ushort g_wmTp  [(size_t)DD * DD];              // perm-row merge^T fp16
// fp16 activations / operands
__device__ ushort g_xs   [(size_t)BB * NN * DD];
__device__ ushort g_qs   [(size_t)BB * NN * DD];          // q fp16 head-major
__device__ ushort g_msgs [(size_t)BB * NN * DD];
__device__ ushort g_hs   [(size_t)BB * NN * 2 * DD];
__device__ ushort g_srch [(size_t)BB * DD * NN];
__device__ ushort g_projT[(size_t)KK * NN];

// ---------------- helpers ----------------
__device__ __forceinline__ uint32_t smem_to_u32(const void* p) {
    uint32_t a;
    asm("{ .reg .u64 t; cvta.to.shared.u64 t, %1; cvt.u32.u64 %0, t; }"
        : "=r"(a) : "l"(p));
    return a;
}
__device__ __forceinline__ void sts_v4(uint32_t addr, uint4 v) {
    asm volatile("st.shared.v4.b32 [%0], {%1, %2, %3, %4};"
                 :: "r"(addr), "r"(v.x), "r"(v.y), "r"(v.z), "r"(v.w));
}
__device__ __forceinline__ void ldsm4(uint* r, uint32_t addr) {
    asm volatile("ldmatrix.sync.aligned.m8n8.x4.shared.b16 {%0,%1,%2,%3}, [%4];"
        : "=r"(r[0]), "=r"(r[1]), "=r"(r[2]), "=r"(r[3]) : "r"(addr));
}

// HMMA m16n8k16 fp16 -> fp32
__device__ __forceinline__ void mma16816(float* c, const uint* a, uint b0, uint b1) {
    asm volatile(
        "mma.sync.aligned.m16n8k16.row.col.f32.f16.f16.f32 "
        "{%0,%1,%2,%3}, {%4,%5,%6,%7}, {%8,%9}, {%0,%1,%2,%3};"
        : "+f"(c[0]), "+f"(c[1]), "+f"(c[2]), "+f"(c[3])
        : "r"(a[0]), "r"(a[1]), "r"(a[2]), "r"(a[3]), "r"(b0), "r"(b1));
}

// ---- packed f32x2 helpers (attn) ----
__device__ __forceinline__ void ffma2(ull& d, ull a, ull b) {
    asm("fma.rn.f32x2 %0, %1, %2, %0;" : "+l"(d) : "l"(a), "l"(b));
}
__device__ __forceinline__ ull pack2(float x, float y) {
    ull r; asm("mov.b64 %0, {%1, %2};" : "=l"(r) : "f"(x), "f"(y)); return r;
}
__device__ __forceinline__ void unpack2(ull v, float& lo, float& hi) {
    asm("mov.b64 {%0, %1}, %2;" : "=f"(lo), "=f"(hi) : "l"(v));
}

// ---------------------------------------------------------------------------
__global__ void weight_half(const float* __restrict__ in, ushort* __restrict__ out, int n) {
    int i = blockIdx.x * 256 + threadIdx.x;
    if (i < n) out[i] = __half_as_ushort(__float2half_rn(in[i]));
}

// Wq rows permuted: out[p][k] = fp16(in[m][k]), p = (m%16)*64 + m/16
__global__ void weight_half_perm(const float* __restrict__ in, ushort* __restrict__ out) {
    int i = blockIdx.x * 256 + threadIdx.x;
    int m = i >> 10, k = i & 1023;
    int p = (m & 15) * 64 + (m >> 4);
    out[(size_t)p * DD + k] = __half_as_ushort(__float2half_rn(in[i]));
}

// permuted bias: out[p] = in[(p%64)*16 + p/64]
__global__ void bias_perm(const float* __restrict__ in, float* __restrict__ out) {
    int p = blockIdx.x * 256 + threadIdx.x;
    int d = (p & 63) * 16 + (p >> 6);
    out[p] = in[d];
}

// mlp_w1 combined prep: read once, write W1a half (stride 2DD) + W1b fp16 (stride DD)
__global__ void w1_prep(const float* __restrict__ w1,
                        ushort* __restrict__ w1a, ushort* __restrict__ w1b) {
    int i = blockIdx.x * 256 + threadIdx.x;   // over 2048*2048
    int m = i >> 11, k = i & 2047;
    ushort v = __half_as_ushort(__float2half_rn(w1[i]));
    if (k < DD) w1a[(size_t)m * (2 * DD) + k] = v;
    else        w1b[(size_t)m * DD + (k - DD)] = v;
}

// fp32 [B, C, N] -> fp16 [B, N, C]
__global__ void transpose_half(const float* __restrict__ in, ushort* __restrict__ out,
                               int C, int Nw) {
    __shared__ float tile[32][33];
    const int b = blockIdx.z;
    const int n0 = blockIdx.x * 32, c0 = blockIdx.y * 32;
    const int tx = threadIdx.x, ty = threadIdx.y;
    const float* inb = in + ((size_t)b * C + c0) * Nw + n0;
#pragma unroll
    for (int i = 0; i < 32; i += 8)
        tile[ty + i][tx] = inb[(size_t)(ty + i) * Nw + tx];
    __syncthreads();
    ushort* ob = out + ((size_t)b * Nw + n0) * C + c0;
#pragma unroll
    for (int i = 0; i < 32; i += 8)
        ob[(size_t)(ty + i) * C + tx] = __half_as_ushort(__float2half_rn(tile[tx][ty + i]));
}

// Permuted merge transpose: out[p][j] = fp16(merge_w[j][c]), p=(c%16)*64+c/16
__global__ void transpose_perm(const float* __restrict__ in, ushort* __restrict__ out) {
    __shared__ float tile[32][33];
    const int n0 = blockIdx.x * 32, c0 = blockIdx.y * 32;
    const int tx = threadIdx.x, ty = threadIdx.y;
    const float* inb = in + (size_t)(c0) * DD + n0;
#pragma unroll
    for (int i = 0; i < 32; i += 8)
        tile[ty + i][tx] = inb[(size_t)(ty + i) * DD + tx];
    __syncthreads();
#pragma unroll
    for (int i = 0; i < 32; i += 8) {
        const int r = n0 + ty + i;
        const int p = (r & 15) * 64 + (r >> 4);
        out[(size_t)p * DD + c0 + tx] =
            __half_as_ushort(__float2half_rn(tile[tx][ty + i]));
    }
}

// colsum of proj (coalesced, 32 CTAs)
__global__ void colsum_kernel(const float* __restrict__ proj, float* __restrict__ S) {
    const int c = threadIdx.x;
    const float* p = proj + (size_t)blockIdx.x * 128 * KK + c;
    float s = 0.f;
#pragma unroll 8
    for (int m = 0; m < 128; m++) s += p[(size_t)m * KK];
    atomicAdd(&S[c], s);
}

// kp init: kp[b,d,c] = bk[d] * S[c]
__global__ void kp_init(const float* __restrict__ bk, const float* __restrict__ S,
                        float* __restrict__ kp) {
    int i = blockIdx.x * 256 + threadIdx.x;
    int c = i & (KK - 1);
    int d = (i >> 7) & (DD - 1);
    kp[i] = bk[d] * S[c];
}

// b1f[m] = b1[m] + dot(W1[m, 1024:2048], bm)
__global__ void bias_fold(const float* __restrict__ w1, const float* __restrict__ bm,
                          const float* __restrict__ b1, float* __restrict__ out) {
    const int m = blockIdx.x * 8 + (threadIdx.x >> 5);
    const int lane = threadIdx.x & 31;
    float s = 0.f;
#pragma unroll 4
    for (int c = lane; c < DD; c += 32)
        s += w1[(size_t)m * (2 * DD) + DD + c] * bm[c];
#pragma unroll
    for (int o = 16; o; o >>= 1) s += __shfl_xor_sync(0xFFFFFFFFu, s, o);
    if (lane == 0) out[m] = b1[m] + s;
}

// ---------------------------------------------------------------------------
// Warp-level HMMA GEMM (single-plane fp16 A).
// MODE 0: fp32 out (+bias); MODE 1: +bias fp16-transpose out [B,Nw,M];
// MODE 2: +bias/BN/ReLU fp16-transpose out; MODE 3: plain-fp16 out [M,ostr].
// CTA 128x128, KC=64, double-buffered smem (row stride 144B), 2 CTAs/SM.
// ---------------------------------------------------------------------------
#define STG_S 136

template <int MODE>
__global__ void __launch_bounds__(256, 2) hmma_gemm(
    const ushort* __restrict__ Aptr,
    const ushort* __restrict__ B1,
    const ushort* __restrict__ B2,
    const float* __restrict__ bias,
    const float* __restrict__ gamma,
    const float* __restrict__ beta,
    const float* __restrict__ mean,
    const float* __restrict__ var,
    float* __restrict__ outF,
    ushort* __restrict__ outT,
    int M, int Kd, int Nw, int K1, int ostr)
{
    constexpr uint32_t PLB   = 18432u;
    constexpr uint32_t SMBUF = 36864u;

    extern __shared__ char smem[];
    const uint32_t sb = smem_to_u32(smem);

    const int tid  = threadIdx.x;
    const int wid  = tid >> 5;
    const int lane = tid & 31;
    const int m0 = blockIdx.y * 128;
    const int n0 = blockIdx.x * 128;
    const int bb = blockIdx.z;

    const int wm = wid & 3;
    const int wn = wid >> 2;
    const int K2 = Kd - K1;
    const int fr = lane >> 2;
    const int fc = (lane & 3) * 2;

    float c[2][8][4];
#pragma unroll
    for (int mt = 0; mt < 2; mt++)
#pragma unroll
        for (int nt = 0; nt < 8; nt++)
#pragma unroll
            for (int j = 0; j < 4; j++) c[mt][nt][j] = 0.f;

    const int nc = Kd >> 6;
    uint4 pa[4], pb[4];

    auto ldg_tile = [&](int ch) {
        const int k0 = ch * 64;
        const ushort* Ab = Aptr + (size_t)m0 * Kd;
#pragma unroll
        for (int it = 0; it < 4; it++) {
            const int idx = it * 256 + tid;
            const int row = idx >> 3, q4 = idx & 7;
            pa[it] = *(const uint4*)(Ab + (size_t)row * Kd + k0 + q4 * 8);
        }
        const ushort* Bsrc; int kloc, kstride;
        if (k0 < K1) { Bsrc = B1; kloc = k0;      kstride = K1; }
        else         { Bsrc = B2; kloc = k0 - K1; kstride = K2; }
        const ushort* Bb = Bsrc + ((size_t)bb * Nw + n0) * kstride + kloc;
#pragma unroll
        for (int it = 0; it < 4; it++) {
            const int idx = it * 256 + tid;
            const int row = idx >> 3, q4 = idx & 7;
            pb[it] = *(const uint4*)(Bb + (size_t)row * kstride + q4 * 8);
        }
    };
    auto sts_tile = [&](int buf) {
        const uint32_t base = sb + buf * SMBUF;
#pragma unroll
        for (int it = 0; it < 4; it++) {
            const int idx = it * 256 + tid;
            const int row = idx >> 3, q4 = idx & 7;
            sts_v4(base + (uint32_t)row * 144 + q4 * 16, pa[it]);
            sts_v4(base + PLB + (uint32_t)row * 144 + q4 * 16, pb[it]);
        }
    };

    ldg_tile(0);
    sts_tile(0);
    __syncthreads();

    const uint32_t aOff = (uint32_t)(wm * 32 + (lane & 15)) * 144 + ((lane >> 4) & 1) * 16;
    const uint32_t bOff = (uint32_t)(wn * 64 + (lane & 7) + ((lane & 16) ? 8 : 0)) * 144
                        + ((lane & 8) ? 16 : 0);

    for (int ch = 0; ch < nc; ch++) {
        const uint32_t base = sb + (ch & 1) * SMBUF;
        if (ch + 1 < nc) ldg_tile(ch + 1);
#pragma unroll
        for (int ksb = 0; ksb < 128; ksb += 32) {
            uint ah[2][4];
            ldsm4(ah[0], base + aOff + ksb);
            ldsm4(ah[1], base + aOff + 2304 + ksb);
            uint bh[4][4];
#pragma unroll
            for (int np = 0; np < 4; np++)
                ldsm4(bh[np], base + PLB + bOff + np * 2304 + ksb);
#pragma unroll
            for (int np = 0; np < 4; np++)
#pragma unroll
                for (int sub = 0; sub < 2; sub++) {
                    const int nt = np * 2 + sub;
                    const uint b0 = bh[np][sub * 2], b1 = bh[np][sub * 2 + 1];
#pragma unroll
                    for (int mt = 0; mt < 2; mt++)
                        mma16816(c[mt][nt], ah[mt], b0, b1);
                }
        }
        if (ch + 1 < nc) {
            sts_tile((ch + 1) & 1);
            __syncthreads();
        }
    }

    // ---- epilogue ----
    if (MODE == 0) {
        const int cm = m0 + wm * 32 + fr;
        const int cn = n0 + wn * 64 + fc;
#pragma unroll
        for (int mt = 0; mt < 2; mt++) {
            const int mlo = cm + mt * 16;
            const int mhi = mlo + 8;
            const float bi0 = bias[mlo], bi1 = bias[mhi];
#pragma unroll
            for (int nt = 0; nt < 8; nt++) {
                const int n = cn + nt * 8;
                *(float2*)(outF + ((size_t)bb * M + mlo) * ostr + n) =
                    make_float2(c[mt][nt][0] + bi0, c[mt][nt][1] + bi0);
                *(float2*)(outF + ((size_t)bb * M + mhi) * ostr + n) =
                    make_float2(c[mt][nt][2] + bi1, c[mt][nt][3] + bi1);
            }
        }
    } else if (MODE == 3) {
        ushort* ob = outT;
        const int cm = m0 + wm * 32 + fr;
        const int cn = n0 + wn * 64 + fc;
#pragma unroll
        for (int mt = 0; mt < 2; mt++) {
            const int mlo = cm + mt * 16;
            const int mhi = mlo + 8;
#pragma unroll
            for (int nt = 0; nt < 8; nt++) {
                const int n = cn + nt * 8;
                ob[(size_t)mlo * ostr + n]     = __half_as_ushort(__float2half_rn(c[mt][nt][0]));
                ob[(size_t)mlo * ostr + n + 1] = __half_as_ushort(__float2half_rn(c[mt][nt][1]));
                ob[(size_t)mhi * ostr + n]     = __half_as_ushort(__float2half_rn(c[mt][nt][2]));
                ob[(size_t)mhi * ostr + n + 1] = __half_as_ushort(__float2half_rn(c[mt][nt][3]));
            }
        }
    } else {  // MODE 1 (bias) / MODE 2 (bias+BN+ReLU): fp16 transpose out
        float* stg = (float*)smem;
        uint* ob = (uint*)(outT + (size_t)bb * Nw * M);
#pragma unroll
        for (int p = 0; p < 2; p++) {
            __syncthreads();
            if (wn == p) {
#pragma unroll
                for (int mt = 0; mt < 2; mt++) {
                    const int mloL = wm * 32 + mt * 16 + fr;
                    const int mhiL = mloL + 8;
                    const int mlo = m0 + mloL, mhi = m0 + mhiL;
                    float sc0 = 1.f, sh0 = bias[mlo];
                    float sc1 = 1.f, sh1 = bias[mhi];
                    if (MODE == 2) {
                        sc0 = gamma[mlo] * rsqrtf(var[mlo] + 1e-3f);
                        sh0 = beta[mlo] + (sh0 - mean[mlo]) * sc0;
                        sc1 = gamma[mhi] * rsqrtf(var[mhi] + 1e-3f);
                        sh1 = beta[mhi] + (sh1 - mean[mhi]) * sc1;
                    }
#pragma unroll
                    for (int nt = 0; nt < 8; nt++) {
                        const int nl = fc + nt * 8;
                        float v0 = fmaf(c[mt][nt][0], sc0, sh0);
                        float v1 = fmaf(c[mt][nt][1], sc0, sh0);
                        float v2 = fmaf(c[mt][nt][2], sc1, sh1);
                        float v3 = fmaf(c[mt][nt][3], sc1, sh1);
                        if (MODE == 2) {
                            v0 = fmaxf(v0, 0.f); v1 = fmaxf(v1, 0.f);
                            v2 = fmaxf(v2, 0.f); v3 = fmaxf(v3, 0.f);
                        }
                        stg[(nl)     * STG_S + mloL] = v0;
                        stg[(nl + 1) * STG_S + mloL] = v1;
                        stg[(nl)     * STG_S + mhiL] = v2;
                        stg[(nl + 1) * STG_S + mhiL] = v3;
                    }
                }
            }
            __syncthreads();
            const int nb = n0 + p * 64;
#pragma unroll 4
            for (int i = 0; i < 16; i++) {
                const int idx = i * 256 + tid;
                const int nn = idx >> 6;
                const int mp = idx & 63;
                const float* s = stg + nn * STG_S + mp * 2;
                const uint u = (uint)__half_as_ushort(__float2half_rn(s[0]))
                             | ((uint)__half_as_ushort(__float2half_rn(s[1])) << 16);
                ob[(size_t)(nb + nn) * (M >> 1) + (m0 >> 1) + mp] = u;
            }
        }
    }
}

// ---------------------------------------------------------------------------
// Split-K fp16 HMMA: srcp[r,c] += srch[r,:] . projT[c,:]  (atomicAdd epilogue)
// ---------------------------------------------------------------------------
__global__ void __launch_bounds__(256, 2) hmma_splitk(
    const ushort* __restrict__ A,
    const ushort* __restrict__ Bp,
    float* __restrict__ C)
{
    constexpr uint32_t PLB = 18432;
    constexpr uint32_t SMBUF = 36864;
    extern __shared__ char smem[];
    const uint32_t sb = smem_to_u32(smem);

    const int tid  = threadIdx.x;
    const int wid  = tid >> 5;
    const int lane = tid & 31;
    const int m0 = blockIdx.y * 128;
    const int kbase = blockIdx.x * 512;
    const int Kd = NN;

    const int wm = wid & 3;
    const int wn = wid >> 2;
    const int fr = lane >> 2;
    const int fc = (lane & 3) * 2;

    float c[2][8][4];
#pragma unroll
    for (int mt = 0; mt < 2; mt++)
#pragma unroll
        for (int nt = 0; nt < 8; nt++)
#pragma unroll
            for (int j = 0; j < 4; j++) c[mt][nt][j] = 0.f;

    uint4 pa[4], pb[4];
    auto ldg_tile = [&](int ch) {
        const int k0 = kbase + ch * 64;
        const ushort* Ab = A + (size_t)m0 * Kd;
#pragma unroll
        for (int it = 0; it < 4; it++) {
            const int idx = it * 256 + tid;
            const int row = idx >> 3, q4 = idx & 7;
            pa[it] = *(const uint4*)(Ab + (size_t)row * Kd + k0 + q4 * 8);
        }
#pragma unroll
        for (int it = 0; it < 4; it++) {
            const int idx = it * 256 + tid;
            const int row = idx >> 3, q4 = idx & 7;
            pb[it] = *(const uint4*)(Bp + (size_t)row * Kd + k0 + q4 * 8);
        }
    };
    auto sts_tile = [&](int buf) {
        const uint32_t base = sb + buf * SMBUF;
#pragma unroll
        for (int it = 0; it < 4; it++) {
            const int idx = it * 256 + tid;
            const int row = idx >> 3, q4 = idx & 7;
            sts_v4(base + (uint32_t)row * 144 + q4 * 16, pa[it]);
            sts_v4(base + PLB + (uint32_t)row * 144 + q4 * 16, pb[it]);
        }
    };

    ldg_tile(0);
    sts_tile(0);
    __syncthreads();

    const uint32_t aOff = (uint32_t)(wm * 32 + (lane & 15)) * 144 + ((lane >> 4) & 1) * 16;
    const uint32_t bOff = (uint32_t)(wn * 64 + (lane & 7) + ((lane & 16) ? 8 : 0)) * 144
                        + ((lane & 8) ? 16 : 0);

    for (int ch = 0; ch < 8; ch++) {
        const uint32_t base = sb + (ch & 1) * SMBUF;
        if (ch + 1 < 8) ldg_tile(ch + 1);
#pragma unroll
        for (int ksb = 0; ksb < 128; ksb += 32) {
            uint ah[2][4];
            ldsm4(ah[0], base + aOff + ksb);
            ldsm4(ah[1], base + aOff + 2304 + ksb);
            uint bh[4][4];
#pragma unroll
            for (int np = 0; np < 4; np++)
                ldsm4(bh[np], base + PLB + bOff + np * 2304 + ksb);
#pragma unroll
            for (int np = 0; np < 4; np++)
#pragma unroll
                for (int sub = 0; sub < 2; sub++) {
                    const int nt = np * 2 + sub;
#pragma unroll
                    for (int mt = 0; mt < 2; mt++)
                        mma16816(c[mt][nt], ah[mt], bh[np][sub * 2], bh[np][sub * 2 + 1]);
                }
        }
        if (ch + 1 < 8) {
            sts_tile((ch + 1) & 1);
            __syncthreads();
        }
    }

    const int cm = m0 + wm * 32 + fr;
    const int cn = wn * 64 + fc;
#pragma unroll
    for (int mt = 0; mt < 2; mt++) {
        const int mlo = cm + mt * 16;
        const int mhi = mlo + 8;
#pragma unroll
        for (int nt = 0; nt < 8; nt++) {
            const int n = cn + nt * 8;
            atomicAdd(&C[(size_t)mlo * KK + n],     c[mt][nt][0]);
            atomicAdd(&C[(size_t)mlo * KK + n + 1], c[mt][nt][1]);
            atomicAdd(&C[(size_t)mhi * KK + n],     c[mt][nt][2]);
            atomicAdd(&C[(size_t)mhi * KK + n + 1], c[mt][nt][3]);
        }
    }
}

// ---------------------------------------------------------------------------
// kp = Wk @ srcp (per batch), accumulated onto kp_init values. (fp32, small)
// ---------------------------------------------------------------------------
__global__ void __launch_bounds__(256) kp_gemm(
    const float* __restrict__ W, const float* __restrict__ P, float* __restrict__ C)
{
    __shared__ float As[8][128];
    __shared__ float Bs[8][128];

    const int t  = threadIdx.x;
    const int ty = t >> 4;
    const int tx = t & 15;
    const int r0 = blockIdx.x * 128;
    const int chunk = DD / gridDim.y;
    const int c0 = blockIdx.y * chunk;
    const int b = blockIdx.z;

    const float* Pb = P + (size_t)b * DD * KK;
    float* Cb = C + (size_t)b * DD * KK;

    const int ar = t >> 1, ac = (t & 1) * 4;
    const int br = t >> 5, bc = (t & 31) * 4;

    float acc[8][8];
#pragma unroll
    for (int i = 0; i < 8; i++)
#pragma unroll
        for (int j = 0; j < 8; j++) acc[i][j] = 0.f;

    for (int kt = 0; kt < chunk; kt += 8) {
        const int kb = c0 + kt;
        float4 av = *(const float4*)(W + (size_t)(r0 + ar) * DD + kb + ac);
        As[ac + 0][ar] = av.x;
        As[ac + 1][ar] = av.y;
        As[ac + 2][ar] = av.z;
        As[ac + 3][ar] = av.w;
        *(float4*)&Bs[br][bc] = *(const float4*)(Pb + (size_t)(kb + br) * KK + bc);
        __syncthreads();
#pragma unroll
        for (int kk = 0; kk < 8; kk++) {
            float a[8], bv[8];
#pragma unroll
            for (int i = 0; i < 8; i++) a[i] = As[kk][ty * 8 + i];
#pragma unroll
            for (int j = 0; j < 8; j++) bv[j] = Bs[kk][tx * 8 + j];
#pragma unroll
            for (int i = 0; i < 8; i++)
#pragma unroll
                for (int j = 0; j < 8; j++)
                    acc[i][j] = fmaf(a[i], bv[j], acc[i][j]);
        }
        __syncthreads();
    }

#pragma unroll
    for (int i = 0; i < 8; i++)
#pragma unroll
        for (int j = 0; j < 8; j++)
            atomicAdd(&Cb[(size_t)(r0 + ty * 8 + i) * KK + tx * 8 + j], acc[i][j]);
}

// ---------------------------------------------------------------------------
// Fused Linformer attention, SINGLE PASS (no max subtraction — scores are
// bounded |s|≲10 by construction, exp cannot overflow/underflow to all-zero).
// q read fp16 head-major; msg written fp16 head-major per-thread contiguous.
// smem: KsT only (33.8 KB static).
// ---------------------------------------------------------------------------
#define KST_STRIDE 66

__global__ void __launch_bounds__(128, 2) attn_kernel(
    const ushort* __restrict__ qs,
    const float* __restrict__ kp,
    ushort* __restrict__ msgs)
{
    __shared__ float KsT[KK * KST_STRIDE];

    const int tid = threadIdx.x;
    const int n = blockIdx.x * 128 + tid;
    const int h = blockIdx.y;
    const int b = blockIdx.z;

#pragma unroll 4
    for (int dh = 0; dh < DHH; dh++)
        KsT[tid * KST_STRIDE + dh] = kp[((size_t)b * DD + (size_t)dh * HH + h) * KK + tid];
    __syncthreads();

    // q: contiguous 64 fp16 at qs[b][n][h*64]
    const uint4* qb = (const uint4*)(qs + ((size_t)b * NN + n) * DD + (size_t)h * DHH);
    ull qv2[DHH / 2];
#pragma unroll
    for (int i = 0; i < 8; i++) {
        const uint4 v = qb[i];
        float2 f;
        f = __half22float2(*(const __half2*)&v.x); qv2[i * 4 + 0] = pack2(f.x, f.y);
        f = __half22float2(*(const __half2*)&v.y); qv2[i * 4 + 1] = pack2(f.x, f.y);
        f = __half22float2(*(const __half2*)&v.z); qv2[i * 4 + 2] = pack2(f.x, f.y);
        f = __half22float2(*(const __half2*)&v.w); qv2[i * 4 + 3] = pack2(f.x, f.y);
    }

    float sum = 0.f;
    ull acc2[DHH / 2];
#pragma unroll
    for (int dhp = 0; dhp < DHH / 2; dhp++) acc2[dhp] = 0ULL;

#pragma unroll 2
    for (int k = 0; k < KK; k++) {
        const float* krow = KsT + k * KST_STRIDE;
        ull s2 = 0ULL;
#pragma unroll
        for (int dhp = 0; dhp < DHH / 2; dhp++)
            ffma2(s2, qv2[dhp], *(const ull*)(krow + 2 * dhp));
        float lo, hi;
        unpack2(s2, lo, hi);
        const float e = __expf((lo + hi) * 0.125f);
        sum += e;
        const ull e2 = pack2(e, e);
#pragma unroll
        for (int dhp = 0; dhp < DHH / 2; dhp++)
            ffma2(acc2[dhp], e2, *(const ull*)(krow + 2 * dhp));
    }
    const float inv = 1.f / sum;

    // direct contiguous store: msgs[b][n][h*64 + dh]
    uint4* ob = (uint4*)(msgs + ((size_t)b * NN + n) * DD + (size_t)h * DHH);
#pragma unroll
    for (int g = 0; g < 8; g++) {
        uint u[4];
#pragma unroll
        for (int j = 0; j < 4; j++) {
            float lo, hi;
            unpack2(acc2[g * 4 + j], lo, hi);
            u[j] = (uint)__half_as_ushort(__float2half_rn(lo * inv))
                 | ((uint)__half_as_ushort(__float2half_rn(hi * inv)) << 16);
        }
        ob[g] = make_uint4(u[0], u[1], u[2], u[3]);
    }
}

// ---------------------------------------------------------------------------
extern "C" void kernel_launch(void* const* d_in, const int* in_sizes, int n_in,
                              void* d_out, int out_size)
{
    const float* x       = (const float*)d_in[0];
    const float* source  = (const float*)d_in[1];
    const float* to_q_w  = (const float*)d_in[2];
    const float* to_q_b  = (const float*)d_in[3];
    const float* to_k_w  = (const float*)d_in[4];
    const float* to_k_b  = (const float*)d_in[5];
    const float* proj_k  = (const float*)d_in[6];
    const float* merge_w = (const float*)d_in[7];
    const float* merge_b = (const float*)d_in[8];
    const float* mlp_w1  = (const float*)d_in[9];
    const float* mlp_b1  = (const float*)d_in[10];
    const float* bn_g    = (const float*)d_in[11];
    const float* bn_b    = (const float*)d_in[12];
    const float* bn_m    = (const float*)d_in[13];
    const float* bn_v    = (const float*)d_in[14];
    const float* mlp_w2  = (const float*)d_in[15];
    const float* mlp_b2  = (const float*)d_in[16];
    float* out = (float*)d_out;

    float *kp, *srcp, *scol, *b1f, *bqp;
    ushort *wqp, *ws1fh, *ws2h, *w1bh, *wmTp, *xs, *qs, *msgs, *hs, *srch, *projT;
    cudaGetSymbolAddress((void**)&kp,   g_kp);
    cudaGetSymbolAddress((void**)&srcp, g_srcp);
    cudaGetSymbolAddress((void**)&scol, g_scol);
    cudaGetSymbolAddress((void**)&b1f,  g_b1f);
    cudaGetSymbolAddress((void**)&bqp,  g_bqp);
    cudaGetSymbolAddress((void**)&wqp,  g_wqp_h);
    cudaGetSymbolAddress((void**)&ws1fh,g_ws1f_h);
    cudaGetSymbolAddress((void**)&ws2h, g_ws2_h);
    cudaGetSymbolAddress((void**)&w1bh, g_w1b_h);
    cudaGetSymbolAddress((void**)&wmTp, g_wmTp);
    cudaGetSymbolAddress((void**)&xs,   g_xs);
    cudaGetSymbolAddress((void**)&qs,   g_qs);
    cudaGetSymbolAddress((void**)&msgs, g_msgs);
    cudaGetSymbolAddress((void**)&hs,   g_hs);
    cudaGetSymbolAddress((void**)&srch, g_srch);
    cudaGetSymbolAddress((void**)&projT,g_projT);

    const int SM1 = 2 * 36864;
    cudaFuncSetAttribute(hmma_gemm<0>, cudaFuncAttributeMaxDynamicSharedMemorySize, SM1);
    cudaFuncSetAttribute(hmma_gemm<1>, cudaFuncAttributeMaxDynamicSharedMemorySize, SM1);
    cudaFuncSetAttribute(hmma_gemm<2>, cudaFuncAttributeMaxDynamicSharedMemorySize, SM1);
    cudaFuncSetAttribute(hmma_gemm<3>, cudaFuncAttributeMaxDynamicSharedMemorySize, SM1);
    cudaFuncSetAttribute(hmma_splitk, cudaFuncAttributeMaxDynamicSharedMemorySize, SM1);

    // 0) weight prep
    weight_half_perm<<<(DD * DD) / 256, 256>>>(to_q_w, wqp);
    bias_perm<<<DD / 256, 256>>>(to_q_b, bqp);
    weight_half<<<(2 * DD * DD + 255) / 256, 256>>>(mlp_w2, ws2h, 2 * DD * DD);
    w1_prep<<<(4 * DD * DD) / 256, 256>>>(mlp_w1, ws1fh, w1bh);
    transpose_perm<<<dim3(DD / 32, DD / 32), dim3(32, 8)>>>(merge_w, wmTp);
    // W1c' = W1b @ Wm (perm cols) -> ws1fh[m][1024:2048]  (single-plane)
    hmma_gemm<3><<<dim3(DD / 128, (2 * DD) / 128, 1), 256, SM1>>>(
        w1bh, wmTp, wmTp, nullptr, nullptr, nullptr, nullptr, nullptr,
        nullptr, ws1fh + DD, 2 * DD, DD, DD, DD, 2 * DD);
    bias_fold<<<(2 * DD) / 8, 256>>>(mlp_w1, merge_b, mlp_b1, b1f);

    // x transpose, source fp16 convert, proj transpose
    transpose_half<<<dim3(NN / 32, DD / 32, BB), dim3(32, 8)>>>(x, xs, DD, NN);
    weight_half<<<(int)(((size_t)BB * DD * NN + 255) / 256), 256>>>(source, srch,
                                                                    BB * DD * NN);
    transpose_half<<<dim3(KK / 32, NN / 32, 1), dim3(32, 8)>>>(proj_k, projT, NN, KK);

    // 1) Linformer fold: kp = Wk @ (src @ proj) + bk * colsum(proj)
    cudaMemsetAsync(scol, 0, sizeof(float) * KK);
    colsum_kernel<<<NN / 128, KK>>>(proj_k, scol);
    cudaMemsetAsync(srcp, 0, sizeof(float) * (size_t)BB * DD * KK);
    hmma_splitk<<<dim3(8, (BB * DD) / 128), 256, SM1>>>(srch, projT, srcp);
    kp_init<<<(BB * DD * KK) / 256, 256>>>(to_k_b, scol, kp);
    kp_gemm<<<dim3(DD / 128, 4, BB), 256>>>(to_k_w, srcp, kp);

    // 2) q = Wq @ x + bq  (fp16 head-major transposed out)
    hmma_gemm<1><<<dim3(NN / 128, DD / 128, BB), 256, SM1>>>(
        wqp, xs, xs, bqp, nullptr, nullptr, nullptr, nullptr,
        nullptr, qs, DD, DD, NN, DD, 0);

    // 3) fused attention -> msgs fp16 head-major
    attn_kernel<<<dim3(NN / 128, HH, BB), dim3(128)>>>(qs, kp, msgs);

    // 4) h = relu(BN([W1a | W1c'] @ concat(x, msg) + b1'))
    hmma_gemm<2><<<dim3(NN / 128, (2 * DD) / 128, BB), 256, SM1>>>(
        ws1fh, xs, msgs, b1f, bn_g, bn_b, bn_m, bn_v,
        nullptr, hs, 2 * DD, 2 * DD, NN, DD, 0);

    // 5) out = W2 @ h + b2  (fp32 out)
    hmma_gemm<0><<<dim3(NN / 128, DD / 128, BB), 256, SM1>>>(
        ws2h, hs, hs, mlp_b2, nullptr, nullptr, nullptr, nullptr,
        out, nullptr, DD, 2 * DD, NN, 2 * DD, NN);
}

// round 12
// speedup vs baseline: 8.4186x; 1.1482x over previous
#include <cuda_runtime.h>
#include <cuda_fp16.h>
#include <math.h>
#include <stdint.h>

// Problem constants
#define BB 4
#define DD 1024
#define NN 4096
#define HH 16
#define KK 128
#define DHH 64

typedef unsigned long long ull;
typedef unsigned int uint;
typedef unsigned short ushort;

// ---------------- scratch (device globals) ----------------
__device__ float g_kp  [(size_t)BB * DD * KK];
__device__ float g_srcp[(size_t)BB * DD * KK];
__device__ float g_scol[KK];
__device__ float g_b1f [2 * DD];
__device__ float g_bqp [DD];

// single-plane fp16 weights
__device__ ushort g_wqp_h [(size_t)DD * DD];
__device__ ushort g_ws1f_h[(size_t)(2 * DD) * (2 * DD)];
__device__ ushort g_ws2_h [(size_t)DD * (2 * DD)];
__device__ ushort g_w1b_h [(size_t)(2 * DD) * DD];
__device__ ushort g_wmTp  [(size_t)DD * DD];
// fp16 activations / operands
__device__ ushort g_xs   [(size_t)BB * NN * DD];
__device__ ushort g_qs   [(size_t)BB * NN * DD];
__device__ ushort g_msgs [(size_t)BB * NN * DD];
__device__ ushort g_hs   [(size_t)BB * NN * 2 * DD];
__device__ ushort g_srch [(size_t)BB * DD * NN];
__device__ ushort g_projT[(size_t)KK * NN];

// ---------------- helpers ----------------
__device__ __forceinline__ uint32_t smem_to_u32(const void* p) {
    uint32_t a;
    asm("{ .reg .u64 t; cvta.to.shared.u64 t, %1; cvt.u32.u64 %0, t; }"
        : "=r"(a) : "l"(p));
    return a;
}
__device__ __forceinline__ void sts_v4(uint32_t addr, uint4 v) {
    asm volatile("st.shared.v4.b32 [%0], {%1, %2, %3, %4};"
                 :: "r"(addr), "r"(v.x), "r"(v.y), "r"(v.z), "r"(v.w));
}
__device__ __forceinline__ void ldsm4(uint* r, uint32_t addr) {
    asm volatile("ldmatrix.sync.aligned.m8n8.x4.shared.b16 {%0,%1,%2,%3}, [%4];"
        : "=r"(r[0]), "=r"(r[1]), "=r"(r[2]), "=r"(r[3]) : "r"(addr));
}

// HMMA m16n8k16 fp16 -> fp32
__device__ __forceinline__ void mma16816(float* c, const uint* a, uint b0, uint b1) {
    asm volatile(
        "mma.sync.aligned.m16n8k16.row.col.f32.f16.f16.f32 "
        "{%0,%1,%2,%3}, {%4,%5,%6,%7}, {%8,%9}, {%0,%1,%2,%3};"
        : "+f"(c[0]), "+f"(c[1]), "+f"(c[2]), "+f"(c[3])
        : "r"(a[0]), "r"(a[1]), "r"(a[2]), "r"(a[3]), "r"(b0), "r"(b1));
}

// ---------------------------------------------------------------------------
__global__ void weight_half(const float* __restrict__ in, ushort* __restrict__ out, int n) {
    int i = blockIdx.x * 256 + threadIdx.x;
    if (i < n) out[i] = __half_as_ushort(__float2half_rn(in[i]));
}

// Wq rows permuted: out[p][k] = fp16(in[m][k]), p = (m%16)*64 + m/16
__global__ void weight_half_perm(const float* __restrict__ in, ushort* __restrict__ out) {
    int i = blockIdx.x * 256 + threadIdx.x;
    int m = i >> 10, k = i & 1023;
    int p = (m & 15) * 64 + (m >> 4);
    out[(size_t)p * DD + k] = __half_as_ushort(__float2half_rn(in[i]));
}

// permuted bias: out[p] = in[(p%64)*16 + p/64]
__global__ void bias_perm(const float* __restrict__ in, float* __restrict__ out) {
    int p = blockIdx.x * 256 + threadIdx.x;
    int d = (p & 63) * 16 + (p >> 6);
    out[p] = in[d];
}

// mlp_w1 combined prep
__global__ void w1_prep(const float* __restrict__ w1,
                        ushort* __restrict__ w1a, ushort* __restrict__ w1b) {
    int i = blockIdx.x * 256 + threadIdx.x;
    int m = i >> 11, k = i & 2047;
    ushort v = __half_as_ushort(__float2half_rn(w1[i]));
    if (k < DD) w1a[(size_t)m * (2 * DD) + k] = v;
    else        w1b[(size_t)m * DD + (k - DD)] = v;
}

// fp32 [B, C, N] -> fp16 [B, N, C]
__global__ void transpose_half(const float* __restrict__ in, ushort* __restrict__ out,
                               int C, int Nw) {
    __shared__ float tile[32][33];
    const int b = blockIdx.z;
    const int n0 = blockIdx.x * 32, c0 = blockIdx.y * 32;
    const int tx = threadIdx.x, ty = threadIdx.y;
    const float* inb = in + ((size_t)b * C + c0) * Nw + n0;
#pragma unroll
    for (int i = 0; i < 32; i += 8)
        tile[ty + i][tx] = inb[(size_t)(ty + i) * Nw + tx];
    __syncthreads();
    ushort* ob = out + ((size_t)b * Nw + n0) * C + c0;
#pragma unroll
    for (int i = 0; i < 32; i += 8)
        ob[(size_t)(ty + i) * C + tx] = __half_as_ushort(__float2half_rn(tile[tx][ty + i]));
}

// Permuted merge transpose: out[p][j] = fp16(merge_w[j][c]), p=(c%16)*64+c/16
__global__ void transpose_perm(const float* __restrict__ in, ushort* __restrict__ out) {
    __shared__ float tile[32][33];
    const int n0 = blockIdx.x * 32, c0 = blockIdx.y * 32;
    const int tx = threadIdx.x, ty = threadIdx.y;
    const float* inb = in + (size_t)(c0) * DD + n0;
#pragma unroll
    for (int i = 0; i < 32; i += 8)
        tile[ty + i][tx] = inb[(size_t)(ty + i) * DD + tx];
    __syncthreads();
#pragma unroll
    for (int i = 0; i < 32; i += 8) {
        const int r = n0 + ty + i;
        const int p = (r & 15) * 64 + (r >> 4);
        out[(size_t)p * DD + c0 + tx] =
            __half_as_ushort(__float2half_rn(tile[tx][ty + i]));
    }
}

// colsum of proj (coalesced, 32 CTAs)
__global__ void colsum_kernel(const float* __restrict__ proj, float* __restrict__ S) {
    const int c = threadIdx.x;
    const float* p = proj + (size_t)blockIdx.x * 128 * KK + c;
    float s = 0.f;
#pragma unroll 8
    for (int m = 0; m < 128; m++) s += p[(size_t)m * KK];
    atomicAdd(&S[c], s);
}

// kp init: kp[b,d,c] = bk[d] * S[c]
__global__ void kp_init(const float* __restrict__ bk, const float* __restrict__ S,
                        float* __restrict__ kp) {
    int i = blockIdx.x * 256 + threadIdx.x;
    int c = i & (KK - 1);
    int d = (i >> 7) & (DD - 1);
    kp[i] = bk[d] * S[c];
}

// b1f[m] = b1[m] + dot(W1[m, 1024:2048], bm)
__global__ void bias_fold(const float* __restrict__ w1, const float* __restrict__ bm,
                          const float* __restrict__ b1, float* __restrict__ out) {
    const int m = blockIdx.x * 8 + (threadIdx.x >> 5);
    const int lane = threadIdx.x & 31;
    float s = 0.f;
#pragma unroll 4
    for (int c = lane; c < DD; c += 32)
        s += w1[(size_t)m * (2 * DD) + DD + c] * bm[c];
#pragma unroll
    for (int o = 16; o; o >>= 1) s += __shfl_xor_sync(0xFFFFFFFFu, s, o);
    if (lane == 0) out[m] = b1[m] + s;
}

// ---------------------------------------------------------------------------
// Warp-level HMMA GEMM (single-plane fp16 A).
// MODE 0: fp32 out (+bias); MODE 1: +bias fp16-transpose out [B,Nw,M];
// MODE 2: +bias/BN/ReLU fp16-transpose out; MODE 3: plain-fp16 out [M,ostr].
// ---------------------------------------------------------------------------
#define STG_S 136

template <int MODE>
__global__ void __launch_bounds__(256, 2) hmma_gemm(
    const ushort* __restrict__ Aptr,
    const ushort* __restrict__ B1,
    const ushort* __restrict__ B2,
    const float* __restrict__ bias,
    const float* __restrict__ gamma,
    const float* __restrict__ beta,
    const float* __restrict__ mean,
    const float* __restrict__ var,
    float* __restrict__ outF,
    ushort* __restrict__ outT,
    int M, int Kd, int Nw, int K1, int ostr)
{
    constexpr uint32_t PLB   = 18432u;
    constexpr uint32_t SMBUF = 36864u;

    extern __shared__ char smem[];
    const uint32_t sb = smem_to_u32(smem);

    const int tid  = threadIdx.x;
    const int wid  = tid >> 5;
    const int lane = tid & 31;
    const int m0 = blockIdx.y * 128;
    const int n0 = blockIdx.x * 128;
    const int bb = blockIdx.z;

    const int wm = wid & 3;
    const int wn = wid >> 2;
    const int K2 = Kd - K1;
    const int fr = lane >> 2;
    const int fc = (lane & 3) * 2;

    float c[2][8][4];
#pragma unroll
    for (int mt = 0; mt < 2; mt++)
#pragma unroll
        for (int nt = 0; nt < 8; nt++)
#pragma unroll
            for (int j = 0; j < 4; j++) c[mt][nt][j] = 0.f;

    const int nc = Kd >> 6;
    uint4 pa[4], pb[4];

    auto ldg_tile = [&](int ch) {
        const int k0 = ch * 64;
        const ushort* Ab = Aptr + (size_t)m0 * Kd;
#pragma unroll
        for (int it = 0; it < 4; it++) {
            const int idx = it * 256 + tid;
            const int row = idx >> 3, q4 = idx & 7;
            pa[it] = *(const uint4*)(Ab + (size_t)row * Kd + k0 + q4 * 8);
        }
        const ushort* Bsrc; int kloc, kstride;
        if (k0 < K1) { Bsrc = B1; kloc = k0;      kstride = K1; }
        else         { Bsrc = B2; kloc = k0 - K1; kstride = K2; }
        const ushort* Bb = Bsrc + ((size_t)bb * Nw + n0) * kstride + kloc;
#pragma unroll
        for (int it = 0; it < 4; it++) {
            const int idx = it * 256 + tid;
            const int row = idx >> 3, q4 = idx & 7;
            pb[it] = *(const uint4*)(Bb + (size_t)row * kstride + q4 * 8);
        }
    };
    auto sts_tile = [&](int buf) {
        const uint32_t base = sb + buf * SMBUF;
#pragma unroll
        for (int it = 0; it < 4; it++) {
            const int idx = it * 256 + tid;
            const int row = idx >> 3, q4 = idx & 7;
            sts_v4(base + (uint32_t)row * 144 + q4 * 16, pa[it]);
            sts_v4(base + PLB + (uint32_t)row * 144 + q4 * 16, pb[it]);
        }
    };

    ldg_tile(0);
    sts_tile(0);
    __syncthreads();

    const uint32_t aOff = (uint32_t)(wm * 32 + (lane & 15)) * 144 + ((lane >> 4) & 1) * 16;
    const uint32_t bOff = (uint32_t)(wn * 64 + (lane & 7) + ((lane & 16) ? 8 : 0)) * 144
                        + ((lane & 8) ? 16 : 0);

    for (int ch = 0; ch < nc; ch++) {
        const uint32_t base = sb + (ch & 1) * SMBUF;
        if (ch + 1 < nc) ldg_tile(ch + 1);
#pragma unroll
        for (int ksb = 0; ksb < 128; ksb += 32) {
            uint ah[2][4];
            ldsm4(ah[0], base + aOff + ksb);
            ldsm4(ah[1], base + aOff + 2304 + ksb);
            uint bh[4][4];
#pragma unroll
            for (int np = 0; np < 4; np++)
                ldsm4(bh[np], base + PLB + bOff + np * 2304 + ksb);
#pragma unroll
            for (int np = 0; np < 4; np++)
#pragma unroll
                for (int sub = 0; sub < 2; sub++) {
                    const int nt = np * 2 + sub;
                    const uint b0 = bh[np][sub * 2], b1 = bh[np][sub * 2 + 1];
#pragma unroll
                    for (int mt = 0; mt < 2; mt++)
                        mma16816(c[mt][nt], ah[mt], b0, b1);
                }
        }
        if (ch + 1 < nc) {
            sts_tile((ch + 1) & 1);
            __syncthreads();
        }
    }

    // ---- epilogue ----
    if (MODE == 0) {
        const int cm = m0 + wm * 32 + fr;
        const int cn = n0 + wn * 64 + fc;
#pragma unroll
        for (int mt = 0; mt < 2; mt++) {
            const int mlo = cm + mt * 16;
            const int mhi = mlo + 8;
            const float bi0 = bias[mlo], bi1 = bias[mhi];
#pragma unroll
            for (int nt = 0; nt < 8; nt++) {
                const int n = cn + nt * 8;
                *(float2*)(outF + ((size_t)bb * M + mlo) * ostr + n) =
                    make_float2(c[mt][nt][0] + bi0, c[mt][nt][1] + bi0);
                *(float2*)(outF + ((size_t)bb * M + mhi) * ostr + n) =
                    make_float2(c[mt][nt][2] + bi1, c[mt][nt][3] + bi1);
            }
        }
    } else if (MODE == 3) {
        ushort* ob = outT;
        const int cm = m0 + wm * 32 + fr;
        const int cn = n0 + wn * 64 + fc;
#pragma unroll
        for (int mt = 0; mt < 2; mt++) {
            const int mlo = cm + mt * 16;
            const int mhi = mlo + 8;
#pragma unroll
            for (int nt = 0; nt < 8; nt++) {
                const int n = cn + nt * 8;
                ob[(size_t)mlo * ostr + n]     = __half_as_ushort(__float2half_rn(c[mt][nt][0]));
                ob[(size_t)mlo * ostr + n + 1] = __half_as_ushort(__float2half_rn(c[mt][nt][1]));
                ob[(size_t)mhi * ostr + n]     = __half_as_ushort(__float2half_rn(c[mt][nt][2]));
                ob[(size_t)mhi * ostr + n + 1] = __half_as_ushort(__float2half_rn(c[mt][nt][3]));
            }
        }
    } else {
        float* stg = (float*)smem;
        uint* ob = (uint*)(outT + (size_t)bb * Nw * M);
#pragma unroll
        for (int p = 0; p < 2; p++) {
            __syncthreads();
            if (wn == p) {
#pragma unroll
                for (int mt = 0; mt < 2; mt++) {
                    const int mloL = wm * 32 + mt * 16 + fr;
                    const int mhiL = mloL + 8;
                    const int mlo = m0 + mloL, mhi = m0 + mhiL;
                    float sc0 = 1.f, sh0 = bias[mlo];
                    float sc1 = 1.f, sh1 = bias[mhi];
                    if (MODE == 2) {
                        sc0 = gamma[mlo] * rsqrtf(var[mlo] + 1e-3f);
                        sh0 = beta[mlo] + (sh0 - mean[mlo]) * sc0;
                        sc1 = gamma[mhi] * rsqrtf(var[mhi] + 1e-3f);
                        sh1 = beta[mhi] + (sh1 - mean[mhi]) * sc1;
                    }
#pragma unroll
                    for (int nt = 0; nt < 8; nt++) {
                        const int nl = fc + nt * 8;
                        float v0 = fmaf(c[mt][nt][0], sc0, sh0);
                        float v1 = fmaf(c[mt][nt][1], sc0, sh0);
                        float v2 = fmaf(c[mt][nt][2], sc1, sh1);
                        float v3 = fmaf(c[mt][nt][3], sc1, sh1);
                        if (MODE == 2) {
                            v0 = fmaxf(v0, 0.f); v1 = fmaxf(v1, 0.f);
                            v2 = fmaxf(v2, 0.f); v3 = fmaxf(v3, 0.f);
                        }
                        stg[(nl)     * STG_S + mloL] = v0;
                        stg[(nl + 1) * STG_S + mloL] = v1;
                        stg[(nl)     * STG_S + mhiL] = v2;
                        stg[(nl + 1) * STG_S + mhiL] = v3;
                    }
                }
            }
            __syncthreads();
            const int nb = n0 + p * 64;
#pragma unroll 4
            for (int i = 0; i < 16; i++) {
                const int idx = i * 256 + tid;
                const int nn = idx >> 6;
                const int mp = idx & 63;
                const float* s = stg + nn * STG_S + mp * 2;
                const uint u = (uint)__half_as_ushort(__float2half_rn(s[0]))
                             | ((uint)__half_as_ushort(__float2half_rn(s[1])) << 16);
                ob[(size_t)(nb + nn) * (M >> 1) + (m0 >> 1) + mp] = u;
            }
        }
    }
}

// ---------------------------------------------------------------------------
// Split-K fp16 HMMA: srcp[r,c] += srch[r,:] . projT[c,:]
// ---------------------------------------------------------------------------
__global__ void __launch_bounds__(256, 2) hmma_splitk(
    const ushort* __restrict__ A,
    const ushort* __restrict__ Bp,
    float* __restrict__ C)
{
    constexpr uint32_t PLB = 18432;
    constexpr uint32_t SMBUF = 36864;
    extern __shared__ char smem[];
    const uint32_t sb = smem_to_u32(smem);

    const int tid  = threadIdx.x;
    const int wid  = tid >> 5;
    const int lane = tid & 31;
    const int m0 = blockIdx.y * 128;
    const int kbase = blockIdx.x * 512;
    const int Kd = NN;

    const int wm = wid & 3;
    const int wn = wid >> 2;
    const int fr = lane >> 2;
    const int fc = (lane & 3) * 2;

    float c[2][8][4];
#pragma unroll
    for (int mt = 0; mt < 2; mt++)
#pragma unroll
        for (int nt = 0; nt < 8; nt++)
#pragma unroll
            for (int j = 0; j < 4; j++) c[mt][nt][j] = 0.f;

    uint4 pa[4], pb[4];
    auto ldg_tile = [&](int ch) {
        const int k0 = kbase + ch * 64;
        const ushort* Ab = A + (size_t)m0 * Kd;
#pragma unroll
        for (int it = 0; it < 4; it++) {
            const int idx = it * 256 + tid;
            const int row = idx >> 3, q4 = idx & 7;
            pa[it] = *(const uint4*)(Ab + (size_t)row * Kd + k0 + q4 * 8);
        }
#pragma unroll
        for (int it = 0; it < 4; it++) {
            const int idx = it * 256 + tid;
            const int row = idx >> 3, q4 = idx & 7;
            pb[it] = *(const uint4*)(Bp + (size_t)row * Kd + k0 + q4 * 8);
        }
    };
    auto sts_tile = [&](int buf) {
        const uint32_t base = sb + buf * SMBUF;
#pragma unroll
        for (int it = 0; it < 4; it++) {
            const int idx = it * 256 + tid;
            const int row = idx >> 3, q4 = idx & 7;
            sts_v4(base + (uint32_t)row * 144 + q4 * 16, pa[it]);
            sts_v4(base + PLB + (uint32_t)row * 144 + q4 * 16, pb[it]);
        }
    };

    ldg_tile(0);
    sts_tile(0);
    __syncthreads();

    const uint32_t aOff = (uint32_t)(wm * 32 + (lane & 15)) * 144 + ((lane >> 4) & 1) * 16;
    const uint32_t bOff = (uint32_t)(wn * 64 + (lane & 7) + ((lane & 16) ? 8 : 0)) * 144
                        + ((lane & 8) ? 16 : 0);

    for (int ch = 0; ch < 8; ch++) {
        const uint32_t base = sb + (ch & 1) * SMBUF;
        if (ch + 1 < 8) ldg_tile(ch + 1);
#pragma unroll
        for (int ksb = 0; ksb < 128; ksb += 32) {
            uint ah[2][4];
            ldsm4(ah[0], base + aOff + ksb);
            ldsm4(ah[1], base + aOff + 2304 + ksb);
            uint bh[4][4];
#pragma unroll
            for (int np = 0; np < 4; np++)
                ldsm4(bh[np], base + PLB + bOff + np * 2304 + ksb);
#pragma unroll
            for (int np = 0; np < 4; np++)
#pragma unroll
                for (int sub = 0; sub < 2; sub++) {
                    const int nt = np * 2 + sub;
#pragma unroll
                    for (int mt = 0; mt < 2; mt++)
                        mma16816(c[mt][nt], ah[mt], bh[np][sub * 2], bh[np][sub * 2 + 1]);
                }
        }
        if (ch + 1 < 8) {
            sts_tile((ch + 1) & 1);
            __syncthreads();
        }
    }

    const int cm = m0 + wm * 32 + fr;
    const int cn = wn * 64 + fc;
#pragma unroll
    for (int mt = 0; mt < 2; mt++) {
        const int mlo = cm + mt * 16;
        const int mhi = mlo + 8;
#pragma unroll
        for (int nt = 0; nt < 8; nt++) {
            const int n = cn + nt * 8;
            atomicAdd(&C[(size_t)mlo * KK + n],     c[mt][nt][0]);
            atomicAdd(&C[(size_t)mlo * KK + n + 1], c[mt][nt][1]);
            atomicAdd(&C[(size_t)mhi * KK + n],     c[mt][nt][2]);
            atomicAdd(&C[(size_t)mhi * KK + n + 1], c[mt][nt][3]);
        }
    }
}

// ---------------------------------------------------------------------------
// kp = Wk @ srcp (per batch), accumulated onto kp_init values. (fp32, small)
// ---------------------------------------------------------------------------
__global__ void __launch_bounds__(256) kp_gemm(
    const float* __restrict__ W, const float* __restrict__ P, float* __restrict__ C)
{
    __shared__ float As[8][128];
    __shared__ float Bs[8][128];

    const int t  = threadIdx.x;
    const int ty = t >> 4;
    const int tx = t & 15;
    const int r0 = blockIdx.x * 128;
    const int chunk = DD / gridDim.y;
    const int c0 = blockIdx.y * chunk;
    const int b = blockIdx.z;

    const float* Pb = P + (size_t)b * DD * KK;
    float* Cb = C + (size_t)b * DD * KK;

    const int ar = t >> 1, ac = (t & 1) * 4;
    const int br = t >> 5, bc = (t & 31) * 4;

    float acc[8][8];
#pragma unroll
    for (int i = 0; i < 8; i++)
#pragma unroll
        for (int j = 0; j < 8; j++) acc[i][j] = 0.f;

    for (int kt = 0; kt < chunk; kt += 8) {
        const int kb = c0 + kt;
        float4 av = *(const float4*)(W + (size_t)(r0 + ar) * DD + kb + ac);
        As[ac + 0][ar] = av.x;
        As[ac + 1][ar] = av.y;
        As[ac + 2][ar] = av.z;
        As[ac + 3][ar] = av.w;
        *(float4*)&Bs[br][bc] = *(const float4*)(Pb + (size_t)(kb + br) * KK + bc);
        __syncthreads();
#pragma unroll
        for (int kk = 0; kk < 8; kk++) {
            float a[8], bv[8];
#pragma unroll
            for (int i = 0; i < 8; i++) a[i] = As[kk][ty * 8 + i];
#pragma unroll
            for (int j = 0; j < 8; j++) bv[j] = Bs[kk][tx * 8 + j];
#pragma unroll
            for (int i = 0; i < 8; i++)
#pragma unroll
                for (int j = 0; j < 8; j++)
                    acc[i][j] = fmaf(a[i], bv[j], acc[i][j]);
        }
        __syncthreads();
    }

#pragma unroll
    for (int i = 0; i < 8; i++)
#pragma unroll
        for (int j = 0; j < 8; j++)
            atomicAdd(&Cb[(size_t)(r0 + ty * 8 + i) * KK + tx * 8 + j], acc[i][j]);
}

// ---------------------------------------------------------------------------
// Tensor-core attention (one KV block): per CTA (128 n, head h, batch b):
//   MMA1: S = Q[128x64] @ K^T  -> fp32 fragments
//   exp (scale 1/8, no max-sub; P packed fp16 with extra 1/16 scale)
//   rowsum via quad-shfl + smem atomics
//   MMA2: O_partial = P @ V (V = K), warp-split over kk; partials merged in smem
//   out = O * (16/rowsum), fp16 head-major.
// smem: Q 18432 | K1 [kk][dh] 18432 | K2 [dh][kk] 17408 | rowsum 512 = 54784 B.
// Epilogue stg (128x68 fp32 = 34816) aliases Q+K1.
// ---------------------------------------------------------------------------
#define AT_Q   0
#define AT_K1  18432
#define AT_K2  36864
#define AT_RS  54272
#define AT_SMEM 54784

__global__ void __launch_bounds__(256) attn_mma(
    const ushort* __restrict__ qs,
    const float* __restrict__ kp,
    ushort* __restrict__ msgs)
{
    extern __shared__ char smem[];
    const uint32_t sb = smem_to_u32(smem);
    float* rowsum = (float*)(smem + AT_RS);

    const int tid = threadIdx.x;
    const int wid = tid >> 5, lane = tid & 31;
    const int wm = wid & 3, wn = wid >> 2;
    const int fr = lane >> 2, fc = (lane & 3) * 2;
    const int n0 = blockIdx.x * 128;
    const int h = blockIdx.y;
    const int b = blockIdx.z;

    // Q tile [128][64] fp16 -> smem stride 144B
    {
        const ushort* qb = qs + ((size_t)b * NN + n0) * DD + (size_t)h * DHH;
#pragma unroll
        for (int it = 0; it < 4; it++) {
            const int idx = it * 256 + tid;
            const int row = idx >> 3, q4 = idx & 7;
            uint4 v = *(const uint4*)(qb + (size_t)row * DD + q4 * 8);
            sts_v4(sb + AT_Q + (uint32_t)row * 144 + q4 * 16, v);
        }
    }
    // K fp32 [64 dh][128 kk] -> K1 [kk][dh] (144B stride) + K2 [dh][kk] (272B)
    {
        const float* kb = kp + ((size_t)b * DD + h) * KK;
        ushort* K1 = (ushort*)(smem + AT_K1);
        ushort* K2 = (ushort*)(smem + AT_K2);
#pragma unroll 8
        for (int i = 0; i < 32; i++) {
            const int e = i * 256 + tid;
            const int dh = e >> 7, kk = e & 127;
            const ushort v = __half_as_ushort(
                __float2half_rn(kb[(size_t)dh * HH * KK + kk]));
            K2[dh * 136 + kk] = v;
            K1[kk * 72 + dh] = v;
        }
    }
    if (tid < 128) rowsum[tid] = 0.f;
    __syncthreads();

    // MMA1: S[n][kk], warp tile 32(m) x 64(kk)
    float c[2][8][4];
#pragma unroll
    for (int mt = 0; mt < 2; mt++)
#pragma unroll
        for (int nt = 0; nt < 8; nt++)
#pragma unroll
            for (int j = 0; j < 4; j++) c[mt][nt][j] = 0.f;

    const uint32_t aOff = (uint32_t)(wm * 32 + (lane & 15)) * 144 + ((lane >> 4) & 1) * 16;
    const uint32_t bOff = (uint32_t)(wn * 64 + (lane & 7) + ((lane & 16) ? 8 : 0)) * 144
                        + ((lane & 8) ? 16 : 0);
#pragma unroll
    for (int ksb = 0; ksb < 128; ksb += 32) {   // dh = 64 -> 4 k-steps (32B each)
        uint ah[2][4];
        ldsm4(ah[0], sb + AT_Q + aOff + ksb);
        ldsm4(ah[1], sb + AT_Q + aOff + 2304 + ksb);
#pragma unroll
        for (int np = 0; np < 4; np++) {
            uint bh[4];
            ldsm4(bh, sb + AT_K1 + bOff + np * 2304 + ksb);
#pragma unroll
            for (int sub = 0; sub < 2; sub++)
#pragma unroll
                for (int mt = 0; mt < 2; mt++)
                    mma16816(c[mt][np * 2 + sub], ah[mt], bh[sub * 2], bh[sub * 2 + 1]);
        }
    }

    // exp + rowsum + pack P (scale e by 1/16 for fp16 headroom)
    uint ph[2][8][2];
#pragma unroll
    for (int mt = 0; mt < 2; mt++) {
        float r0 = 0.f, r1 = 0.f;
#pragma unroll
        for (int nt = 0; nt < 8; nt++) {
            const float e0 = __expf(c[mt][nt][0] * 0.125f);
            const float e1 = __expf(c[mt][nt][1] * 0.125f);
            const float e2 = __expf(c[mt][nt][2] * 0.125f);
            const float e3 = __expf(c[mt][nt][3] * 0.125f);
            r0 += e0 + e1; r1 += e2 + e3;
            const __half2 p01 = __floats2half2_rn(e0 * 0.0625f, e1 * 0.0625f);
            const __half2 p23 = __floats2half2_rn(e2 * 0.0625f, e3 * 0.0625f);
            ph[mt][nt][0] = *(const uint*)&p01;
            ph[mt][nt][1] = *(const uint*)&p23;
        }
        r0 += __shfl_xor_sync(0xFFFFFFFFu, r0, 1);
        r0 += __shfl_xor_sync(0xFFFFFFFFu, r0, 2);
        r1 += __shfl_xor_sync(0xFFFFFFFFu, r1, 1);
        r1 += __shfl_xor_sync(0xFFFFFFFFu, r1, 2);
        if ((lane & 3) == 0) {
            atomicAdd(&rowsum[wm * 32 + mt * 16 + fr], r0);
            atomicAdd(&rowsum[wm * 32 + mt * 16 + fr + 8], r1);
        }
    }

    // MMA2: O_partial = P(warp's 64 kk) @ V  (N = 64 dh)
    float o[2][8][4];
#pragma unroll
    for (int mt = 0; mt < 2; mt++)
#pragma unroll
        for (int nt = 0; nt < 8; nt++)
#pragma unroll
            for (int j = 0; j < 4; j++) o[mt][nt][j] = 0.f;

    const uint32_t b2Off = (uint32_t)((lane & 7) + ((lane & 16) ? 8 : 0)) * 272
                         + ((lane & 8) ? 16 : 0) + (uint32_t)wn * 128;
#pragma unroll
    for (int s = 0; s < 4; s++) {     // local kk k-steps of 16
        uint a2[2][4];
#pragma unroll
        for (int mt = 0; mt < 2; mt++) {
            a2[mt][0] = ph[mt][2 * s][0];
            a2[mt][1] = ph[mt][2 * s][1];
            a2[mt][2] = ph[mt][2 * s + 1][0];
            a2[mt][3] = ph[mt][2 * s + 1][1];
        }
#pragma unroll
        for (int np = 0; np < 4; np++) {
            uint bh[4];
            ldsm4(bh, sb + AT_K2 + b2Off + (uint32_t)np * 16 * 272 + s * 32);
#pragma unroll
            for (int sub = 0; sub < 2; sub++)
#pragma unroll
                for (int mt = 0; mt < 2; mt++)
                    mma16816(o[mt][np * 2 + sub], a2[mt], bh[sub * 2], bh[sub * 2 + 1]);
        }
    }

    // merge partials (wn 0/1) in smem, normalize, write fp16 head-major
    __syncthreads();
    float* stg = (float*)smem;                 // [128][68] fp32, aliases Q/K1
    if (tid < 128) rowsum[tid] = 16.f / rowsum[tid];
    const int mb = wm * 32 + fr;
    if (wn == 0) {
#pragma unroll
        for (int mt = 0; mt < 2; mt++)
#pragma unroll
            for (int nt = 0; nt < 8; nt++) {
                const int col = nt * 8 + fc;
                stg[(mb + mt * 16)     * 68 + col]     = o[mt][nt][0];
                stg[(mb + mt * 16)     * 68 + col + 1] = o[mt][nt][1];
                stg[(mb + mt * 16 + 8) * 68 + col]     = o[mt][nt][2];
                stg[(mb + mt * 16 + 8) * 68 + col + 1] = o[mt][nt][3];
            }
    }
    __syncthreads();
    if (wn == 1) {
#pragma unroll
        for (int mt = 0; mt < 2; mt++)
#pragma unroll
            for (int nt = 0; nt < 8; nt++) {
                const int col = nt * 8 + fc;
                stg[(mb + mt * 16)     * 68 + col]     += o[mt][nt][0];
                stg[(mb + mt * 16)     * 68 + col + 1] += o[mt][nt][1];
                stg[(mb + mt * 16 + 8) * 68 + col]     += o[mt][nt][2];
                stg[(mb + mt * 16 + 8) * 68 + col + 1] += o[mt][nt][3];
            }
    }
    __syncthreads();

    uint* ob = (uint*)(msgs + ((size_t)b * NN + n0) * DD + (size_t)h * DHH);
#pragma unroll 4
    for (int i = 0; i < 16; i++) {
        const int idx = i * 256 + tid;
        const int nn = idx >> 5;
        const int dq = idx & 31;
        const float inv = rowsum[nn];
        const float v0 = stg[nn * 68 + dq * 2]     * inv;
        const float v1 = stg[nn * 68 + dq * 2 + 1] * inv;
        const uint u = (uint)__half_as_ushort(__float2half_rn(v0))
                     | ((uint)__half_as_ushort(__float2half_rn(v1)) << 16);
        ob[(size_t)nn * (DD / 2) + dq] = u;
    }
}

// ---------------------------------------------------------------------------
extern "C" void kernel_launch(void* const* d_in, const int* in_sizes, int n_in,
                              void* d_out, int out_size)
{
    const float* x       = (const float*)d_in[0];
    const float* source  = (const float*)d_in[1];
    const float* to_q_w  = (const float*)d_in[2];
    const float* to_q_b  = (const float*)d_in[3];
    const float* to_k_w  = (const float*)d_in[4];
    const float* to_k_b  = (const float*)d_in[5];
    const float* proj_k  = (const float*)d_in[6];
    const float* merge_w = (const float*)d_in[7];
    const float* merge_b = (const float*)d_in[8];
    const float* mlp_w1  = (const float*)d_in[9];
    const float* mlp_b1  = (const float*)d_in[10];
    const float* bn_g    = (const float*)d_in[11];
    const float* bn_b    = (const float*)d_in[12];
    const float* bn_m    = (const float*)d_in[13];
    const float* bn_v    = (const float*)d_in[14];
    const float* mlp_w2  = (const float*)d_in[15];
    const float* mlp_b2  = (const float*)d_in[16];
    float* out = (float*)d_out;

    float *kp, *srcp, *scol, *b1f, *bqp;
    ushort *wqp, *ws1fh, *ws2h, *w1bh, *wmTp, *xs, *qs, *msgs, *hs, *srch, *projT;
    cudaGetSymbolAddress((void**)&kp,   g_kp);
    cudaGetSymbolAddress((void**)&srcp, g_srcp);
    cudaGetSymbolAddress((void**)&scol, g_scol);
    cudaGetSymbolAddress((void**)&b1f,  g_b1f);
    cudaGetSymbolAddress((void**)&bqp,  g_bqp);
    cudaGetSymbolAddress((void**)&wqp,  g_wqp_h);
    cudaGetSymbolAddress((void**)&ws1fh,g_ws1f_h);
    cudaGetSymbolAddress((void**)&ws2h, g_ws2_h);
    cudaGetSymbolAddress((void**)&w1bh, g_w1b_h);
    cudaGetSymbolAddress((void**)&wmTp, g_wmTp);
    cudaGetSymbolAddress((void**)&xs,   g_xs);
    cudaGetSymbolAddress((void**)&qs,   g_qs);
    cudaGetSymbolAddress((void**)&msgs, g_msgs);
    cudaGetSymbolAddress((void**)&hs,   g_hs);
    cudaGetSymbolAddress((void**)&srch, g_srch);
    cudaGetSymbolAddress((void**)&projT,g_projT);

    const int SM1 = 2 * 36864;
    cudaFuncSetAttribute(hmma_gemm<0>, cudaFuncAttributeMaxDynamicSharedMemorySize, SM1);
    cudaFuncSetAttribute(hmma_gemm<1>, cudaFuncAttributeMaxDynamicSharedMemorySize, SM1);
    cudaFuncSetAttribute(hmma_gemm<2>, cudaFuncAttributeMaxDynamicSharedMemorySize, SM1);
    cudaFuncSetAttribute(hmma_gemm<3>, cudaFuncAttributeMaxDynamicSharedMemorySize, SM1);
    cudaFuncSetAttribute(hmma_splitk, cudaFuncAttributeMaxDynamicSharedMemorySize, SM1);
    cudaFuncSetAttribute(attn_mma, cudaFuncAttributeMaxDynamicSharedMemorySize, AT_SMEM);

    // 0) weight prep
    weight_half_perm<<<(DD * DD) / 256, 256>>>(to_q_w, wqp);
    bias_perm<<<DD / 256, 256>>>(to_q_b, bqp);
    weight_half<<<(2 * DD * DD + 255) / 256, 256>>>(mlp_w2, ws2h, 2 * DD * DD);
    w1_prep<<<(4 * DD * DD) / 256, 256>>>(mlp_w1, ws1fh, w1bh);
    transpose_perm<<<dim3(DD / 32, DD / 32), dim3(32, 8)>>>(merge_w, wmTp);
    hmma_gemm<3><<<dim3(DD / 128, (2 * DD) / 128, 1), 256, SM1>>>(
        w1bh, wmTp, wmTp, nullptr, nullptr, nullptr, nullptr, nullptr,
        nullptr, ws1fh + DD, 2 * DD, DD, DD, DD, 2 * DD);
    bias_fold<<<(2 * DD) / 8, 256>>>(mlp_w1, merge_b, mlp_b1, b1f);

    // x transpose, source fp16 convert, proj transpose
    transpose_half<<<dim3(NN / 32, DD / 32, BB), dim3(32, 8)>>>(x, xs, DD, NN);
    weight_half<<<(int)(((size_t)BB * DD * NN + 255) / 256), 256>>>(source, srch,
                                                                    BB * DD * NN);
    transpose_half<<<dim3(KK / 32, NN / 32, 1), dim3(32, 8)>>>(proj_k, projT, NN, KK);

    // 1) Linformer fold: kp = Wk @ (src @ proj) + bk * colsum(proj)
    cudaMemsetAsync(scol, 0, sizeof(float) * KK);
    colsum_kernel<<<NN / 128, KK>>>(proj_k, scol);
    cudaMemsetAsync(srcp, 0, sizeof(float) * (size_t)BB * DD * KK);
    hmma_splitk<<<dim3(8, (BB * DD) / 128), 256, SM1>>>(srch, projT, srcp);
    kp_init<<<(BB * DD * KK) / 256, 256>>>(to_k_b, scol, kp);
    kp_gemm<<<dim3(DD / 128, 4, BB), 256>>>(to_k_w, srcp, kp);

    // 2) q = Wq @ x + bq  (fp16 head-major transposed out)
    hmma_gemm<1><<<dim3(NN / 128, DD / 128, BB), 256, SM1>>>(
        wqp, xs, xs, bqp, nullptr, nullptr, nullptr, nullptr,
        nullptr, qs, DD, DD, NN, DD, 0);

    // 3) tensor-core attention -> msgs fp16 head-major
    attn_mma<<<dim3(NN / 128, HH, BB), 256, AT_SMEM>>>(qs, kp, msgs);

    // 4) h = relu(BN([W1a | W1c'] @ concat(x, msg) + b1'))
    hmma_gemm<2><<<dim3(NN / 128, (2 * DD) / 128, BB), 256, SM1>>>(
        ws1fh, xs, msgs, b1f, bn_g, bn_b, bn_m, bn_v,
        nullptr, hs, 2 * DD, 2 * DD, NN, DD, 0);

    // 5) out = W2 @ h + b2  (fp32 out)
    hmma_gemm<0><<<dim3(NN / 128, DD / 128, BB), 256, SM1>>>(
        ws2h, hs, hs, mlp_b2, nullptr, nullptr, nullptr, nullptr,
        out, nullptr, DD, 2 * DD, NN, 2 * DD, NN);
}

// round 13
// speedup vs baseline: 9.2720x; 1.1014x over previous
#include <cuda_runtime.h>
#include <cuda_fp16.h>
#include <math.h>
#include <stdint.h>

// Problem constants
#define BB 4
#define DD 1024
#define NN 4096
#define HH 16
#define KK 128
#define DHH 64

typedef unsigned long long ull;
typedef unsigned int uint;
typedef unsigned short ushort;

// ---------------- scratch (device globals) ----------------
__device__ float g_kp  [(size_t)BB * DD * KK];
__device__ float g_srcp[(size_t)BB * DD * KK];
__device__ float g_scol[KK];
__device__ float g_b1f [2 * DD];
__device__ float g_bqp [DD];

// single-plane fp16 weights
__device__ ushort g_wqp_h [(size_t)DD * DD];
__device__ ushort g_wk_h  [(size_t)DD * DD];
__device__ ushort g_ws1f_h[(size_t)(2 * DD) * (2 * DD)];
__device__ ushort g_ws2_h [(size_t)DD * (2 * DD)];
__device__ ushort g_w1b_h [(size_t)(2 * DD) * DD];
__device__ ushort g_wmTp  [(size_t)DD * DD];
// fp16 activations / operands
__device__ ushort g_xs   [(size_t)BB * NN * DD];
__device__ ushort g_qs   [(size_t)BB * NN * DD];
__device__ ushort g_msgs [(size_t)BB * NN * DD];
__device__ ushort g_hs   [(size_t)BB * NN * 2 * DD];
__device__ ushort g_srcpT[(size_t)BB * KK * DD];
__device__ ushort g_projT[(size_t)KK * NN];

// ---------------- helpers ----------------
__device__ __forceinline__ uint32_t smem_to_u32(const void* p) {
    uint32_t a;
    asm("{ .reg .u64 t; cvta.to.shared.u64 t, %1; cvt.u32.u64 %0, t; }"
        : "=r"(a) : "l"(p));
    return a;
}
__device__ __forceinline__ void sts_v4(uint32_t addr, uint4 v) {
    asm volatile("st.shared.v4.b32 [%0], {%1, %2, %3, %4};"
                 :: "r"(addr), "r"(v.x), "r"(v.y), "r"(v.z), "r"(v.w));
}
__device__ __forceinline__ void ldsm4(uint* r, uint32_t addr) {
    asm volatile("ldmatrix.sync.aligned.m8n8.x4.shared.b16 {%0,%1,%2,%3}, [%4];"
        : "=r"(r[0]), "=r"(r[1]), "=r"(r[2]), "=r"(r[3]) : "r"(addr));
}

// HMMA m16n8k16 fp16 -> fp32
__device__ __forceinline__ void mma16816(float* c, const uint* a, uint b0, uint b1) {
    asm volatile(
        "mma.sync.aligned.m16n8k16.row.col.f32.f16.f16.f32 "
        "{%0,%1,%2,%3}, {%4,%5,%6,%7}, {%8,%9}, {%0,%1,%2,%3};"
        : "+f"(c[0]), "+f"(c[1]), "+f"(c[2]), "+f"(c[3])
        : "r"(a[0]), "r"(a[1]), "r"(a[2]), "r"(a[3]), "r"(b0), "r"(b1));
}
__device__ __forceinline__ uint ex2_f16x2(uint t) {
    uint r;
    asm("ex2.approx.f16x2 %0, %1;" : "=r"(r) : "r"(t));
    return r;
}

// ---------------------------------------------------------------------------
__global__ void weight_half(const float* __restrict__ in, ushort* __restrict__ out, int n) {
    int i = blockIdx.x * 256 + threadIdx.x;
    if (i < n) out[i] = __half_as_ushort(__float2half_rn(in[i]));
}

// Wq rows permuted: out[p][k] = fp16(in[m][k]), p = (m%16)*64 + m/16
__global__ void weight_half_perm(const float* __restrict__ in, ushort* __restrict__ out) {
    int i = blockIdx.x * 256 + threadIdx.x;
    int m = i >> 10, k = i & 1023;
    int p = (m & 15) * 64 + (m >> 4);
    out[(size_t)p * DD + k] = __half_as_ushort(__float2half_rn(in[i]));
}

// permuted bias: out[p] = in[(p%64)*16 + p/64]
__global__ void bias_perm(const float* __restrict__ in, float* __restrict__ out) {
    int p = blockIdx.x * 256 + threadIdx.x;
    int d = (p & 63) * 16 + (p >> 6);
    out[p] = in[d];
}

// mlp_w1 combined prep
__global__ void w1_prep(const float* __restrict__ w1,
                        ushort* __restrict__ w1a, ushort* __restrict__ w1b) {
    int i = blockIdx.x * 256 + threadIdx.x;
    int m = i >> 11, k = i & 2047;
    ushort v = __half_as_ushort(__float2half_rn(w1[i]));
    if (k < DD) w1a[(size_t)m * (2 * DD) + k] = v;
    else        w1b[(size_t)m * DD + (k - DD)] = v;
}

// fp32 [B, C, N] -> fp16 [B, N, C]
__global__ void transpose_half(const float* __restrict__ in, ushort* __restrict__ out,
                               int C, int Nw) {
    __shared__ float tile[32][33];
    const int b = blockIdx.z;
    const int n0 = blockIdx.x * 32, c0 = blockIdx.y * 32;
    const int tx = threadIdx.x, ty = threadIdx.y;
    const float* inb = in + ((size_t)b * C + c0) * Nw + n0;
#pragma unroll
    for (int i = 0; i < 32; i += 8)
        tile[ty + i][tx] = inb[(size_t)(ty + i) * Nw + tx];
    __syncthreads();
    ushort* ob = out + ((size_t)b * Nw + n0) * C + c0;
#pragma unroll
    for (int i = 0; i < 32; i += 8)
        ob[(size_t)(ty + i) * C + tx] = __half_as_ushort(__float2half_rn(tile[tx][ty + i]));
}

// Permuted merge transpose: out[p][j] = fp16(merge_w[j][c]), p=(c%16)*64+c/16
__global__ void transpose_perm(const float* __restrict__ in, ushort* __restrict__ out) {
    __shared__ float tile[32][33];
    const int n0 = blockIdx.x * 32, c0 = blockIdx.y * 32;
    const int tx = threadIdx.x, ty = threadIdx.y;
    const float* inb = in + (size_t)(c0) * DD + n0;
#pragma unroll
    for (int i = 0; i < 32; i += 8)
        tile[ty + i][tx] = inb[(size_t)(ty + i) * DD + tx];
    __syncthreads();
#pragma unroll
    for (int i = 0; i < 32; i += 8) {
        const int r = n0 + ty + i;
        const int p = (r & 15) * 64 + (r >> 4);
        out[(size_t)p * DD + c0 + tx] =
            __half_as_ushort(__float2half_rn(tile[tx][ty + i]));
    }
}

// colsum of proj (coalesced, 32 CTAs)
__global__ void colsum_kernel(const float* __restrict__ proj, float* __restrict__ S) {
    const int c = threadIdx.x;
    const float* p = proj + (size_t)blockIdx.x * 128 * KK + c;
    float s = 0.f;
#pragma unroll 8
    for (int m = 0; m < 128; m++) s += p[(size_t)m * KK];
    atomicAdd(&S[c], s);
}

// b1f[m] = b1[m] + dot(W1[m, 1024:2048], bm)
__global__ void bias_fold(const float* __restrict__ w1, const float* __restrict__ bm,
                          const float* __restrict__ b1, float* __restrict__ out) {
    const int m = blockIdx.x * 8 + (threadIdx.x >> 5);
    const int lane = threadIdx.x & 31;
    float s = 0.f;
#pragma unroll 4
    for (int c = lane; c < DD; c += 32)
        s += w1[(size_t)m * (2 * DD) + DD + c] * bm[c];
#pragma unroll
    for (int o = 16; o; o >>= 1) s += __shfl_xor_sync(0xFFFFFFFFu, s, o);
    if (lane == 0) out[m] = b1[m] + s;
}

// ---------------------------------------------------------------------------
// Warp-level HMMA GEMM (single-plane fp16 A).
// MODE 0: fp32 out (+bias); MODE 1: +bias fp16-transpose out [B,Nw,M];
// MODE 2: +bias/BN/ReLU fp16-transpose out; MODE 3: plain-fp16 out [M,ostr];
// MODE 4: fp32 out + bias[m]*colS[n]  (colS passed via gamma).
// ---------------------------------------------------------------------------
#define STG_S 136

template <int MODE>
__global__ void __launch_bounds__(256, 2) hmma_gemm(
    const ushort* __restrict__ Aptr,
    const ushort* __restrict__ B1,
    const ushort* __restrict__ B2,
    const float* __restrict__ bias,
    const float* __restrict__ gamma,
    const float* __restrict__ beta,
    const float* __restrict__ mean,
    const float* __restrict__ var,
    float* __restrict__ outF,
    ushort* __restrict__ outT,
    int M, int Kd, int Nw, int K1, int ostr)
{
    constexpr uint32_t PLB   = 18432u;
    constexpr uint32_t SMBUF = 36864u;

    extern __shared__ char smem[];
    const uint32_t sb = smem_to_u32(smem);

    const int tid  = threadIdx.x;
    const int wid  = tid >> 5;
    const int lane = tid & 31;
    const int m0 = blockIdx.y * 128;
    const int n0 = blockIdx.x * 128;
    const int bb = blockIdx.z;

    const int wm = wid & 3;
    const int wn = wid >> 2;
    const int K2 = Kd - K1;
    const int fr = lane >> 2;
    const int fc = (lane & 3) * 2;

    float c[2][8][4];
#pragma unroll
    for (int mt = 0; mt < 2; mt++)
#pragma unroll
        for (int nt = 0; nt < 8; nt++)
#pragma unroll
            for (int j = 0; j < 4; j++) c[mt][nt][j] = 0.f;

    const int nc = Kd >> 6;
    uint4 pa[4], pb[4];

    auto ldg_tile = [&](int ch) {
        const int k0 = ch * 64;
        const ushort* Ab = Aptr + (size_t)m0 * Kd;
#pragma unroll
        for (int it = 0; it < 4; it++) {
            const int idx = it * 256 + tid;
            const int row = idx >> 3, q4 = idx & 7;
            pa[it] = *(const uint4*)(Ab + (size_t)row * Kd + k0 + q4 * 8);
        }
        const ushort* Bsrc; int kloc, kstride;
        if (k0 < K1) { Bsrc = B1; kloc = k0;      kstride = K1; }
        else         { Bsrc = B2; kloc = k0 - K1; kstride = K2; }
        const ushort* Bb = Bsrc + ((size_t)bb * Nw + n0) * kstride + kloc;
#pragma unroll
        for (int it = 0; it < 4; it++) {
            const int idx = it * 256 + tid;
            const int row = idx >> 3, q4 = idx & 7;
            pb[it] = *(const uint4*)(Bb + (size_t)row * kstride + q4 * 8);
        }
    };
    auto sts_tile = [&](int buf) {
        const uint32_t base = sb + buf * SMBUF;
#pragma unroll
        for (int it = 0; it < 4; it++) {
            const int idx = it * 256 + tid;
            const int row = idx >> 3, q4 = idx & 7;
            sts_v4(base + (uint32_t)row * 144 + q4 * 16, pa[it]);
            sts_v4(base + PLB + (uint32_t)row * 144 + q4 * 16, pb[it]);
        }
    };

    ldg_tile(0);
    sts_tile(0);
    __syncthreads();

    const uint32_t aOff = (uint32_t)(wm * 32 + (lane & 15)) * 144 + ((lane >> 4) & 1) * 16;
    const uint32_t bOff = (uint32_t)(wn * 64 + (lane & 7) + ((lane & 16) ? 8 : 0)) * 144
                        + ((lane & 8) ? 16 : 0);

    for (int ch = 0; ch < nc; ch++) {
        const uint32_t base = sb + (ch & 1) * SMBUF;
        if (ch + 1 < nc) ldg_tile(ch + 1);
#pragma unroll
        for (int ksb = 0; ksb < 128; ksb += 32) {
            uint ah[2][4];
            ldsm4(ah[0], base + aOff + ksb);
            ldsm4(ah[1], base + aOff + 2304 + ksb);
            uint bh[4][4];
#pragma unroll
            for (int np = 0; np < 4; np++)
                ldsm4(bh[np], base + PLB + bOff + np * 2304 + ksb);
#pragma unroll
            for (int np = 0; np < 4; np++)
#pragma unroll
                for (int sub = 0; sub < 2; sub++) {
                    const int nt = np * 2 + sub;
                    const uint b0 = bh[np][sub * 2], b1 = bh[np][sub * 2 + 1];
#pragma unroll
                    for (int mt = 0; mt < 2; mt++)
                        mma16816(c[mt][nt], ah[mt], b0, b1);
                }
        }
        if (ch + 1 < nc) {
            sts_tile((ch + 1) & 1);
            __syncthreads();
        }
    }

    // ---- epilogue ----
    if (MODE == 0 || MODE == 4) {
        const int cm = m0 + wm * 32 + fr;
        const int cn = n0 + wn * 64 + fc;
#pragma unroll
        for (int mt = 0; mt < 2; mt++) {
            const int mlo = cm + mt * 16;
            const int mhi = mlo + 8;
            const float bi0 = bias[mlo], bi1 = bias[mhi];
#pragma unroll
            for (int nt = 0; nt < 8; nt++) {
                const int n = cn + nt * 8;
                float s0 = 1.f, s1 = 1.f;
                if (MODE == 4) { s0 = gamma[n]; s1 = gamma[n + 1]; }
                *(float2*)(outF + ((size_t)bb * M + mlo) * ostr + n) =
                    make_float2(c[mt][nt][0] + bi0 * s0, c[mt][nt][1] + bi0 * s1);
                *(float2*)(outF + ((size_t)bb * M + mhi) * ostr + n) =
                    make_float2(c[mt][nt][2] + bi1 * s0, c[mt][nt][3] + bi1 * s1);
            }
        }
    } else if (MODE == 3) {
        ushort* ob = outT;
        const int cm = m0 + wm * 32 + fr;
        const int cn = n0 + wn * 64 + fc;
#pragma unroll
        for (int mt = 0; mt < 2; mt++) {
            const int mlo = cm + mt * 16;
            const int mhi = mlo + 8;
#pragma unroll
            for (int nt = 0; nt < 8; nt++) {
                const int n = cn + nt * 8;
                ob[(size_t)mlo * ostr + n]     = __half_as_ushort(__float2half_rn(c[mt][nt][0]));
                ob[(size_t)mlo * ostr + n + 1] = __half_as_ushort(__float2half_rn(c[mt][nt][1]));
                ob[(size_t)mhi * ostr + n]     = __half_as_ushort(__float2half_rn(c[mt][nt][2]));
                ob[(size_t)mhi * ostr + n + 1] = __half_as_ushort(__float2half_rn(c[mt][nt][3]));
            }
        }
    } else {
        float* stg = (float*)smem;
        uint* ob = (uint*)(outT + (size_t)bb * Nw * M);
#pragma unroll
        for (int p = 0; p < 2; p++) {
            __syncthreads();
            if (wn == p) {
#pragma unroll
                for (int mt = 0; mt < 2; mt++) {
                    const int mloL = wm * 32 + mt * 16 + fr;
                    const int mhiL = mloL + 8;
                    const int mlo = m0 + mloL, mhi = m0 + mhiL;
                    float sc0 = 1.f, sh0 = bias[mlo];
                    float sc1 = 1.f, sh1 = bias[mhi];
                    if (MODE == 2) {
                        sc0 = gamma[mlo] * rsqrtf(var[mlo] + 1e-3f);
                        sh0 = beta[mlo] + (sh0 - mean[mlo]) * sc0;
                        sc1 = gamma[mhi] * rsqrtf(var[mhi] + 1e-3f);
                        sh1 = beta[mhi] + (sh1 - mean[mhi]) * sc1;
                    }
#pragma unroll
                    for (int nt = 0; nt < 8; nt++) {
                        const int nl = fc + nt * 8;
                        float v0 = fmaf(c[mt][nt][0], sc0, sh0);
                        float v1 = fmaf(c[mt][nt][1], sc0, sh0);
                        float v2 = fmaf(c[mt][nt][2], sc1, sh1);
                        float v3 = fmaf(c[mt][nt][3], sc1, sh1);
                        if (MODE == 2) {
                            v0 = fmaxf(v0, 0.f); v1 = fmaxf(v1, 0.f);
                            v2 = fmaxf(v2, 0.f); v3 = fmaxf(v3, 0.f);
                        }
                        stg[(nl)     * STG_S + mloL] = v0;
                        stg[(nl + 1) * STG_S + mloL] = v1;
                        stg[(nl)     * STG_S + mhiL] = v2;
                        stg[(nl + 1) * STG_S + mhiL] = v3;
                    }
                }
            }
            __syncthreads();
            const int nb = n0 + p * 64;
#pragma unroll 4
            for (int i = 0; i < 16; i++) {
                const int idx = i * 256 + tid;
                const int nn = idx >> 6;
                const int mp = idx & 63;
                const float* s = stg + nn * STG_S + mp * 2;
                const uint u = (uint)__half_as_ushort(__float2half_rn(s[0]))
                             | ((uint)__half_as_ushort(__float2half_rn(s[1])) << 16);
                ob[(size_t)(nb + nn) * (M >> 1) + (m0 >> 1) + mp] = u;
            }
        }
    }
}

// ---------------------------------------------------------------------------
// Split-K fp16 HMMA: srcp[r,c] += fp16(source[r,:]) . projT[c,:]
// A read fp32 and converted inline in the loader.
// ---------------------------------------------------------------------------
__global__ void __launch_bounds__(256, 2) hmma_splitk(
    const float* __restrict__ A,
    const ushort* __restrict__ Bp,
    float* __restrict__ C)
{
    constexpr uint32_t PLB = 18432;
    constexpr uint32_t SMBUF = 36864;
    extern __shared__ char smem[];
    const uint32_t sb = smem_to_u32(smem);

    const int tid  = threadIdx.x;
    const int wid  = tid >> 5;
    const int lane = tid & 31;
    const int m0 = blockIdx.y * 128;
    const int kbase = blockIdx.x * 512;
    const int Kd = NN;

    const int wm = wid & 3;
    const int wn = wid >> 2;
    const int fr = lane >> 2;
    const int fc = (lane & 3) * 2;

    float c[2][8][4];
#pragma unroll
    for (int mt = 0; mt < 2; mt++)
#pragma unroll
        for (int nt = 0; nt < 8; nt++)
#pragma unroll
            for (int j = 0; j < 4; j++) c[mt][nt][j] = 0.f;

    uint4 pa[4], pb[4];
    auto ldg_tile = [&](int ch) {
        const int k0 = kbase + ch * 64;
        const float* Ab = A + (size_t)m0 * Kd;
#pragma unroll
        for (int it = 0; it < 4; it++) {
            const int idx = it * 256 + tid;
            const int row = idx >> 3, q4 = idx & 7;
            const float* ap = Ab + (size_t)row * Kd + k0 + q4 * 8;
            float4 f0 = *(const float4*)ap;
            float4 f1 = *(const float4*)(ap + 4);
            __half2 h0 = __floats2half2_rn(f0.x, f0.y);
            __half2 h1 = __floats2half2_rn(f0.z, f0.w);
            __half2 h2 = __floats2half2_rn(f1.x, f1.y);
            __half2 h3 = __floats2half2_rn(f1.z, f1.w);
            pa[it] = make_uint4(*(uint*)&h0, *(uint*)&h1, *(uint*)&h2, *(uint*)&h3);
        }
#pragma unroll
        for (int it = 0; it < 4; it++) {
            const int idx = it * 256 + tid;
            const int row = idx >> 3, q4 = idx & 7;
            pb[it] = *(const uint4*)(Bp + (size_t)row * Kd + k0 + q4 * 8);
        }
    };
    auto sts_tile = [&](int buf) {
        const uint32_t base = sb + buf * SMBUF;
#pragma unroll
        for (int it = 0; it < 4; it++) {
            const int idx = it * 256 + tid;
            const int row = idx >> 3, q4 = idx & 7;
            sts_v4(base + (uint32_t)row * 144 + q4 * 16, pa[it]);
            sts_v4(base + PLB + (uint32_t)row * 144 + q4 * 16, pb[it]);
        }
    };

    ldg_tile(0);
    sts_tile(0);
    __syncthreads();

    const uint32_t aOff = (uint32_t)(wm * 32 + (lane & 15)) * 144 + ((lane >> 4) & 1) * 16;
    const uint32_t bOff = (uint32_t)(wn * 64 + (lane & 7) + ((lane & 16) ? 8 : 0)) * 144
                        + ((lane & 8) ? 16 : 0);

    for (int ch = 0; ch < 8; ch++) {
        const uint32_t base = sb + (ch & 1) * SMBUF;
        if (ch + 1 < 8) ldg_tile(ch + 1);
#pragma unroll
        for (int ksb = 0; ksb < 128; ksb += 32) {
            uint ah[2][4];
            ldsm4(ah[0], base + aOff + ksb);
            ldsm4(ah[1], base + aOff + 2304 + ksb);
            uint bh[4][4];
#pragma unroll
            for (int np = 0; np < 4; np++)
                ldsm4(bh[np], base + PLB + bOff + np * 2304 + ksb);
#pragma unroll
            for (int np = 0; np < 4; np++)
#pragma unroll
                for (int sub = 0; sub < 2; sub++) {
                    const int nt = np * 2 + sub;
#pragma unroll
                    for (int mt = 0; mt < 2; mt++)
                        mma16816(c[mt][nt], ah[mt], bh[np][sub * 2], bh[np][sub * 2 + 1]);
                }
        }
        if (ch + 1 < 8) {
            sts_tile((ch + 1) & 1);
            __syncthreads();
        }
    }

    const int cm = m0 + wm * 32 + fr;
    const int cn = wn * 64 + fc;
#pragma unroll
    for (int mt = 0; mt < 2; mt++) {
        const int mlo = cm + mt * 16;
        const int mhi = mlo + 8;
#pragma unroll
        for (int nt = 0; nt < 8; nt++) {
            const int n = cn + nt * 8;
            atomicAdd(&C[(size_t)mlo * KK + n],     c[mt][nt][0]);
            atomicAdd(&C[(size_t)mlo * KK + n + 1], c[mt][nt][1]);
            atomicAdd(&C[(size_t)mhi * KK + n],     c[mt][nt][2]);
            atomicAdd(&C[(size_t)mhi * KK + n + 1], c[mt][nt][3]);
        }
    }
}

// ---------------------------------------------------------------------------
// Tensor-core attention with fp16x2 MUFU exp.
//   MMA1: S = Q @ K^T; P = 2^(S*log2e/8 - 4*log2e) via ex2.approx.f16x2
//   rowsum fp32 (quad shfl + smem atomics); MMA2: O = P @ V; out = O / rowsum.
// ---------------------------------------------------------------------------
#define AT_Q   0
#define AT_K1  18432
#define AT_K2  36864
#define AT_RS  54272
#define AT_SMEM 54784

__global__ void __launch_bounds__(256) attn_mma(
    const ushort* __restrict__ qs,
    const float* __restrict__ kp,
    ushort* __restrict__ msgs)
{
    extern __shared__ char smem[];
    const uint32_t sb = smem_to_u32(smem);
    float* rowsum = (float*)(smem + AT_RS);

    const int tid = threadIdx.x;
    const int wid = tid >> 5, lane = tid & 31;
    const int wm = wid & 3, wn = wid >> 2;
    const int fr = lane >> 2, fc = (lane & 3) * 2;
    const int n0 = blockIdx.x * 128;
    const int h = blockIdx.y;
    const int b = blockIdx.z;

    // Q tile [128][64] fp16 -> smem stride 144B
    {
        const ushort* qb = qs + ((size_t)b * NN + n0) * DD + (size_t)h * DHH;
#pragma unroll
        for (int it = 0; it < 4; it++) {
            const int idx = it * 256 + tid;
            const int row = idx >> 3, q4 = idx & 7;
            uint4 v = *(const uint4*)(qb + (size_t)row * DD + q4 * 8);
            sts_v4(sb + AT_Q + (uint32_t)row * 144 + q4 * 16, v);
        }
    }
    // K fp32 [64 dh][128 kk] -> K1 [kk][dh] (144B stride) + K2 [dh][kk] (272B)
    {
        const float* kb = kp + ((size_t)b * DD + h) * KK;
        ushort* K1 = (ushort*)(smem + AT_K1);
        ushort* K2 = (ushort*)(smem + AT_K2);
#pragma unroll 8
        for (int i = 0; i < 32; i++) {
            const int e = i * 256 + tid;
            const int dh = e >> 7, kk = e & 127;
            const ushort v = __half_as_ushort(
                __float2half_rn(kb[(size_t)dh * HH * KK + kk]));
            K2[dh * 136 + kk] = v;
            K1[kk * 72 + dh] = v;
        }
    }
    if (tid < 128) rowsum[tid] = 0.f;
    __syncthreads();

    // MMA1: S[n][kk]
    float c[2][8][4];
#pragma unroll
    for (int mt = 0; mt < 2; mt++)
#pragma unroll
        for (int nt = 0; nt < 8; nt++)
#pragma unroll
            for (int j = 0; j < 4; j++) c[mt][nt][j] = 0.f;

    const uint32_t aOff = (uint32_t)(wm * 32 + (lane & 15)) * 144 + ((lane >> 4) & 1) * 16;
    const uint32_t bOff = (uint32_t)(wn * 64 + (lane & 7) + ((lane & 16) ? 8 : 0)) * 144
                        + ((lane & 8) ? 16 : 0);
#pragma unroll
    for (int ksb = 0; ksb < 128; ksb += 32) {
        uint ah[2][4];
        ldsm4(ah[0], sb + AT_Q + aOff + ksb);
        ldsm4(ah[1], sb + AT_Q + aOff + 2304 + ksb);
#pragma unroll
        for (int np = 0; np < 4; np++) {
            uint bh[4];
            ldsm4(bh, sb + AT_K1 + bOff + np * 2304 + ksb);
#pragma unroll
            for (int sub = 0; sub < 2; sub++)
#pragma unroll
                for (int mt = 0; mt < 2; mt++)
                    mma16816(c[mt][np * 2 + sub], ah[mt], bh[sub * 2], bh[sub * 2 + 1]);
        }
    }

    // P = 2^(s*C1 + C2) via ex2.approx.f16x2 ; rowsum fp32
    const float C1 = 0.18033688f;    // log2(e)/8
    const float C2 = -5.7707801f;    // -4*log2(e)  (P = e^{s/8 - 4})
    uint ph[2][8][2];
#pragma unroll
    for (int mt = 0; mt < 2; mt++) {
        float r0 = 0.f, r1 = 0.f;
#pragma unroll
        for (int nt = 0; nt < 8; nt++) {
            const float t0 = fmaf(c[mt][nt][0], C1, C2);
            const float t1 = fmaf(c[mt][nt][1], C1, C2);
            const float t2 = fmaf(c[mt][nt][2], C1, C2);
            const float t3 = fmaf(c[mt][nt][3], C1, C2);
            const __half2 ta = __floats2half2_rn(t0, t1);
            const __half2 tb = __floats2half2_rn(t2, t3);
            const uint ea = ex2_f16x2(*(const uint*)&ta);
            const uint eb = ex2_f16x2(*(const uint*)&tb);
            ph[mt][nt][0] = ea;
            ph[mt][nt][1] = eb;
            const float2 fa = __half22float2(*(const __half2*)&ea);
            const float2 fb = __half22float2(*(const __half2*)&eb);
            r0 += fa.x + fa.y;
            r1 += fb.x + fb.y;
        }
        r0 += __shfl_xor_sync(0xFFFFFFFFu, r0, 1);
        r0 += __shfl_xor_sync(0xFFFFFFFFu, r0, 2);
        r1 += __shfl_xor_sync(0xFFFFFFFFu, r1, 1);
        r1 += __shfl_xor_sync(0xFFFFFFFFu, r1, 2);
        if ((lane & 3) == 0) {
            atomicAdd(&rowsum[wm * 32 + mt * 16 + fr], r0);
            atomicAdd(&rowsum[wm * 32 + mt * 16 + fr + 8], r1);
        }
    }

    // MMA2: O_partial = P(warp's 64 kk) @ V
    float o[2][8][4];
#pragma unroll
    for (int mt = 0; mt < 2; mt++)
#pragma unroll
        for (int nt = 0; nt < 8; nt++)
#pragma unroll
            for (int j = 0; j < 4; j++) o[mt][nt][j] = 0.f;

    const uint32_t b2Off = (uint32_t)((lane & 7) + ((lane & 16) ? 8 : 0)) * 272
                         + ((lane & 8) ? 16 : 0) + (uint32_t)wn * 128;
#pragma unroll
    for (int s = 0; s < 4; s++) {
        uint a2[2][4];
#pragma unroll
        for (int mt = 0; mt < 2; mt++) {
            a2[mt][0] = ph[mt][2 * s][0];
            a2[mt][1] = ph[mt][2 * s][1];
            a2[mt][2] = ph[mt][2 * s + 1][0];
            a2[mt][3] = ph[mt][2 * s + 1][1];
        }
#pragma unroll
        for (int np = 0; np < 4; np++) {
            uint bh[4];
            ldsm4(bh, sb + AT_K2 + b2Off + (uint32_t)np * 16 * 272 + s * 32);
#pragma unroll
            for (int sub = 0; sub < 2; sub++)
#pragma unroll
                for (int mt = 0; mt < 2; mt++)
                    mma16816(o[mt][np * 2 + sub], a2[mt], bh[sub * 2], bh[sub * 2 + 1]);
        }
    }

    // merge partials, normalize, write fp16 head-major
    __syncthreads();
    float* stg = (float*)smem;
    if (tid < 128) rowsum[tid] = 1.f / rowsum[tid];
    const int mb = wm * 32 + fr;
    if (wn == 0) {
#pragma unroll
        for (int mt = 0; mt < 2; mt++)
#pragma unroll
            for (int nt = 0; nt < 8; nt++) {
                const int col = nt * 8 + fc;
                stg[(mb + mt * 16)     * 68 + col]     = o[mt][nt][0];
                stg[(mb + mt * 16)     * 68 + col + 1] = o[mt][nt][1];
                stg[(mb + mt * 16 + 8) * 68 + col]     = o[mt][nt][2];
                stg[(mb + mt * 16 + 8) * 68 + col + 1] = o[mt][nt][3];
            }
    }
    __syncthreads();
    if (wn == 1) {
#pragma unroll
        for (int mt = 0; mt < 2; mt++)
#pragma unroll
            for (int nt = 0; nt < 8; nt++) {
                const int col = nt * 8 + fc;
                stg[(mb + mt * 16)     * 68 + col]     += o[mt][nt][0];
                stg[(mb + mt * 16)     * 68 + col + 1] += o[mt][nt][1];
                stg[(mb + mt * 16 + 8) * 68 + col]     += o[mt][nt][2];
                stg[(mb + mt * 16 + 8) * 68 + col + 1] += o[mt][nt][3];
            }
    }
    __syncthreads();

    uint* ob = (uint*)(msgs + ((size_t)b * NN + n0) * DD + (size_t)h * DHH);
#pragma unroll 4
    for (int i = 0; i < 16; i++) {
        const int idx = i * 256 + tid;
        const int nn = idx >> 5;
        const int dq = idx & 31;
        const float inv = rowsum[nn];
        const float v0 = stg[nn * 68 + dq * 2]     * inv;
        const float v1 = stg[nn * 68 + dq * 2 + 1] * inv;
        const uint u = (uint)__half_as_ushort(__float2half_rn(v0))
                     | ((uint)__half_as_ushort(__float2half_rn(v1)) << 16);
        ob[(size_t)nn * (DD / 2) + dq] = u;
    }
}

// ---------------------------------------------------------------------------
extern "C" void kernel_launch(void* const* d_in, const int* in_sizes, int n_in,
                              void* d_out, int out_size)
{
    const float* x       = (const float*)d_in[0];
    const float* source  = (const float*)d_in[1];
    const float* to_q_w  = (const float*)d_in[2];
    const float* to_q_b  = (const float*)d_in[3];
    const float* to_k_w  = (const float*)d_in[4];
    const float* to_k_b  = (const float*)d_in[5];
    const float* proj_k  = (const float*)d_in[6];
    const float* merge_w = (const float*)d_in[7];
    const float* merge_b = (const float*)d_in[8];
    const float* mlp_w1  = (const float*)d_in[9];
    const float* mlp_b1  = (const float*)d_in[10];
    const float* bn_g    = (const float*)d_in[11];
    const float* bn_b    = (const float*)d_in[12];
    const float* bn_m    = (const float*)d_in[13];
    const float* bn_v    = (const float*)d_in[14];
    const float* mlp_w2  = (const float*)d_in[15];
    const float* mlp_b2  = (const float*)d_in[16];
    float* out = (float*)d_out;

    float *kp, *srcp, *scol, *b1f, *bqp;
    ushort *wqp, *wkh, *ws1fh, *ws2h, *w1bh, *wmTp, *xs, *qs, *msgs, *hs, *srcpT, *projT;
    cudaGetSymbolAddress((void**)&kp,   g_kp);
    cudaGetSymbolAddress((void**)&srcp, g_srcp);
    cudaGetSymbolAddress((void**)&scol, g_scol);
    cudaGetSymbolAddress((void**)&b1f,  g_b1f);
    cudaGetSymbolAddress((void**)&bqp,  g_bqp);
    cudaGetSymbolAddress((void**)&wqp,  g_wqp_h);
    cudaGetSymbolAddress((void**)&wkh,  g_wk_h);
    cudaGetSymbolAddress((void**)&ws1fh,g_ws1f_h);
    cudaGetSymbolAddress((void**)&ws2h, g_ws2_h);
    cudaGetSymbolAddress((void**)&w1bh, g_w1b_h);
    cudaGetSymbolAddress((void**)&wmTp, g_wmTp);
    cudaGetSymbolAddress((void**)&xs,   g_xs);
    cudaGetSymbolAddress((void**)&qs,   g_qs);
    cudaGetSymbolAddress((void**)&msgs, g_msgs);
    cudaGetSymbolAddress((void**)&hs,   g_hs);
    cudaGetSymbolAddress((void**)&srcpT,g_srcpT);
    cudaGetSymbolAddress((void**)&projT,g_projT);

    const int SM1 = 2 * 36864;
    cudaFuncSetAttribute(hmma_gemm<0>, cudaFuncAttributeMaxDynamicSharedMemorySize, SM1);
    cudaFuncSetAttribute(hmma_gemm<1>, cudaFuncAttributeMaxDynamicSharedMemorySize, SM1);
    cudaFuncSetAttribute(hmma_gemm<2>, cudaFuncAttributeMaxDynamicSharedMemorySize, SM1);
    cudaFuncSetAttribute(hmma_gemm<3>, cudaFuncAttributeMaxDynamicSharedMemorySize, SM1);
    cudaFuncSetAttribute(hmma_gemm<4>, cudaFuncAttributeMaxDynamicSharedMemorySize, SM1);
    cudaFuncSetAttribute(hmma_splitk, cudaFuncAttributeMaxDynamicSharedMemorySize, SM1);
    cudaFuncSetAttribute(attn_mma, cudaFuncAttributeMaxDynamicSharedMemorySize, AT_SMEM);

    // 0) weight prep
    weight_half_perm<<<(DD * DD) / 256, 256>>>(to_q_w, wqp);
    bias_perm<<<DD / 256, 256>>>(to_q_b, bqp);
    weight_half<<<(DD * DD + 255) / 256, 256>>>(to_k_w, wkh, DD * DD);
    weight_half<<<(2 * DD * DD + 255) / 256, 256>>>(mlp_w2, ws2h, 2 * DD * DD);
    w1_prep<<<(4 * DD * DD) / 256, 256>>>(mlp_w1, ws1fh, w1bh);
    transpose_perm<<<dim3(DD / 32, DD / 32), dim3(32, 8)>>>(merge_w, wmTp);
    hmma_gemm<3><<<dim3(DD / 128, (2 * DD) / 128, 1), 256, SM1>>>(
        w1bh, wmTp, wmTp, nullptr, nullptr, nullptr, nullptr, nullptr,
        nullptr, ws1fh + DD, 2 * DD, DD, DD, DD, 2 * DD);
    bias_fold<<<(2 * DD) / 8, 256>>>(mlp_w1, merge_b, mlp_b1, b1f);

    // x transpose, proj transpose
    transpose_half<<<dim3(NN / 32, DD / 32, BB), dim3(32, 8)>>>(x, xs, DD, NN);
    transpose_half<<<dim3(KK / 32, NN / 32, 1), dim3(32, 8)>>>(proj_k, projT, NN, KK);

    // 1) Linformer fold: kp = Wk @ (src @ proj) + bk * colsum(proj)
    cudaMemsetAsync(scol, 0, sizeof(float) * KK);
    colsum_kernel<<<NN / 128, KK>>>(proj_k, scol);
    cudaMemsetAsync(srcp, 0, sizeof(float) * (size_t)BB * DD * KK);
    hmma_splitk<<<dim3(8, (BB * DD) / 128), 256, SM1>>>(source, projT, srcp);
    transpose_half<<<dim3(KK / 32, DD / 32, BB), dim3(32, 8)>>>(srcp, srcpT, DD, KK);
    hmma_gemm<4><<<dim3(1, DD / 128, BB), 256, SM1>>>(
        wkh, srcpT, srcpT, to_k_b, scol, nullptr, nullptr, nullptr,
        kp, nullptr, DD, DD, KK, DD, KK);

    // 2) q = Wq @ x + bq  (fp16 head-major transposed out)
    hmma_gemm<1><<<dim3(NN / 128, DD / 128, BB), 256, SM1>>>(
        wqp, xs, xs, bqp, nullptr, nullptr, nullptr, nullptr,
        nullptr, qs, DD, DD, NN, DD, 0);

    // 3) tensor-core attention -> msgs fp16 head-major
    attn_mma<<<dim3(NN / 128, HH, BB), 256, AT_SMEM>>>(qs, kp, msgs);

    // 4) h = relu(BN([W1a | W1c'] @ concat(x, msg) + b1'))
    hmma_gemm<2><<<dim3(NN / 128, (2 * DD) / 128, BB), 256, SM1>>>(
        ws1fh, xs, msgs, b1f, bn_g, bn_b, bn_m, bn_v,
        nullptr, hs, 2 * DD, 2 * DD, NN, DD, 0);

    // 5) out = W2 @ h + b2  (fp32 out)
    hmma_gemm<0><<<dim3(NN / 128, DD / 128, BB), 256, SM1>>>(
        ws2h, hs, hs, mlp_b2, nullptr, nullptr, nullptr, nullptr,
        out, nullptr, DD, 2 * DD, NN, 2 * DD, NN);
}

// round 14
// speedup vs baseline: 9.4738x; 1.0218x over previous
#include <cuda_runtime.h>
#include <cuda_fp16.h>
#include <math.h>
#include <stdint.h>

// Problem constants
#define BB 4
#define DD 1024
#define NN 4096
#define HH 16
#define KK 128
#define DHH 64

typedef unsigned long long ull;
typedef unsigned int uint;
typedef unsigned short ushort;

// ---------------- scratch (device globals) ----------------
__device__ float g_kp  [(size_t)BB * DD * KK];
__device__ float g_srcp[(size_t)BB * DD * KK];
__device__ float g_scol[KK];
__device__ float g_b1f [2 * DD];
__device__ float g_bqp [DD];

// single-plane fp16 weights
__device__ ushort g_wqp_h [(size_t)DD * DD];
__device__ ushort g_wk_h  [(size_t)DD * DD];
__device__ ushort g_ws1f_h[(size_t)(2 * DD) * (2 * DD)];
__device__ ushort g_ws2_h [(size_t)DD * (2 * DD)];
__device__ ushort g_w1b_h [(size_t)(2 * DD) * DD];
__device__ ushort g_wmTp  [(size_t)DD * DD];
// fp16 activations / operands
__device__ ushort g_xs   [(size_t)BB * NN * DD];
__device__ ushort g_qs   [(size_t)BB * NN * DD];
__device__ ushort g_msgs [(size_t)BB * NN * DD];
__device__ ushort g_hs   [(size_t)BB * NN * 2 * DD];
__device__ ushort g_srcpT[(size_t)BB * KK * DD];
__device__ ushort g_projT[(size_t)KK * NN];

// ---------------- helpers ----------------
__device__ __forceinline__ uint32_t smem_to_u32(const void* p) {
    uint32_t a;
    asm("{ .reg .u64 t; cvta.to.shared.u64 t, %1; cvt.u32.u64 %0, t; }"
        : "=r"(a) : "l"(p));
    return a;
}
__device__ __forceinline__ void sts_v4(uint32_t addr, uint4 v) {
    asm volatile("st.shared.v4.b32 [%0], {%1, %2, %3, %4};"
                 :: "r"(addr), "r"(v.x), "r"(v.y), "r"(v.z), "r"(v.w));
}
__device__ __forceinline__ void ldsm4(uint* r, uint32_t addr) {
    asm volatile("ldmatrix.sync.aligned.m8n8.x4.shared.b16 {%0,%1,%2,%3}, [%4];"
        : "=r"(r[0]), "=r"(r[1]), "=r"(r[2]), "=r"(r[3]) : "r"(addr));
}

// HMMA m16n8k16 fp16 -> fp32
__device__ __forceinline__ void mma16816(float* c, const uint* a, uint b0, uint b1) {
    asm volatile(
        "mma.sync.aligned.m16n8k16.row.col.f32.f16.f16.f32 "
        "{%0,%1,%2,%3}, {%4,%5,%6,%7}, {%8,%9}, {%0,%1,%2,%3};"
        : "+f"(c[0]), "+f"(c[1]), "+f"(c[2]), "+f"(c[3])
        : "r"(a[0]), "r"(a[1]), "r"(a[2]), "r"(a[3]), "r"(b0), "r"(b1));
}
__device__ __forceinline__ uint ex2_f16x2(uint t) {
    uint r;
    asm("ex2.approx.f16x2 %0, %1;" : "=r"(r) : "r"(t));
    return r;
}

// pack 8 consecutive fp32 -> 8 fp16 (one uint4 store)
__device__ __forceinline__ void cvt8(const float* __restrict__ in, ushort* __restrict__ out) {
    float4 f0 = *(const float4*)in;
    float4 f1 = *(const float4*)(in + 4);
    __half2 h0 = __floats2half2_rn(f0.x, f0.y);
    __half2 h1 = __floats2half2_rn(f0.z, f0.w);
    __half2 h2 = __floats2half2_rn(f1.x, f1.y);
    __half2 h3 = __floats2half2_rn(f1.z, f1.w);
    *(uint4*)out = make_uint4(*(uint*)&h0, *(uint*)&h1, *(uint*)&h2, *(uint*)&h3);
}

// ---------------------------------------------------------------------------
// Mega weight prep: one kernel, 8 elems/thread, fully vectorized.
// regions: [0,512) wq(perm) | [512,1024) wk | [1024,2048) w2 | [2048,4096) w1
// ---------------------------------------------------------------------------
__global__ void prep_all(const float* __restrict__ wq, const float* __restrict__ wk,
                         const float* __restrict__ w2, const float* __restrict__ w1,
                         ushort* __restrict__ wqp, ushort* __restrict__ wkh,
                         ushort* __restrict__ ws2h,
                         ushort* __restrict__ w1a, ushort* __restrict__ w1b)
{
    const int cta = blockIdx.x;
    const int tid = threadIdx.x;
    if (cta < 512) {
        const int i = cta * 2048 + tid * 8;
        const int m = i >> 10, k = i & 1023;
        const int p = (m & 15) * 64 + (m >> 4);
        cvt8(wq + i, wqp + (size_t)p * DD + k);
    } else if (cta < 1024) {
        const int i = (cta - 512) * 2048 + tid * 8;
        cvt8(wk + i, wkh + i);
    } else if (cta < 2048) {
        const int i = (cta - 1024) * 2048 + tid * 8;
        cvt8(w2 + i, ws2h + i);
    } else {
        const int i = (cta - 2048) * 2048 + tid * 8;
        const int m = i >> 11, k = i & 2047;
        if (k < DD) cvt8(w1 + i, w1a + (size_t)m * (2 * DD) + k);
        else        cvt8(w1 + i, w1b + (size_t)m * DD + (k - DD));
    }
}

// permuted bias: out[p] = in[(p%64)*16 + p/64]
__global__ void bias_perm(const float* __restrict__ in, float* __restrict__ out) {
    int p = blockIdx.x * 256 + threadIdx.x;
    int d = (p & 63) * 16 + (p >> 6);
    out[p] = in[d];
}

// fp32 [B, C, N] -> fp16 [B, N, C]
__global__ void transpose_half(const float* __restrict__ in, ushort* __restrict__ out,
                               int C, int Nw) {
    __shared__ float tile[32][33];
    const int b = blockIdx.z;
    const int n0 = blockIdx.x * 32, c0 = blockIdx.y * 32;
    const int tx = threadIdx.x, ty = threadIdx.y;
    const float* inb = in + ((size_t)b * C + c0) * Nw + n0;
#pragma unroll
    for (int i = 0; i < 32; i += 8)
        tile[ty + i][tx] = inb[(size_t)(ty + i) * Nw + tx];
    __syncthreads();
    ushort* ob = out + ((size_t)b * Nw + n0) * C + c0;
#pragma unroll
    for (int i = 0; i < 32; i += 8)
        ob[(size_t)(ty + i) * C + tx] = __half_as_ushort(__float2half_rn(tile[tx][ty + i]));
}

// Permuted merge transpose: out[p][j] = fp16(merge_w[j][c]), p=(c%16)*64+c/16
__global__ void transpose_perm(const float* __restrict__ in, ushort* __restrict__ out) {
    __shared__ float tile[32][33];
    const int n0 = blockIdx.x * 32, c0 = blockIdx.y * 32;
    const int tx = threadIdx.x, ty = threadIdx.y;
    const float* inb = in + (size_t)(c0) * DD + n0;
#pragma unroll
    for (int i = 0; i < 32; i += 8)
        tile[ty + i][tx] = inb[(size_t)(ty + i) * DD + tx];
    __syncthreads();
#pragma unroll
    for (int i = 0; i < 32; i += 8) {
        const int r = n0 + ty + i;
        const int p = (r & 15) * 64 + (r >> 4);
        out[(size_t)p * DD + c0 + tx] =
            __half_as_ushort(__float2half_rn(tile[tx][ty + i]));
    }
}

// colsum of proj (coalesced, 32 CTAs)
__global__ void colsum_kernel(const float* __restrict__ proj, float* __restrict__ S) {
    const int c = threadIdx.x;
    const float* p = proj + (size_t)blockIdx.x * 128 * KK + c;
    float s = 0.f;
#pragma unroll 8
    for (int m = 0; m < 128; m++) s += p[(size_t)m * KK];
    atomicAdd(&S[c], s);
}

// b1f[m] = b1[m] + dot(W1[m, 1024:2048], bm)
__global__ void bias_fold(const float* __restrict__ w1, const float* __restrict__ bm,
                          const float* __restrict__ b1, float* __restrict__ out) {
    const int m = blockIdx.x * 8 + (threadIdx.x >> 5);
    const int lane = threadIdx.x & 31;
    float s = 0.f;
#pragma unroll 4
    for (int c = lane; c < DD; c += 32)
        s += w1[(size_t)m * (2 * DD) + DD + c] * bm[c];
#pragma unroll
    for (int o = 16; o; o >>= 1) s += __shfl_xor_sync(0xFFFFFFFFu, s, o);
    if (lane == 0) out[m] = b1[m] + s;
}

// ---------------------------------------------------------------------------
// Warp-level HMMA GEMM (single-plane fp16 A).
// MODE 0: fp32 out (+bias); MODE 1: +bias fp16-transpose out [B,Nw,M];
// MODE 2: +bias/BN/ReLU fp16-transpose out; MODE 3: plain-fp16 out [M,ostr];
// MODE 4: fp32 out + bias[m]*colS[n]  (colS passed via gamma).
// ---------------------------------------------------------------------------
#define STG_S 136

template <int MODE>
__global__ void __launch_bounds__(256, 2) hmma_gemm(
    const ushort* __restrict__ Aptr,
    const ushort* __restrict__ B1,
    const ushort* __restrict__ B2,
    const float* __restrict__ bias,
    const float* __restrict__ gamma,
    const float* __restrict__ beta,
    const float* __restrict__ mean,
    const float* __restrict__ var,
    float* __restrict__ outF,
    ushort* __restrict__ outT,
    int M, int Kd, int Nw, int K1, int ostr)
{
    constexpr uint32_t PLB   = 18432u;
    constexpr uint32_t SMBUF = 36864u;

    extern __shared__ char smem[];
    const uint32_t sb = smem_to_u32(smem);

    const int tid  = threadIdx.x;
    const int wid  = tid >> 5;
    const int lane = tid & 31;
    const int m0 = blockIdx.y * 128;
    const int n0 = blockIdx.x * 128;
    const int bb = blockIdx.z;

    const int wm = wid & 3;
    const int wn = wid >> 2;
    const int K2 = Kd - K1;
    const int fr = lane >> 2;
    const int fc = (lane & 3) * 2;

    float c[2][8][4];
#pragma unroll
    for (int mt = 0; mt < 2; mt++)
#pragma unroll
        for (int nt = 0; nt < 8; nt++)
#pragma unroll
            for (int j = 0; j < 4; j++) c[mt][nt][j] = 0.f;

    const int nc = Kd >> 6;
    uint4 pa[4], pb[4];

    auto ldg_tile = [&](int ch) {
        const int k0 = ch * 64;
        const ushort* Ab = Aptr + (size_t)m0 * Kd;
#pragma unroll
        for (int it = 0; it < 4; it++) {
            const int idx = it * 256 + tid;
            const int row = idx >> 3, q4 = idx & 7;
            pa[it] = *(const uint4*)(Ab + (size_t)row * Kd + k0 + q4 * 8);
        }
        const ushort* Bsrc; int kloc, kstride;
        if (k0 < K1) { Bsrc = B1; kloc = k0;      kstride = K1; }
        else         { Bsrc = B2; kloc = k0 - K1; kstride = K2; }
        const ushort* Bb = Bsrc + ((size_t)bb * Nw + n0) * kstride + kloc;
#pragma unroll
        for (int it = 0; it < 4; it++) {
            const int idx = it * 256 + tid;
            const int row = idx >> 3, q4 = idx & 7;
            pb[it] = *(const uint4*)(Bb + (size_t)row * kstride + q4 * 8);
        }
    };
    auto sts_tile = [&](int buf) {
        const uint32_t base = sb + buf * SMBUF;
#pragma unroll
        for (int it = 0; it < 4; it++) {
            const int idx = it * 256 + tid;
            const int row = idx >> 3, q4 = idx & 7;
            sts_v4(base + (uint32_t)row * 144 + q4 * 16, pa[it]);
            sts_v4(base + PLB + (uint32_t)row * 144 + q4 * 16, pb[it]);
        }
    };

    ldg_tile(0);
    sts_tile(0);
    __syncthreads();

    const uint32_t aOff = (uint32_t)(wm * 32 + (lane & 15)) * 144 + ((lane >> 4) & 1) * 16;
    const uint32_t bOff = (uint32_t)(wn * 64 + (lane & 7) + ((lane & 16) ? 8 : 0)) * 144
                        + ((lane & 8) ? 16 : 0);

    for (int ch = 0; ch < nc; ch++) {
        const uint32_t base = sb + (ch & 1) * SMBUF;
        if (ch + 1 < nc) ldg_tile(ch + 1);
#pragma unroll
        for (int ksb = 0; ksb < 128; ksb += 32) {
            uint ah[2][4];
            ldsm4(ah[0], base + aOff + ksb);
            ldsm4(ah[1], base + aOff + 2304 + ksb);
            uint bh[4][4];
#pragma unroll
            for (int np = 0; np < 4; np++)
                ldsm4(bh[np], base + PLB + bOff + np * 2304 + ksb);
#pragma unroll
            for (int np = 0; np < 4; np++)
#pragma unroll
                for (int sub = 0; sub < 2; sub++) {
                    const int nt = np * 2 + sub;
                    const uint b0 = bh[np][sub * 2], b1 = bh[np][sub * 2 + 1];
#pragma unroll
                    for (int mt = 0; mt < 2; mt++)
                        mma16816(c[mt][nt], ah[mt], b0, b1);
                }
        }
        if (ch + 1 < nc) {
            sts_tile((ch + 1) & 1);
            __syncthreads();
        }
    }

    // ---- epilogue ----
    if (MODE == 0 || MODE == 4) {
        const int cm = m0 + wm * 32 + fr;
        const int cn = n0 + wn * 64 + fc;
#pragma unroll
        for (int mt = 0; mt < 2; mt++) {
            const int mlo = cm + mt * 16;
            const int mhi = mlo + 8;
            const float bi0 = bias[mlo], bi1 = bias[mhi];
#pragma unroll
            for (int nt = 0; nt < 8; nt++) {
                const int n = cn + nt * 8;
                float s0 = 1.f, s1 = 1.f;
                if (MODE == 4) { s0 = gamma[n]; s1 = gamma[n + 1]; }
                *(float2*)(outF + ((size_t)bb * M + mlo) * ostr + n) =
                    make_float2(c[mt][nt][0] + bi0 * s0, c[mt][nt][1] + bi0 * s1);
                *(float2*)(outF + ((size_t)bb * M + mhi) * ostr + n) =
                    make_float2(c[mt][nt][2] + bi1 * s0, c[mt][nt][3] + bi1 * s1);
            }
        }
    } else if (MODE == 3) {
        ushort* ob = outT;
        const int cm = m0 + wm * 32 + fr;
        const int cn = n0 + wn * 64 + fc;
#pragma unroll
        for (int mt = 0; mt < 2; mt++) {
            const int mlo = cm + mt * 16;
            const int mhi = mlo + 8;
#pragma unroll
            for (int nt = 0; nt < 8; nt++) {
                const int n = cn + nt * 8;
                ob[(size_t)mlo * ostr + n]     = __half_as_ushort(__float2half_rn(c[mt][nt][0]));
                ob[(size_t)mlo * ostr + n + 1] = __half_as_ushort(__float2half_rn(c[mt][nt][1]));
                ob[(size_t)mhi * ostr + n]     = __half_as_ushort(__float2half_rn(c[mt][nt][2]));
                ob[(size_t)mhi * ostr + n + 1] = __half_as_ushort(__float2half_rn(c[mt][nt][3]));
            }
        }
    } else {
        float* stg = (float*)smem;
        uint* ob = (uint*)(outT + (size_t)bb * Nw * M);
#pragma unroll
        for (int p = 0; p < 2; p++) {
            __syncthreads();
            if (wn == p) {
#pragma unroll
                for (int mt = 0; mt < 2; mt++) {
                    const int mloL = wm * 32 + mt * 16 + fr;
                    const int mhiL = mloL + 8;
                    const int mlo = m0 + mloL, mhi = m0 + mhiL;
                    float sc0 = 1.f, sh0 = bias[mlo];
                    float sc1 = 1.f, sh1 = bias[mhi];
                    if (MODE == 2) {
                        sc0 = gamma[mlo] * rsqrtf(var[mlo] + 1e-3f);
                        sh0 = beta[mlo] + (sh0 - mean[mlo]) * sc0;
                        sc1 = gamma[mhi] * rsqrtf(var[mhi] + 1e-3f);
                        sh1 = beta[mhi] + (sh1 - mean[mhi]) * sc1;
                    }
#pragma unroll
                    for (int nt = 0; nt < 8; nt++) {
                        const int nl = fc + nt * 8;
                        float v0 = fmaf(c[mt][nt][0], sc0, sh0);
                        float v1 = fmaf(c[mt][nt][1], sc0, sh0);
                        float v2 = fmaf(c[mt][nt][2], sc1, sh1);
                        float v3 = fmaf(c[mt][nt][3], sc1, sh1);
                        if (MODE == 2) {
                            v0 = fmaxf(v0, 0.f); v1 = fmaxf(v1, 0.f);
                            v2 = fmaxf(v2, 0.f); v3 = fmaxf(v3, 0.f);
                        }
                        stg[(nl)     * STG_S + mloL] = v0;
                        stg[(nl + 1) * STG_S + mloL] = v1;
                        stg[(nl)     * STG_S + mhiL] = v2;
                        stg[(nl + 1) * STG_S + mhiL] = v3;
                    }
                }
            }
            __syncthreads();
            const int nb = n0 + p * 64;
#pragma unroll 4
            for (int i = 0; i < 16; i++) {
                const int idx = i * 256 + tid;
                const int nn = idx >> 6;
                const int mp = idx & 63;
                const float* s = stg + nn * STG_S + mp * 2;
                const uint u = (uint)__half_as_ushort(__float2half_rn(s[0]))
                             | ((uint)__half_as_ushort(__float2half_rn(s[1])) << 16);
                ob[(size_t)(nb + nn) * (M >> 1) + (m0 >> 1) + mp] = u;
            }
        }
    }
}

// ---------------------------------------------------------------------------
// Split-K fp16 HMMA: srcp[r,c] += fp16(source[r,:]) . projT[c,:]
// ---------------------------------------------------------------------------
__global__ void __launch_bounds__(256, 2) hmma_splitk(
    const float* __restrict__ A,
    const ushort* __restrict__ Bp,
    float* __restrict__ C)
{
    constexpr uint32_t PLB = 18432;
    constexpr uint32_t SMBUF = 36864;
    extern __shared__ char smem[];
    const uint32_t sb = smem_to_u32(smem);

    const int tid  = threadIdx.x;
    const int wid  = tid >> 5;
    const int lane = tid & 31;
    const int m0 = blockIdx.y * 128;
    const int kbase = blockIdx.x * 512;
    const int Kd = NN;

    const int wm = wid & 3;
    const int wn = wid >> 2;
    const int fr = lane >> 2;
    const int fc = (lane & 3) * 2;

    float c[2][8][4];
#pragma unroll
    for (int mt = 0; mt < 2; mt++)
#pragma unroll
        for (int nt = 0; nt < 8; nt++)
#pragma unroll
            for (int j = 0; j < 4; j++) c[mt][nt][j] = 0.f;

    uint4 pa[4], pb[4];
    auto ldg_tile = [&](int ch) {
        const int k0 = kbase + ch * 64;
        const float* Ab = A + (size_t)m0 * Kd;
#pragma unroll
        for (int it = 0; it < 4; it++) {
            const int idx = it * 256 + tid;
            const int row = idx >> 3, q4 = idx & 7;
            const float* ap = Ab + (size_t)row * Kd + k0 + q4 * 8;
            float4 f0 = *(const float4*)ap;
            float4 f1 = *(const float4*)(ap + 4);
            __half2 h0 = __floats2half2_rn(f0.x, f0.y);
            __half2 h1 = __floats2half2_rn(f0.z, f0.w);
            __half2 h2 = __floats2half2_rn(f1.x, f1.y);
            __half2 h3 = __floats2half2_rn(f1.z, f1.w);
            pa[it] = make_uint4(*(uint*)&h0, *(uint*)&h1, *(uint*)&h2, *(uint*)&h3);
        }
#pragma unroll
        for (int it = 0; it < 4; it++) {
            const int idx = it * 256 + tid;
            const int row = idx >> 3, q4 = idx & 7;
            pb[it] = *(const uint4*)(Bp + (size_t)row * Kd + k0 + q4 * 8);
        }
    };
    auto sts_tile = [&](int buf) {
        const uint32_t base = sb + buf * SMBUF;
#pragma unroll
        for (int it = 0; it < 4; it++) {
            const int idx = it * 256 + tid;
            const int row = idx >> 3, q4 = idx & 7;
            sts_v4(base + (uint32_t)row * 144 + q4 * 16, pa[it]);
            sts_v4(base + PLB + (uint32_t)row * 144 + q4 * 16, pb[it]);
        }
    };

    ldg_tile(0);
    sts_tile(0);
    __syncthreads();

    const uint32_t aOff = (uint32_t)(wm * 32 + (lane & 15)) * 144 + ((lane >> 4) & 1) * 16;
    const uint32_t bOff = (uint32_t)(wn * 64 + (lane & 7) + ((lane & 16) ? 8 : 0)) * 144
                        + ((lane & 8) ? 16 : 0);

    for (int ch = 0; ch < 8; ch++) {
        const uint32_t base = sb + (ch & 1) * SMBUF;
        if (ch + 1 < 8) ldg_tile(ch + 1);
#pragma unroll
        for (int ksb = 0; ksb < 128; ksb += 32) {
            uint ah[2][4];
            ldsm4(ah[0], base + aOff + ksb);
            ldsm4(ah[1], base + aOff + 2304 + ksb);
            uint bh[4][4];
#pragma unroll
            for (int np = 0; np < 4; np++)
                ldsm4(bh[np], base + PLB + bOff + np * 2304 + ksb);
#pragma unroll
            for (int np = 0; np < 4; np++)
#pragma unroll
                for (int sub = 0; sub < 2; sub++) {
                    const int nt = np * 2 + sub;
#pragma unroll
                    for (int mt = 0; mt < 2; mt++)
                        mma16816(c[mt][nt], ah[mt], bh[np][sub * 2], bh[np][sub * 2 + 1]);
                }
        }
        if (ch + 1 < 8) {
            sts_tile((ch + 1) & 1);
            __syncthreads();
        }
    }

    const int cm = m0 + wm * 32 + fr;
    const int cn = wn * 64 + fc;
#pragma unroll
    for (int mt = 0; mt < 2; mt++) {
        const int mlo = cm + mt * 16;
        const int mhi = mlo + 8;
#pragma unroll
        for (int nt = 0; nt < 8; nt++) {
            const int n = cn + nt * 8;
            atomicAdd(&C[(size_t)mlo * KK + n],     c[mt][nt][0]);
            atomicAdd(&C[(size_t)mlo * KK + n + 1], c[mt][nt][1]);
            atomicAdd(&C[(size_t)mhi * KK + n],     c[mt][nt][2]);
            atomicAdd(&C[(size_t)mhi * KK + n + 1], c[mt][nt][3]);
        }
    }
}

// ---------------------------------------------------------------------------
// Tensor-core attention (fp16x2 MUFU exp, 2 CTAs/SM).
// S accumulators are REUSED as O accumulators after P extraction (reg dieting).
// ---------------------------------------------------------------------------
#define AT_Q   0
#define AT_K1  18432
#define AT_K2  36864
#define AT_RS  54272
#define AT_SMEM 54784

__global__ void __launch_bounds__(256, 2) attn_mma(
    const ushort* __restrict__ qs,
    const float* __restrict__ kp,
    ushort* __restrict__ msgs)
{
    extern __shared__ char smem[];
    const uint32_t sb = smem_to_u32(smem);
    float* rowsum = (float*)(smem + AT_RS);

    const int tid = threadIdx.x;
    const int wid = tid >> 5, lane = tid & 31;
    const int wm = wid & 3, wn = wid >> 2;
    const int fr = lane >> 2, fc = (lane & 3) * 2;
    const int n0 = blockIdx.x * 128;
    const int h = blockIdx.y;
    const int b = blockIdx.z;

    // Q tile [128][64] fp16 -> smem stride 144B
    {
        const ushort* qb = qs + ((size_t)b * NN + n0) * DD + (size_t)h * DHH;
#pragma unroll
        for (int it = 0; it < 4; it++) {
            const int idx = it * 256 + tid;
            const int row = idx >> 3, q4 = idx & 7;
            uint4 v = *(const uint4*)(qb + (size_t)row * DD + q4 * 8);
            sts_v4(sb + AT_Q + (uint32_t)row * 144 + q4 * 16, v);
        }
    }
    // K fp32 [64 dh][128 kk] -> K1 [kk][dh] (144B stride) + K2 [dh][kk] (272B)
    {
        const float* kb = kp + ((size_t)b * DD + h) * KK;
        ushort* K1 = (ushort*)(smem + AT_K1);
        ushort* K2 = (ushort*)(smem + AT_K2);
#pragma unroll 8
        for (int i = 0; i < 32; i++) {
            const int e = i * 256 + tid;
            const int dh = e >> 7, kk = e & 127;
            const ushort v = __half_as_ushort(
                __float2half_rn(kb[(size_t)dh * HH * KK + kk]));
            K2[dh * 136 + kk] = v;
            K1[kk * 72 + dh] = v;
        }
    }
    if (tid < 128) rowsum[tid] = 0.f;
    __syncthreads();

    // MMA1: S[n][kk]
    float c[2][8][4];
#pragma unroll
    for (int mt = 0; mt < 2; mt++)
#pragma unroll
        for (int nt = 0; nt < 8; nt++)
#pragma unroll
            for (int j = 0; j < 4; j++) c[mt][nt][j] = 0.f;

    const uint32_t aOff = (uint32_t)(wm * 32 + (lane & 15)) * 144 + ((lane >> 4) & 1) * 16;
    const uint32_t bOff = (uint32_t)(wn * 64 + (lane & 7) + ((lane & 16) ? 8 : 0)) * 144
                        + ((lane & 8) ? 16 : 0);
#pragma unroll
    for (int ksb = 0; ksb < 128; ksb += 32) {
        uint ah[2][4];
        ldsm4(ah[0], sb + AT_Q + aOff + ksb);
        ldsm4(ah[1], sb + AT_Q + aOff + 2304 + ksb);
#pragma unroll
        for (int np = 0; np < 4; np++) {
            uint bh[4];
            ldsm4(bh, sb + AT_K1 + bOff + np * 2304 + ksb);
#pragma unroll
            for (int sub = 0; sub < 2; sub++)
#pragma unroll
                for (int mt = 0; mt < 2; mt++)
                    mma16816(c[mt][np * 2 + sub], ah[mt], bh[sub * 2], bh[sub * 2 + 1]);
        }
    }

    // P = 2^(s*C1 + C2) via ex2.approx.f16x2 ; rowsum fp32
    const float C1 = 0.18033688f;    // log2(e)/8
    const float C2 = -5.7707801f;    // -4*log2(e)
    uint ph[2][8][2];
#pragma unroll
    for (int mt = 0; mt < 2; mt++) {
        float r0 = 0.f, r1 = 0.f;
#pragma unroll
        for (int nt = 0; nt < 8; nt++) {
            const float t0 = fmaf(c[mt][nt][0], C1, C2);
            const float t1 = fmaf(c[mt][nt][1], C1, C2);
            const float t2 = fmaf(c[mt][nt][2], C1, C2);
            const float t3 = fmaf(c[mt][nt][3], C1, C2);
            const __half2 ta = __floats2half2_rn(t0, t1);
            const __half2 tb = __floats2half2_rn(t2, t3);
            const uint ea = ex2_f16x2(*(const uint*)&ta);
            const uint eb = ex2_f16x2(*(const uint*)&tb);
            ph[mt][nt][0] = ea;
            ph[mt][nt][1] = eb;
            const float2 fa = __half22float2(*(const __half2*)&ea);
            const float2 fb = __half22float2(*(const __half2*)&eb);
            r0 += fa.x + fa.y;
            r1 += fb.x + fb.y;
        }
        r0 += __shfl_xor_sync(0xFFFFFFFFu, r0, 1);
        r0 += __shfl_xor_sync(0xFFFFFFFFu, r0, 2);
        r1 += __shfl_xor_sync(0xFFFFFFFFu, r1, 1);
        r1 += __shfl_xor_sync(0xFFFFFFFFu, r1, 2);
        if ((lane & 3) == 0) {
            atomicAdd(&rowsum[wm * 32 + mt * 16 + fr], r0);
            atomicAdd(&rowsum[wm * 32 + mt * 16 + fr + 8], r1);
        }
    }

    // MMA2: reuse c as O accumulators (S is dead)
#pragma unroll
    for (int mt = 0; mt < 2; mt++)
#pragma unroll
        for (int nt = 0; nt < 8; nt++)
#pragma unroll
            for (int j = 0; j < 4; j++) c[mt][nt][j] = 0.f;

    const uint32_t b2Off = (uint32_t)((lane & 7) + ((lane & 16) ? 8 : 0)) * 272
                         + ((lane & 8) ? 16 : 0) + (uint32_t)wn * 128;
#pragma unroll
    for (int s = 0; s < 4; s++) {
        uint a2[2][4];
#pragma unroll
        for (int mt = 0; mt < 2; mt++) {
            a2[mt][0] = ph[mt][2 * s][0];
            a2[mt][1] = ph[mt][2 * s][1];
            a2[mt][2] = ph[mt][2 * s + 1][0];
            a2[mt][3] = ph[mt][2 * s + 1][1];
        }
#pragma unroll
        for (int np = 0; np < 4; np++) {
            uint bh[4];
            ldsm4(bh, sb + AT_K2 + b2Off + (uint32_t)np * 16 * 272 + s * 32);
#pragma unroll
            for (int sub = 0; sub < 2; sub++)
#pragma unroll
                for (int mt = 0; mt < 2; mt++)
                    mma16816(c[mt][np * 2 + sub], a2[mt], bh[sub * 2], bh[sub * 2 + 1]);
        }
    }

    // merge partials, normalize, write fp16 head-major
    __syncthreads();
    float* stg = (float*)smem;
    if (tid < 128) rowsum[tid] = 1.f / rowsum[tid];
    const int mb = wm * 32 + fr;
    if (wn == 0) {
#pragma unroll
        for (int mt = 0; mt < 2; mt++)
#pragma unroll
            for (int nt = 0; nt < 8; nt++) {
                const int col = nt * 8 + fc;
                stg[(mb + mt * 16)     * 68 + col]     = c[mt][nt][0];
                stg[(mb + mt * 16)     * 68 + col + 1] = c[mt][nt][1];
                stg[(mb + mt * 16 + 8) * 68 + col]     = c[mt][nt][2];
                stg[(mb + mt * 16 + 8) * 68 + col + 1] = c[mt][nt][3];
            }
    }
    __syncthreads();
    if (wn == 1) {
#pragma unroll
        for (int mt = 0; mt < 2; mt++)
#pragma unroll
            for (int nt = 0; nt < 8; nt++) {
                const int col = nt * 8 + fc;
                stg[(mb + mt * 16)     * 68 + col]     += c[mt][nt][0];
                stg[(mb + mt * 16)     * 68 + col + 1] += c[mt][nt][1];
                stg[(mb + mt * 16 + 8) * 68 + col]     += c[mt][nt][2];
                stg[(mb + mt * 16 + 8) * 68 + col + 1] += c[mt][nt][3];
            }
    }
    __syncthreads();

    uint* ob = (uint*)(msgs + ((size_t)b * NN + n0) * DD + (size_t)h * DHH);
#pragma unroll 4
    for (int i = 0; i < 16; i++) {
        const int idx = i * 256 + tid;
        const int nn = idx >> 5;
        const int dq = idx & 31;
        const float inv = rowsum[nn];
        const float v0 = stg[nn * 68 + dq * 2]     * inv;
        const float v1 = stg[nn * 68 + dq * 2 + 1] * inv;
        const uint u = (uint)__half_as_ushort(__float2half_rn(v0))
                     | ((uint)__half_as_ushort(__float2half_rn(v1)) << 16);
        ob[(size_t)nn * (DD / 2) + dq] = u;
    }
}

// ---------------------------------------------------------------------------
extern "C" void kernel_launch(void* const* d_in, const int* in_sizes, int n_in,
                              void* d_out, int out_size)
{
    const float* x       = (const float*)d_in[0];
    const float* source  = (const float*)d_in[1];
    const float* to_q_w  = (const float*)d_in[2];
    const float* to_q_b  = (const float*)d_in[3];
    const float* to_k_w  = (const float*)d_in[4];
    const float* to_k_b  = (const float*)d_in[5];
    const float* proj_k  = (const float*)d_in[6];
    const float* merge_w = (const float*)d_in[7];
    const float* merge_b = (const float*)d_in[8];
    const float* mlp_w1  = (const float*)d_in[9];
    const float* mlp_b1  = (const float*)d_in[10];
    const float* bn_g    = (const float*)d_in[11];
    const float* bn_b    = (const float*)d_in[12];
    const float* bn_m    = (const float*)d_in[13];
    const float* bn_v    = (const float*)d_in[14];
    const float* mlp_w2  = (const float*)d_in[15];
    const float* mlp_b2  = (const float*)d_in[16];
    float* out = (float*)d_out;

    float *kp, *srcp, *scol, *b1f, *bqp;
    ushort *wqp, *wkh, *ws1fh, *ws2h, *w1bh, *wmTp, *xs, *qs, *msgs, *hs, *srcpT, *projT;
    cudaGetSymbolAddress((void**)&kp,   g_kp);
    cudaGetSymbolAddress((void**)&srcp, g_srcp);
    cudaGetSymbolAddress((void**)&scol, g_scol);
    cudaGetSymbolAddress((void**)&b1f,  g_b1f);
    cudaGetSymbolAddress((void**)&bqp,  g_bqp);
    cudaGetSymbolAddress((void**)&wqp,  g_wqp_h);
    cudaGetSymbolAddress((void**)&wkh,  g_wk_h);
    cudaGetSymbolAddress((void**)&ws1fh,g_ws1f_h);
    cudaGetSymbolAddress((void**)&ws2h, g_ws2_h);
    cudaGetSymbolAddress((void**)&w1bh, g_w1b_h);
    cudaGetSymbolAddress((void**)&wmTp, g_wmTp);
    cudaGetSymbolAddress((void**)&xs,   g_xs);
    cudaGetSymbolAddress((void**)&qs,   g_qs);
    cudaGetSymbolAddress((void**)&msgs, g_msgs);
    cudaGetSymbolAddress((void**)&hs,   g_hs);
    cudaGetSymbolAddress((void**)&srcpT,g_srcpT);
    cudaGetSymbolAddress((void**)&projT,g_projT);

    const int SM1 = 2 * 36864;
    cudaFuncSetAttribute(hmma_gemm<0>, cudaFuncAttributeMaxDynamicSharedMemorySize, SM1);
    cudaFuncSetAttribute(hmma_gemm<1>, cudaFuncAttributeMaxDynamicSharedMemorySize, SM1);
    cudaFuncSetAttribute(hmma_gemm<2>, cudaFuncAttributeMaxDynamicSharedMemorySize, SM1);
    cudaFuncSetAttribute(hmma_gemm<3>, cudaFuncAttributeMaxDynamicSharedMemorySize, SM1);
    cudaFuncSetAttribute(hmma_gemm<4>, cudaFuncAttributeMaxDynamicSharedMemorySize, SM1);
    cudaFuncSetAttribute(hmma_splitk, cudaFuncAttributeMaxDynamicSharedMemorySize, SM1);
    cudaFuncSetAttribute(attn_mma, cudaFuncAttributeMaxDynamicSharedMemorySize, AT_SMEM);

    // 0) fused weight prep (wqp perm + wk + w2 + w1a/w1b), vectorized
    prep_all<<<4096, 256>>>(to_q_w, to_k_w, mlp_w2, mlp_w1,
                            wqp, wkh, ws2h, ws1fh, w1bh);
    bias_perm<<<DD / 256, 256>>>(to_q_b, bqp);
    transpose_perm<<<dim3(DD / 32, DD / 32), dim3(32, 8)>>>(merge_w, wmTp);
    hmma_gemm<3><<<dim3(DD / 128, (2 * DD) / 128, 1), 256, SM1>>>(
        w1bh, wmTp, wmTp, nullptr, nullptr, nullptr, nullptr, nullptr,
        nullptr, ws1fh + DD, 2 * DD, DD, DD, DD, 2 * DD);
    bias_fold<<<(2 * DD) / 8, 256>>>(mlp_w1, merge_b, mlp_b1, b1f);

    // x transpose, proj transpose
    transpose_half<<<dim3(NN / 32, DD / 32, BB), dim3(32, 8)>>>(x, xs, DD, NN);
    transpose_half<<<dim3(KK / 32, NN / 32, 1), dim3(32, 8)>>>(proj_k, projT, NN, KK);

    // 1) Linformer fold: kp = Wk @ (src @ proj) + bk * colsum(proj)
    cudaMemsetAsync(scol, 0, sizeof(float) * KK);
    colsum_kernel<<<NN / 128, KK>>>(proj_k, scol);
    cudaMemsetAsync(srcp, 0, sizeof(float) * (size_t)BB * DD * KK);
    hmma_splitk<<<dim3(8, (BB * DD) / 128), 256, SM1>>>(source, projT, srcp);
    transpose_half<<<dim3(KK / 32, DD / 32, BB), dim3(32, 8)>>>(srcp, srcpT, DD, KK);
    hmma_gemm<4><<<dim3(1, DD / 128, BB), 256, SM1>>>(
        wkh, srcpT, srcpT, to_k_b, scol, nullptr, nullptr, nullptr,
        kp, nullptr, DD, DD, KK, DD, KK);

    // 2) q = Wq @ x + bq  (fp16 head-major transposed out)
    hmma_gemm<1><<<dim3(NN / 128, DD / 128, BB), 256, SM1>>>(
        wqp, xs, xs, bqp, nullptr, nullptr, nullptr, nullptr,
        nullptr, qs, DD, DD, NN, DD, 0);

    // 3) tensor-core attention -> msgs fp16 head-major
    attn_mma<<<dim3(NN / 128, HH, BB), 256, AT_SMEM>>>(qs, kp, msgs);

    // 4) h = relu(BN([W1a | W1c'] @ concat(x, msg) + b1'))
    hmma_gemm<2><<<dim3(NN / 128, (2 * DD) / 128, BB), 256, SM1>>>(
        ws1fh, xs, msgs, b1f, bn_g, bn_b, bn_m, bn_v,
        nullptr, hs, 2 * DD, 2 * DD, NN, DD, 0);

    // 5) out = W2 @ h + b2  (fp32 out)
    hmma_gemm<0><<<dim3(NN / 128, DD / 128, BB), 256, SM1>>>(
        ws2h, hs, hs, mlp_b2, nullptr, nullptr, nullptr, nullptr,
        out, nullptr, DD, 2 * DD, NN, 2 * DD, NN);
}